// round 1
// baseline (speedup 1.0000x reference)
#include <cuda_runtime.h>
#include <math.h>

#define T_TOK 4096
#define DM 512
#define DFF 2048
#define NE 16
#define PP 128
#define OUT_ELEMS (T_TOK * DM)

// ---------------- device scratch (static, allocation-free) ----------------
__device__ float g_xp[T_TOK * PP];            // 2 MB   projector output
__device__ float g_gx[T_TOK * 3 * PP];        // 6 MB   x-side gates
__device__ float g_gh[T_TOK * 3 * PP];        // 6 MB   h-side gates
__device__ float g_hid[(size_t)T_TOK * 2 * DFF]; // 67 MB hidden activations (compact pairs)
__device__ int   g_list[NE * T_TOK];          // per-expert token lists
__device__ float g_wt[NE * T_TOK];            // per-expert combine weights
__device__ int   g_count[NE];
__device__ int   g_offset[NE];

// ---------------- init: zero out-region and per-expert counts ----------------
__global__ void k_init(float* __restrict__ out) {
    int i = blockIdx.x * blockDim.x + threadIdx.x;
    if (i < OUT_ELEMS) out[i] = 0.0f;
    if (blockIdx.x == 0 && threadIdx.x < NE) g_count[threadIdx.x] = 0;
}

// ---------------- generic fp32 tiled GEMM: C[M,N] = A[M,K] @ B[N,K]^T + bias[N]
// 128x128 tile, BK=8, 256 threads, 8x8 per thread
__device__ __forceinline__ void gemm_bt_body(
    const float* __restrict__ A, const float* __restrict__ B,
    const float* __restrict__ bias, float* __restrict__ C,
    int M, int N, int K)
{
    __shared__ float As[8][128];
    __shared__ float Bs[8][128];
    const int tid = threadIdx.x;
    const int m0 = blockIdx.y * 128;
    const int n0 = blockIdx.x * 128;
    const int ty = tid >> 4, tx = tid & 15;
    const int lrow = tid >> 1;
    const int lc4 = (tid & 1) * 4;

    float acc[8][8];
#pragma unroll
    for (int i = 0; i < 8; i++)
#pragma unroll
        for (int j = 0; j < 8; j++) acc[i][j] = 0.f;

    for (int k0 = 0; k0 < K; k0 += 8) {
        float4 av = make_float4(0.f, 0.f, 0.f, 0.f);
        float4 bv = make_float4(0.f, 0.f, 0.f, 0.f);
        if (m0 + lrow < M) av = *(const float4*)(A + (size_t)(m0 + lrow) * K + k0 + lc4);
        if (n0 + lrow < N) bv = *(const float4*)(B + (size_t)(n0 + lrow) * K + k0 + lc4);
        As[lc4 + 0][lrow] = av.x; As[lc4 + 1][lrow] = av.y;
        As[lc4 + 2][lrow] = av.z; As[lc4 + 3][lrow] = av.w;
        Bs[lc4 + 0][lrow] = bv.x; Bs[lc4 + 1][lrow] = bv.y;
        Bs[lc4 + 2][lrow] = bv.z; Bs[lc4 + 3][lrow] = bv.w;
        __syncthreads();
#pragma unroll
        for (int k = 0; k < 8; k++) {
            float ra[8], rb[8];
#pragma unroll
            for (int i = 0; i < 8; i++) ra[i] = As[k][ty * 8 + i];
#pragma unroll
            for (int j = 0; j < 8; j++) rb[j] = Bs[k][tx * 8 + j];
#pragma unroll
            for (int i = 0; i < 8; i++)
#pragma unroll
                for (int j = 0; j < 8; j++) acc[i][j] = fmaf(ra[i], rb[j], acc[i][j]);
        }
        __syncthreads();
    }
#pragma unroll
    for (int i = 0; i < 8; i++) {
        int m = m0 + ty * 8 + i;
        if (m >= M) continue;
#pragma unroll
        for (int j = 0; j < 8; j++) {
            int n = n0 + tx * 8 + j;
            if (n < N) C[(size_t)m * N + n] = acc[i][j] + bias[n];
        }
    }
}

__global__ void __launch_bounds__(256) k_proj(const float* __restrict__ x,
                                              const float* __restrict__ Wp,
                                              const float* __restrict__ bp) {
    gemm_bt_body(x, Wp, bp, g_xp, T_TOK, PP, DM);
}
__global__ void __launch_bounds__(256) k_gates_x(const float* __restrict__ W_ih,
                                                 const float* __restrict__ b_ih) {
    gemm_bt_body(g_xp, W_ih, b_ih, g_gx, T_TOK, 3 * PP, PP);
}
__global__ void __launch_bounds__(256) k_gates_h(const float* __restrict__ h_prev,
                                                 const float* __restrict__ W_hh,
                                                 const float* __restrict__ b_hh) {
    gemm_bt_body(h_prev, W_hh, b_hh, g_gh, T_TOK, 3 * PP, PP);
}

// ---------------- GRU elementwise + router (softmax top-2) ----------------
// one block = one token, 128 threads
__global__ void __launch_bounds__(128) k_gru_route(
    const float* __restrict__ h_prev,
    const float* __restrict__ Wr, const float* __restrict__ br,
    float* __restrict__ h_out)
{
    const int t = blockIdx.x;
    const int j = threadIdx.x;
    __shared__ float hs[PP];
    __shared__ float logit[NE];

    const float* gx = g_gx + (size_t)t * (3 * PP);
    const float* gh = g_gh + (size_t)t * (3 * PP);
    float xr = gx[j], xz = gx[PP + j], xn = gx[2 * PP + j];
    float hr = gh[j], hz = gh[PP + j], hn = gh[2 * PP + j];
    float r = 1.f / (1.f + expf(-(xr + hr)));
    float z = 1.f / (1.f + expf(-(xz + hz)));
    float n = tanhf(xn + r * hn);
    float hp = h_prev[(size_t)t * PP + j];
    float h = (1.f - z) * n + z * hp;
    hs[j] = h;
    h_out[(size_t)t * PP + j] = h;
    __syncthreads();

    const int w = j >> 5, lane = j & 31;
    for (int e = w; e < NE; e += 4) {
        float p = 0.f;
#pragma unroll
        for (int c = 0; c < 4; c++)
            p += Wr[e * PP + lane + 32 * c] * hs[lane + 32 * c];
#pragma unroll
        for (int off = 16; off; off >>= 1) p += __shfl_down_sync(0xffffffffu, p, off);
        if (lane == 0) logit[e] = p + br[e];
    }
    __syncthreads();

    if (j == 0) {
        // top-2 (ties keep lower index, matching jax top_k)
        int e0 = 0, e1 = -1;
        float l0 = logit[0], l1 = -1e30f;
        for (int e = 1; e < NE; e++) {
            float v = logit[e];
            if (v > l0) { l1 = l0; e1 = e0; l0 = v; e0 = e; }
            else if (v > l1) { l1 = v; e1 = e; }
        }
        // renormalized top-2 softmax == softmax over the two top logits
        float p0 = expf(l0 - l0), p1 = expf(l1 - l0);
        float inv = 1.f / (p0 + p1);
        p0 *= inv; p1 *= inv;
        int pos0 = atomicAdd(&g_count[e0], 1);
        g_list[e0 * T_TOK + pos0] = t; g_wt[e0 * T_TOK + pos0] = p0;
        int pos1 = atomicAdd(&g_count[e1], 1);
        g_list[e1 * T_TOK + pos1] = t; g_wt[e1 * T_TOK + pos1] = p1;
    }
}

__global__ void k_offsets() {
    if (threadIdx.x == 0) {
        int s = 0;
        for (int e = 0; e < NE; e++) { g_offset[e] = s; s += g_count[e]; }
    }
}

// ---------------- expert up-proj: H = relu(gather(X) @ W1[e] + b1[e]) ----------------
// B is [K=512, N=2048] row-major (normal layout). grid (16, 32, 16), early-exit.
__global__ void __launch_bounds__(256) k_expert_up(
    const float* __restrict__ X, const float* __restrict__ W1,
    const float* __restrict__ b1)
{
    const int e = blockIdx.z;
    const int cnt = g_count[e];
    const int m0 = blockIdx.y * 128;
    if (m0 >= cnt) return;
    const int n0 = blockIdx.x * 128;
    const float* Bw = W1 + (size_t)e * DM * DFF;
    const float* b1e = b1 + (size_t)e * DFF;
    const int base = g_offset[e];

    __shared__ float As[8][128];
    __shared__ float Bs[8][128];
    __shared__ int rowidx[128];

    const int tid = threadIdx.x;
    const int ty = tid >> 4, tx = tid & 15;
    const int lrow = tid >> 1;
    const int lc4 = (tid & 1) * 4;
    const int bk = tid >> 5;
    const int bn4 = (tid & 31) * 4;

    if (tid < 128)
        rowidx[tid] = (m0 + tid < cnt) ? g_list[e * T_TOK + m0 + tid] : -1;
    __syncthreads();
    const int myrow = rowidx[lrow];

    float acc[8][8];
#pragma unroll
    for (int i = 0; i < 8; i++)
#pragma unroll
        for (int j = 0; j < 8; j++) acc[i][j] = 0.f;

    for (int k0 = 0; k0 < DM; k0 += 8) {
        float4 av = make_float4(0.f, 0.f, 0.f, 0.f);
        if (myrow >= 0) av = *(const float4*)(X + (size_t)myrow * DM + k0 + lc4);
        As[lc4 + 0][lrow] = av.x; As[lc4 + 1][lrow] = av.y;
        As[lc4 + 2][lrow] = av.z; As[lc4 + 3][lrow] = av.w;
        float4 bv = *(const float4*)(Bw + (size_t)(k0 + bk) * DFF + n0 + bn4);
        *(float4*)&Bs[bk][bn4] = bv;
        __syncthreads();
#pragma unroll
        for (int k = 0; k < 8; k++) {
            float ra[8], rb[8];
#pragma unroll
            for (int i = 0; i < 8; i++) ra[i] = As[k][ty * 8 + i];
#pragma unroll
            for (int j = 0; j < 8; j++) rb[j] = Bs[k][tx * 8 + j];
#pragma unroll
            for (int i = 0; i < 8; i++)
#pragma unroll
                for (int j = 0; j < 8; j++) acc[i][j] = fmaf(ra[i], rb[j], acc[i][j]);
        }
        __syncthreads();
    }
#pragma unroll
    for (int i = 0; i < 8; i++) {
        int m = m0 + ty * 8 + i;
        if (m >= cnt) continue;
        size_t row = (size_t)(base + m);
#pragma unroll
        for (int j = 0; j < 8; j++) {
            int n = n0 + tx * 8 + j;
            g_hid[row * DFF + n] = fmaxf(acc[i][j] + b1e[n], 0.f);
        }
    }
}

// ---------------- expert down-proj + scatter: out[t] += w * (H @ W2[e] + b2[e]) ----
// A rows contiguous in g_hid (compact). B is [K=2048, N=512]. grid (4, 32, 16).
__global__ void __launch_bounds__(256) k_expert_down(
    const float* __restrict__ W2, const float* __restrict__ b2,
    float* __restrict__ out)
{
    const int e = blockIdx.z;
    const int cnt = g_count[e];
    const int m0 = blockIdx.y * 128;
    if (m0 >= cnt) return;
    const int n0 = blockIdx.x * 128;
    const float* Bw = W2 + (size_t)e * DFF * DM;
    const float* b2e = b2 + (size_t)e * DM;
    const int base = g_offset[e];
    const float* A = g_hid + (size_t)(base + m0) * DFF;

    __shared__ float As[8][128];
    __shared__ float Bs[8][128];

    const int tid = threadIdx.x;
    const int ty = tid >> 4, tx = tid & 15;
    const int lrow = tid >> 1;
    const int lc4 = (tid & 1) * 4;
    const int bk = tid >> 5;
    const int bn4 = (tid & 31) * 4;
    const bool arow_ok = (m0 + lrow < cnt);

    float acc[8][8];
#pragma unroll
    for (int i = 0; i < 8; i++)
#pragma unroll
        for (int j = 0; j < 8; j++) acc[i][j] = 0.f;

    for (int k0 = 0; k0 < DFF; k0 += 8) {
        float4 av = make_float4(0.f, 0.f, 0.f, 0.f);
        if (arow_ok) av = *(const float4*)(A + (size_t)lrow * DFF + k0 + lc4);
        As[lc4 + 0][lrow] = av.x; As[lc4 + 1][lrow] = av.y;
        As[lc4 + 2][lrow] = av.z; As[lc4 + 3][lrow] = av.w;
        float4 bv = *(const float4*)(Bw + (size_t)(k0 + bk) * DM + n0 + bn4);
        *(float4*)&Bs[bk][bn4] = bv;
        __syncthreads();
#pragma unroll
        for (int k = 0; k < 8; k++) {
            float ra[8], rb[8];
#pragma unroll
            for (int i = 0; i < 8; i++) ra[i] = As[k][ty * 8 + i];
#pragma unroll
            for (int j = 0; j < 8; j++) rb[j] = Bs[k][tx * 8 + j];
#pragma unroll
            for (int i = 0; i < 8; i++)
#pragma unroll
                for (int j = 0; j < 8; j++) acc[i][j] = fmaf(ra[i], rb[j], acc[i][j]);
        }
        __syncthreads();
    }
#pragma unroll
    for (int i = 0; i < 8; i++) {
        int m = m0 + ty * 8 + i;
        if (m >= cnt) continue;
        int tkn = g_list[e * T_TOK + m];
        float w = g_wt[e * T_TOK + m];
#pragma unroll
        for (int j = 0; j < 8; j++) {
            int n = n0 + tx * 8 + j;
            atomicAdd(&out[(size_t)tkn * DM + n], w * (acc[i][j] + b2e[n]));
        }
    }
}

// ---------------- host launcher ----------------
extern "C" void kernel_launch(void* const* d_in, const int* in_sizes, int n_in,
                              void* d_out, int out_size) {
    const float* x      = (const float*)d_in[0];   // [B,S,DM] = [T,DM]
    const float* h_prev = (const float*)d_in[1];   // [T,PP]
    const float* Wp     = (const float*)d_in[2];   // [PP,DM]
    const float* bp     = (const float*)d_in[3];   // [PP]
    const float* W_ih   = (const float*)d_in[4];   // [3PP,PP]
    const float* W_hh   = (const float*)d_in[5];   // [3PP,PP]
    const float* b_ih   = (const float*)d_in[6];   // [3PP]
    const float* b_hh   = (const float*)d_in[7];   // [3PP]
    const float* Wr     = (const float*)d_in[8];   // [NE,PP]
    const float* br     = (const float*)d_in[9];   // [NE]
    const float* W1     = (const float*)d_in[10];  // [NE,DM,DFF]
    const float* b1     = (const float*)d_in[11];  // [NE,DFF]
    const float* W2     = (const float*)d_in[12];  // [NE,DFF,DM]
    const float* b2     = (const float*)d_in[13];  // [NE,DM]
    // d_in[14] = k (always 2, compiled in)

    float* out   = (float*)d_out;            // [T, DM]
    float* h_out = out + OUT_ELEMS;          // [T, PP]

    k_init<<<(OUT_ELEMS + 255) / 256, 256>>>(out);
    k_proj<<<dim3(1, T_TOK / 128), 256>>>(x, Wp, bp);
    k_gates_x<<<dim3(3, T_TOK / 128), 256>>>(W_ih, b_ih);
    k_gates_h<<<dim3(3, T_TOK / 128), 256>>>(h_prev, W_hh, b_hh);
    k_gru_route<<<T_TOK, 128>>>(h_prev, Wr, br, h_out);
    k_offsets<<<1, 1>>>();
    k_expert_up<<<dim3(DFF / 128, T_TOK / 128, NE), 256>>>(x, W1, b1);
    k_expert_down<<<dim3(DM / 128, T_TOK / 128, NE), 256>>>(W2, b2, out);
}

// round 3
// speedup vs baseline: 2.0468x; 2.0468x over previous
#include <cuda_runtime.h>
#include <cuda_bf16.h>
#include <cstdint>
#include <math.h>

#define T_TOK 4096
#define DM 512
#define DFF 2048
#define NE 16
#define PP 128
#define OUT_ELEMS (T_TOK * DM)
#define BK 32

// smem strides (bytes)
#define ASTR 80    // 32 bf16 (64B) + 16B pad -> conflict-free ldmatrix & st.128
#define BSTR 272   // 128 bf16 (256B) + 16B pad -> conflict-free ldmatrix.trans

// ---------------- device scratch ----------------
__device__ float g_xp[T_TOK * PP];
__device__ float g_gx[T_TOK * 3 * PP];
__device__ float g_gh[T_TOK * 3 * PP];
__device__ __nv_bfloat16 g_hid_hi[(size_t)T_TOK * 2 * DFF];  // 32 MB
__device__ __nv_bfloat16 g_hid_lo[(size_t)T_TOK * 2 * DFF];  // 32 MB
__device__ int   g_list[NE * T_TOK];
__device__ float g_wt[NE * T_TOK];
__device__ int   g_count[NE];
__device__ int   g_offset[NE];

// ---------------- helpers ----------------
__device__ __forceinline__ uint32_t smem_u32(const void* p) {
    uint32_t a;
    asm("{ .reg .u64 t; cvta.to.shared.u64 t, %1; cvt.u32.u64 %0, t; }"
        : "=r"(a) : "l"(p));
    return a;
}
__device__ __forceinline__ void ldmx4(uint32_t addr, uint32_t* r) {
    asm volatile("ldmatrix.sync.aligned.m8n8.x4.shared.b16 {%0,%1,%2,%3}, [%4];"
                 : "=r"(r[0]), "=r"(r[1]), "=r"(r[2]), "=r"(r[3]) : "r"(addr));
}
__device__ __forceinline__ void ldmx4t(uint32_t addr, uint32_t* r) {
    asm volatile("ldmatrix.sync.aligned.m8n8.x4.trans.shared.b16 {%0,%1,%2,%3}, [%4];"
                 : "=r"(r[0]), "=r"(r[1]), "=r"(r[2]), "=r"(r[3]) : "r"(addr));
}
__device__ __forceinline__ void mma16816(float* d, const uint32_t* a,
                                         const uint32_t* b) {
    asm volatile(
        "mma.sync.aligned.m16n8k16.row.col.f32.bf16.bf16.f32 "
        "{%0,%1,%2,%3}, {%4,%5,%6,%7}, {%8,%9}, {%0,%1,%2,%3};"
        : "+f"(d[0]), "+f"(d[1]), "+f"(d[2]), "+f"(d[3])
        : "r"(a[0]), "r"(a[1]), "r"(a[2]), "r"(a[3]), "r"(b[0]), "r"(b[1]));
}
__device__ __forceinline__ uint32_t pack_hi(float a, float b, float& ra, float& rb) {
    __nv_bfloat162 h = __floats2bfloat162_rn(a, b);
    ra = a - __bfloat162float(h.x);
    rb = b - __bfloat162float(h.y);
    return *reinterpret_cast<uint32_t*>(&h);
}
__device__ __forceinline__ uint32_t pack_bf2(float a, float b) {
    __nv_bfloat162 h = __floats2bfloat162_rn(a, b);
    return *reinterpret_cast<uint32_t*>(&h);
}

// ---------------- init ----------------
__global__ void k_init(float* __restrict__ out) {
    int i = blockIdx.x * blockDim.x + threadIdx.x;
    if (i < OUT_ELEMS) out[i] = 0.0f;
    if (blockIdx.x == 0 && threadIdx.x < NE) g_count[threadIdx.x] = 0;
}

// ---------------- fp32 FFMA GEMM for routing path ----------------
__device__ __forceinline__ void gemm_bt_body(
    const float* __restrict__ A, const float* __restrict__ B,
    const float* __restrict__ bias, float* __restrict__ C,
    int M, int N, int K)
{
    __shared__ float As[8][128];
    __shared__ float Bs[8][128];
    const int tid = threadIdx.x;
    const int m0 = blockIdx.y * 128;
    const int n0 = blockIdx.x * 128;
    const int ty = tid >> 4, tx = tid & 15;
    const int lrow = tid >> 1;
    const int lc4 = (tid & 1) * 4;

    float acc[8][8];
#pragma unroll
    for (int i = 0; i < 8; i++)
#pragma unroll
        for (int j = 0; j < 8; j++) acc[i][j] = 0.f;

    for (int k0 = 0; k0 < K; k0 += 8) {
        float4 av = make_float4(0.f, 0.f, 0.f, 0.f);
        float4 bv = make_float4(0.f, 0.f, 0.f, 0.f);
        if (m0 + lrow < M) av = *(const float4*)(A + (size_t)(m0 + lrow) * K + k0 + lc4);
        if (n0 + lrow < N) bv = *(const float4*)(B + (size_t)(n0 + lrow) * K + k0 + lc4);
        As[lc4 + 0][lrow] = av.x; As[lc4 + 1][lrow] = av.y;
        As[lc4 + 2][lrow] = av.z; As[lc4 + 3][lrow] = av.w;
        Bs[lc4 + 0][lrow] = bv.x; Bs[lc4 + 1][lrow] = bv.y;
        Bs[lc4 + 2][lrow] = bv.z; Bs[lc4 + 3][lrow] = bv.w;
        __syncthreads();
#pragma unroll
        for (int k = 0; k < 8; k++) {
            float ra[8], rb[8];
#pragma unroll
            for (int i = 0; i < 8; i++) ra[i] = As[k][ty * 8 + i];
#pragma unroll
            for (int j = 0; j < 8; j++) rb[j] = Bs[k][tx * 8 + j];
#pragma unroll
            for (int i = 0; i < 8; i++)
#pragma unroll
                for (int j = 0; j < 8; j++) acc[i][j] = fmaf(ra[i], rb[j], acc[i][j]);
        }
        __syncthreads();
    }
#pragma unroll
    for (int i = 0; i < 8; i++) {
        int m = m0 + ty * 8 + i;
        if (m >= M) continue;
#pragma unroll
        for (int j = 0; j < 8; j++) {
            int n = n0 + tx * 8 + j;
            if (n < N) C[(size_t)m * N + n] = acc[i][j] + bias[n];
        }
    }
}

__global__ void __launch_bounds__(256) k_proj(const float* __restrict__ x,
                                              const float* __restrict__ Wp,
                                              const float* __restrict__ bp) {
    gemm_bt_body(x, Wp, bp, g_xp, T_TOK, PP, DM);
}
__global__ void __launch_bounds__(256) k_gates_x(const float* __restrict__ W_ih,
                                                 const float* __restrict__ b_ih) {
    gemm_bt_body(g_xp, W_ih, b_ih, g_gx, T_TOK, 3 * PP, PP);
}
__global__ void __launch_bounds__(256) k_gates_h(const float* __restrict__ h_prev,
                                                 const float* __restrict__ W_hh,
                                                 const float* __restrict__ b_hh) {
    gemm_bt_body(h_prev, W_hh, b_hh, g_gh, T_TOK, 3 * PP, PP);
}

// ---------------- GRU + router (top-2) ----------------
__global__ void __launch_bounds__(128) k_gru_route(
    const float* __restrict__ h_prev,
    const float* __restrict__ Wr, const float* __restrict__ br,
    float* __restrict__ h_out)
{
    const int t = blockIdx.x;
    const int j = threadIdx.x;
    __shared__ float hs[PP];
    __shared__ float logit[NE];

    const float* gx = g_gx + (size_t)t * (3 * PP);
    const float* gh = g_gh + (size_t)t * (3 * PP);
    float xr = gx[j], xz = gx[PP + j], xn = gx[2 * PP + j];
    float hr = gh[j], hz = gh[PP + j], hn = gh[2 * PP + j];
    float r = 1.f / (1.f + expf(-(xr + hr)));
    float z = 1.f / (1.f + expf(-(xz + hz)));
    float n = tanhf(xn + r * hn);
    float hp = h_prev[(size_t)t * PP + j];
    float h = (1.f - z) * n + z * hp;
    hs[j] = h;
    h_out[(size_t)t * PP + j] = h;
    __syncthreads();

    const int w = j >> 5, lane = j & 31;
    for (int e = w; e < NE; e += 4) {
        float p = 0.f;
#pragma unroll
        for (int c = 0; c < 4; c++)
            p += Wr[e * PP + lane + 32 * c] * hs[lane + 32 * c];
#pragma unroll
        for (int off = 16; off; off >>= 1) p += __shfl_down_sync(0xffffffffu, p, off);
        if (lane == 0) logit[e] = p + br[e];
    }
    __syncthreads();

    if (j == 0) {
        int e0 = 0, e1 = -1;
        float l0 = logit[0], l1 = -1e30f;
        for (int e = 1; e < NE; e++) {
            float v = logit[e];
            if (v > l0) { l1 = l0; e1 = e0; l0 = v; e0 = e; }
            else if (v > l1) { l1 = v; e1 = e; }
        }
        float p1 = expf(l1 - l0);
        float inv = 1.f / (1.0f + p1);
        float p0 = inv; p1 *= inv;
        int pos0 = atomicAdd(&g_count[e0], 1);
        g_list[e0 * T_TOK + pos0] = t; g_wt[e0 * T_TOK + pos0] = p0;
        int pos1 = atomicAdd(&g_count[e1], 1);
        g_list[e1 * T_TOK + pos1] = t; g_wt[e1 * T_TOK + pos1] = p1;
    }
}

__global__ void k_offsets() {
    if (threadIdx.x == 0) {
        int s = 0;
        for (int e = 0; e < NE; e++) { g_offset[e] = s; s += g_count[e]; }
    }
}

// ============== mma.sync split-bf16 expert up-proj ==============
// H(hi,lo bf16) = relu(gather(X)[128,512] @ W1[e][512, 128-tile of 2048] + b1)
__global__ void __launch_bounds__(256) k_expert_up_mma(
    const float* __restrict__ X, const float* __restrict__ W1,
    const float* __restrict__ b1)
{
    const int e = blockIdx.z;
    const int cnt = g_count[e];
    const int m0 = blockIdx.y * 128;
    if (m0 >= cnt) return;
    const int n0 = blockIdx.x * 128;
    const float* Bw = W1 + (size_t)e * DM * DFF;
    const float* b1e = b1 + (size_t)e * DFF;
    const size_t rowbase = (size_t)g_offset[e] + m0;

    __shared__ __align__(16) __nv_bfloat16 sAhi[128 * (ASTR / 2)];
    __shared__ __align__(16) __nv_bfloat16 sAlo[128 * (ASTR / 2)];
    __shared__ __align__(16) __nv_bfloat16 sBhi[BK * (BSTR / 2)];
    __shared__ __align__(16) __nv_bfloat16 sBlo[BK * (BSTR / 2)];
    __shared__ int rowidx[128];

    const int tid = threadIdx.x;
    const int wid = tid >> 5, lane = tid & 31;
    const int mw = (wid & 3) * 32, nw = (wid >> 2) * 64;

    if (tid < 128)
        rowidx[tid] = (m0 + tid < cnt) ? g_list[e * T_TOK + m0 + tid] : -1;
    __syncthreads();

    const uint32_t aHiB = smem_u32(sAhi), aLoB = smem_u32(sAlo);
    const uint32_t bHiB = smem_u32(sBhi), bLoB = smem_u32(sBlo);

    // prefetch registers
    float4 pa[2][2];   // A: 2 iters x 8 floats
    float4 pb[4];      // B: 4 iters x 4 floats
    int ar[2], aq[2], bkk[4], bn4[4];
#pragma unroll
    for (int i = 0; i < 2; i++) {
        int it = tid + i * 256;
        ar[i] = it >> 2; aq[i] = it & 3;
    }
#pragma unroll
    for (int i = 0; i < 4; i++) {
        int it = tid + i * 256;
        bkk[i] = it >> 5; bn4[i] = (it & 31) * 4;
    }

    // load chunk 0
#pragma unroll
    for (int i = 0; i < 2; i++) {
        int gr = rowidx[ar[i]];
        if (gr >= 0) {
            const float4* p = (const float4*)(X + (size_t)gr * DM + aq[i] * 8);
            pa[i][0] = p[0]; pa[i][1] = p[1];
        } else {
            pa[i][0] = make_float4(0.f, 0.f, 0.f, 0.f); pa[i][1] = pa[i][0];
        }
    }
#pragma unroll
    for (int i = 0; i < 4; i++)
        pb[i] = *(const float4*)(Bw + (size_t)bkk[i] * DFF + n0 + bn4[i]);

    float acc[2][8][4];
#pragma unroll
    for (int a = 0; a < 2; a++)
#pragma unroll
        for (int b = 0; b < 8; b++)
#pragma unroll
            for (int c = 0; c < 4; c++) acc[a][b][c] = 0.f;

    for (int kc = 0; kc < DM; kc += BK) {
        // ---- store prefetched chunk to smem (split hi/lo) ----
#pragma unroll
        for (int i = 0; i < 2; i++) {
            float r0, r1, r2, r3, r4, r5, r6, r7;
            uint4 H, L;
            H.x = pack_hi(pa[i][0].x, pa[i][0].y, r0, r1);
            H.y = pack_hi(pa[i][0].z, pa[i][0].w, r2, r3);
            H.z = pack_hi(pa[i][1].x, pa[i][1].y, r4, r5);
            H.w = pack_hi(pa[i][1].z, pa[i][1].w, r6, r7);
            L.x = pack_bf2(r0, r1); L.y = pack_bf2(r2, r3);
            L.z = pack_bf2(r4, r5); L.w = pack_bf2(r6, r7);
            uint32_t off = (uint32_t)(ar[i] * ASTR + aq[i] * 16);
            *(uint4*)((char*)sAhi + off) = H;
            *(uint4*)((char*)sAlo + off) = L;
        }
#pragma unroll
        for (int i = 0; i < 4; i++) {
            float r0, r1, r2, r3;
            uint2 H, L;
            H.x = pack_hi(pb[i].x, pb[i].y, r0, r1);
            H.y = pack_hi(pb[i].z, pb[i].w, r2, r3);
            L.x = pack_bf2(r0, r1); L.y = pack_bf2(r2, r3);
            uint32_t off = (uint32_t)(bkk[i] * BSTR + bn4[i] * 2);
            *(uint2*)((char*)sBhi + off) = H;
            *(uint2*)((char*)sBlo + off) = L;
        }
        __syncthreads();

        // ---- prefetch next chunk ----
        if (kc + BK < DM) {
            int kc2 = kc + BK;
#pragma unroll
            for (int i = 0; i < 2; i++) {
                int gr = rowidx[ar[i]];
                if (gr >= 0) {
                    const float4* p = (const float4*)(X + (size_t)gr * DM + kc2 + aq[i] * 8);
                    pa[i][0] = p[0]; pa[i][1] = p[1];
                } else {
                    pa[i][0] = make_float4(0.f, 0.f, 0.f, 0.f); pa[i][1] = pa[i][0];
                }
            }
#pragma unroll
            for (int i = 0; i < 4; i++)
                pb[i] = *(const float4*)(Bw + (size_t)(kc2 + bkk[i]) * DFF + n0 + bn4[i]);
        }

        // ---- compute over this chunk ----
#pragma unroll
        for (int ks = 0; ks < 2; ks++) {
            uint32_t ah[2][4], al[2][4];
            uint32_t arow = (uint32_t)((mw + (lane & 15)) * ASTR + ks * 32 + ((lane >> 4) << 4));
            ldmx4(aHiB + arow, ah[0]);
            ldmx4(aHiB + arow + 16 * ASTR, ah[1]);
            ldmx4(aLoB + arow, al[0]);
            ldmx4(aLoB + arow + 16 * ASTR, al[1]);
            uint32_t brow = (uint32_t)((ks * 16 + (lane & 15)) * BSTR + (nw + ((lane >> 4) << 3)) * 2);
#pragma unroll
            for (int nb = 0; nb < 4; nb++) {
                uint32_t bh[4], bl[4];
                ldmx4t(bHiB + brow + nb * 32, bh);
                ldmx4t(bLoB + brow + nb * 32, bl);
#pragma unroll
                for (int mt = 0; mt < 2; mt++) {
                    mma16816(acc[mt][2 * nb],     ah[mt], bh);
                    mma16816(acc[mt][2 * nb],     ah[mt], bl);
                    mma16816(acc[mt][2 * nb],     al[mt], bh);
                    mma16816(acc[mt][2 * nb + 1], ah[mt], bh + 2);
                    mma16816(acc[mt][2 * nb + 1], ah[mt], bl + 2);
                    mma16816(acc[mt][2 * nb + 1], al[mt], bh + 2);
                }
            }
        }
        __syncthreads();
    }

    // ---- epilogue: bias + relu -> split hi/lo -> g_hid ----
#pragma unroll
    for (int mt = 0; mt < 2; mt++) {
        int lr0 = mw + mt * 16 + (lane >> 2);
        int lr1 = lr0 + 8;
        bool ok0 = (m0 + lr0 < cnt), ok1 = (m0 + lr1 < cnt);
        size_t row0 = rowbase + lr0, row1 = rowbase + lr1;
#pragma unroll
        for (int nt = 0; nt < 8; nt++) {
            int c = nw + nt * 8 + (lane & 3) * 2;
            float bz0 = __ldg(&b1e[n0 + c]), bz1 = __ldg(&b1e[n0 + c + 1]);
            if (ok0) {
                float v0 = fmaxf(acc[mt][nt][0] + bz0, 0.f);
                float v1 = fmaxf(acc[mt][nt][1] + bz1, 0.f);
                float r0, r1;
                uint32_t H = pack_hi(v0, v1, r0, r1);
                uint32_t L = pack_bf2(r0, r1);
                *(uint32_t*)(g_hid_hi + row0 * DFF + n0 + c) = H;
                *(uint32_t*)(g_hid_lo + row0 * DFF + n0 + c) = L;
            }
            if (ok1) {
                float v0 = fmaxf(acc[mt][nt][2] + bz0, 0.f);
                float v1 = fmaxf(acc[mt][nt][3] + bz1, 0.f);
                float r0, r1;
                uint32_t H = pack_hi(v0, v1, r0, r1);
                uint32_t L = pack_bf2(r0, r1);
                *(uint32_t*)(g_hid_hi + row1 * DFF + n0 + c) = H;
                *(uint32_t*)(g_hid_lo + row1 * DFF + n0 + c) = L;
            }
        }
    }
}

// ============== mma.sync split-bf16 expert down-proj ==============
// out[tok] += w * (H[128,2048] @ W2[e][2048, 128-tile of 512] + b2)
__global__ void __launch_bounds__(256) k_expert_down_mma(
    const float* __restrict__ W2, const float* __restrict__ b2,
    float* __restrict__ out)
{
    const int e = blockIdx.z;
    const int cnt = g_count[e];
    const int m0 = blockIdx.y * 128;
    if (m0 >= cnt) return;
    const int n0 = blockIdx.x * 128;
    const float* Bw = W2 + (size_t)e * DFF * DM;
    const float* b2e = b2 + (size_t)e * DM;
    const size_t rowbase = (size_t)g_offset[e] + m0;

    __shared__ __align__(16) __nv_bfloat16 sAhi[128 * (ASTR / 2)];
    __shared__ __align__(16) __nv_bfloat16 sAlo[128 * (ASTR / 2)];
    __shared__ __align__(16) __nv_bfloat16 sBhi[BK * (BSTR / 2)];
    __shared__ __align__(16) __nv_bfloat16 sBlo[BK * (BSTR / 2)];
    __shared__ int s_tok[128];
    __shared__ float s_w[128];

    const int tid = threadIdx.x;
    const int wid = tid >> 5, lane = tid & 31;
    const int mw = (wid & 3) * 32, nw = (wid >> 2) * 64;

    if (tid < 128) {
        bool ok = (m0 + tid < cnt);
        s_tok[tid] = ok ? g_list[e * T_TOK + m0 + tid] : 0;
        s_w[tid] = ok ? g_wt[e * T_TOK + m0 + tid] : 0.f;
    }
    __syncthreads();

    const uint32_t aHiB = smem_u32(sAhi), aLoB = smem_u32(sAlo);
    const uint32_t bHiB = smem_u32(sBhi), bLoB = smem_u32(sBlo);

    uint4 pah[2], pal[2];
    float4 pb[4];
    int ar[2], aq[2], bkk[4], bn4[4];
#pragma unroll
    for (int i = 0; i < 2; i++) {
        int it = tid + i * 256;
        ar[i] = it >> 2; aq[i] = it & 3;
    }
#pragma unroll
    for (int i = 0; i < 4; i++) {
        int it = tid + i * 256;
        bkk[i] = it >> 5; bn4[i] = (it & 31) * 4;
    }

    // load chunk 0
#pragma unroll
    for (int i = 0; i < 2; i++) {
        if (m0 + ar[i] < cnt) {
            size_t row = rowbase + ar[i];
            pah[i] = *(const uint4*)(g_hid_hi + row * DFF + aq[i] * 8);
            pal[i] = *(const uint4*)(g_hid_lo + row * DFF + aq[i] * 8);
        } else {
            pah[i] = make_uint4(0, 0, 0, 0); pal[i] = pah[i];
        }
    }
#pragma unroll
    for (int i = 0; i < 4; i++)
        pb[i] = *(const float4*)(Bw + (size_t)bkk[i] * DM + n0 + bn4[i]);

    float acc[2][8][4];
#pragma unroll
    for (int a = 0; a < 2; a++)
#pragma unroll
        for (int b = 0; b < 8; b++)
#pragma unroll
            for (int c = 0; c < 4; c++) acc[a][b][c] = 0.f;

    for (int kc = 0; kc < DFF; kc += BK) {
#pragma unroll
        for (int i = 0; i < 2; i++) {
            uint32_t off = (uint32_t)(ar[i] * ASTR + aq[i] * 16);
            *(uint4*)((char*)sAhi + off) = pah[i];
            *(uint4*)((char*)sAlo + off) = pal[i];
        }
#pragma unroll
        for (int i = 0; i < 4; i++) {
            float r0, r1, r2, r3;
            uint2 H, L;
            H.x = pack_hi(pb[i].x, pb[i].y, r0, r1);
            H.y = pack_hi(pb[i].z, pb[i].w, r2, r3);
            L.x = pack_bf2(r0, r1); L.y = pack_bf2(r2, r3);
            uint32_t off = (uint32_t)(bkk[i] * BSTR + bn4[i] * 2);
            *(uint2*)((char*)sBhi + off) = H;
            *(uint2*)((char*)sBlo + off) = L;
        }
        __syncthreads();

        if (kc + BK < DFF) {
            int kc2 = kc + BK;
#pragma unroll
            for (int i = 0; i < 2; i++) {
                if (m0 + ar[i] < cnt) {
                    size_t row = rowbase + ar[i];
                    pah[i] = *(const uint4*)(g_hid_hi + row * DFF + kc2 + aq[i] * 8);
                    pal[i] = *(const uint4*)(g_hid_lo + row * DFF + kc2 + aq[i] * 8);
                } else {
                    pah[i] = make_uint4(0, 0, 0, 0); pal[i] = pah[i];
                }
            }
#pragma unroll
            for (int i = 0; i < 4; i++)
                pb[i] = *(const float4*)(Bw + (size_t)(kc2 + bkk[i]) * DM + n0 + bn4[i]);
        }

#pragma unroll
        for (int ks = 0; ks < 2; ks++) {
            uint32_t ah[2][4], al[2][4];
            uint32_t arow = (uint32_t)((mw + (lane & 15)) * ASTR + ks * 32 + ((lane >> 4) << 4));
            ldmx4(aHiB + arow, ah[0]);
            ldmx4(aHiB + arow + 16 * ASTR, ah[1]);
            ldmx4(aLoB + arow, al[0]);
            ldmx4(aLoB + arow + 16 * ASTR, al[1]);
            uint32_t brow = (uint32_t)((ks * 16 + (lane & 15)) * BSTR + (nw + ((lane >> 4) << 3)) * 2);
#pragma unroll
            for (int nb = 0; nb < 4; nb++) {
                uint32_t bh[4], bl[4];
                ldmx4t(bHiB + brow + nb * 32, bh);
                ldmx4t(bLoB + brow + nb * 32, bl);
#pragma unroll
                for (int mt = 0; mt < 2; mt++) {
                    mma16816(acc[mt][2 * nb],     ah[mt], bh);
                    mma16816(acc[mt][2 * nb],     ah[mt], bl);
                    mma16816(acc[mt][2 * nb],     al[mt], bh);
                    mma16816(acc[mt][2 * nb + 1], ah[mt], bh + 2);
                    mma16816(acc[mt][2 * nb + 1], ah[mt], bl + 2);
                    mma16816(acc[mt][2 * nb + 1], al[mt], bh + 2);
                }
            }
        }
        __syncthreads();
    }

    // ---- epilogue: bias + weighted atomic scatter ----
#pragma unroll
    for (int mt = 0; mt < 2; mt++) {
        int lr0 = mw + mt * 16 + (lane >> 2);
        int lr1 = lr0 + 8;
        bool ok0 = (m0 + lr0 < cnt), ok1 = (m0 + lr1 < cnt);
        int tok0 = s_tok[lr0], tok1 = s_tok[lr1];
        float w0 = s_w[lr0], w1 = s_w[lr1];
#pragma unroll
        for (int nt = 0; nt < 8; nt++) {
            int c = nw + nt * 8 + (lane & 3) * 2;
            float bz0 = __ldg(&b2e[n0 + c]), bz1 = __ldg(&b2e[n0 + c + 1]);
            if (ok0) {
                float* op = out + (size_t)tok0 * DM + n0 + c;
                atomicAdd(op,     w0 * (acc[mt][nt][0] + bz0));
                atomicAdd(op + 1, w0 * (acc[mt][nt][1] + bz1));
            }
            if (ok1) {
                float* op = out + (size_t)tok1 * DM + n0 + c;
                atomicAdd(op,     w1 * (acc[mt][nt][2] + bz0));
                atomicAdd(op + 1, w1 * (acc[mt][nt][3] + bz1));
            }
        }
    }
}

// ---------------- host launcher ----------------
extern "C" void kernel_launch(void* const* d_in, const int* in_sizes, int n_in,
                              void* d_out, int out_size) {
    const float* x      = (const float*)d_in[0];
    const float* h_prev = (const float*)d_in[1];
    const float* Wp     = (const float*)d_in[2];
    const float* bp     = (const float*)d_in[3];
    const float* W_ih   = (const float*)d_in[4];
    const float* W_hh   = (const float*)d_in[5];
    const float* b_ih   = (const float*)d_in[6];
    const float* b_hh   = (const float*)d_in[7];
    const float* Wr     = (const float*)d_in[8];
    const float* br     = (const float*)d_in[9];
    const float* W1     = (const float*)d_in[10];
    const float* b1     = (const float*)d_in[11];
    const float* W2     = (const float*)d_in[12];
    const float* b2     = (const float*)d_in[13];

    float* out   = (float*)d_out;
    float* h_out = out + OUT_ELEMS;

    k_init<<<(OUT_ELEMS + 255) / 256, 256>>>(out);
    k_proj<<<dim3(1, T_TOK / 128), 256>>>(x, Wp, bp);
    k_gates_x<<<dim3(3, T_TOK / 128), 256>>>(W_ih, b_ih);
    k_gates_h<<<dim3(3, T_TOK / 128), 256>>>(h_prev, W_hh, b_hh);
    k_gru_route<<<T_TOK, 128>>>(h_prev, Wr, br, h_out);
    k_offsets<<<1, 1>>>();
    k_expert_up_mma<<<dim3(DFF / 128, T_TOK / 128, NE), 256>>>(x, W1, b1);
    k_expert_down_mma<<<dim3(DM / 128, T_TOK / 128, NE), 256>>>(W2, b2, out);
}

// round 4
// speedup vs baseline: 2.0512x; 1.0021x over previous
#include <cuda_runtime.h>
#include <cuda_bf16.h>
#include <cstdint>
#include <math.h>

#define T_TOK 4096
#define DM 512
#define DFF 2048
#define NE 16
#define PP 128
#define OUT_ELEMS (T_TOK * DM)
#define BK 32

// smem strides (bytes)
#define ASTR 80    // 32 bf16 (64B) + 16B pad
#define BSTR 272   // 128 bf16 (256B) + 16B pad
// per-stage offsets (bytes)
#define OFF_ALO 10240
#define OFF_BHI 20480
#define OFF_BLO 29184
#define STAGE   37888
#define DYN_SMEM (2 * STAGE)

// ---------------- device scratch ----------------
__device__ float g_gx[T_TOK * 3 * PP];
__device__ float g_gh[T_TOK * 3 * PP];
__device__ float g_Wc[3 * PP * DM];
__device__ float g_bc[3 * PP];
__device__ __nv_bfloat16 g_xhi[T_TOK * DM];
__device__ __nv_bfloat16 g_xlo[T_TOK * DM];
__device__ __nv_bfloat16 g_w1hi[(size_t)NE * DM * DFF];
__device__ __nv_bfloat16 g_w1lo[(size_t)NE * DM * DFF];
__device__ __nv_bfloat16 g_w2hi[(size_t)NE * DFF * DM];
__device__ __nv_bfloat16 g_w2lo[(size_t)NE * DFF * DM];
__device__ __nv_bfloat16 g_hid_hi[(size_t)T_TOK * 2 * DFF];
__device__ __nv_bfloat16 g_hid_lo[(size_t)T_TOK * 2 * DFF];
__device__ int   g_list[NE * T_TOK];
__device__ float g_wt[NE * T_TOK];
__device__ int   g_count[NE];
__device__ int   g_offset[NE];

// ---------------- helpers ----------------
__device__ __forceinline__ uint32_t smem_u32(const void* p) {
    uint32_t a;
    asm("{ .reg .u64 t; cvta.to.shared.u64 t, %1; cvt.u32.u64 %0, t; }"
        : "=r"(a) : "l"(p));
    return a;
}
__device__ __forceinline__ void ldmx4(uint32_t addr, uint32_t* r) {
    asm volatile("ldmatrix.sync.aligned.m8n8.x4.shared.b16 {%0,%1,%2,%3}, [%4];"
                 : "=r"(r[0]), "=r"(r[1]), "=r"(r[2]), "=r"(r[3]) : "r"(addr));
}
__device__ __forceinline__ void ldmx4t(uint32_t addr, uint32_t* r) {
    asm volatile("ldmatrix.sync.aligned.m8n8.x4.trans.shared.b16 {%0,%1,%2,%3}, [%4];"
                 : "=r"(r[0]), "=r"(r[1]), "=r"(r[2]), "=r"(r[3]) : "r"(addr));
}
__device__ __forceinline__ void mma16816(float* d, const uint32_t* a,
                                         const uint32_t* b) {
    asm volatile(
        "mma.sync.aligned.m16n8k16.row.col.f32.bf16.bf16.f32 "
        "{%0,%1,%2,%3}, {%4,%5,%6,%7}, {%8,%9}, {%0,%1,%2,%3};"
        : "+f"(d[0]), "+f"(d[1]), "+f"(d[2]), "+f"(d[3])
        : "r"(a[0]), "r"(a[1]), "r"(a[2]), "r"(a[3]), "r"(b[0]), "r"(b[1]));
}
__device__ __forceinline__ void cp16(uint32_t dst, const void* src, bool ok) {
    int sz = ok ? 16 : 0;
    asm volatile("cp.async.cg.shared.global [%0], [%1], 16, %2;"
                 :: "r"(dst), "l"(src), "r"(sz) : "memory");
}
#define CP_COMMIT() asm volatile("cp.async.commit_group;" ::: "memory")
template <int N>
__device__ __forceinline__ void cp_wait() {
    asm volatile("cp.async.wait_group %0;" :: "n"(N) : "memory");
}
__device__ __forceinline__ uint32_t pack_hi(float a, float b, float& ra, float& rb) {
    __nv_bfloat162 h = __floats2bfloat162_rn(a, b);
    ra = a - __bfloat162float(h.x);
    rb = b - __bfloat162float(h.y);
    return *reinterpret_cast<uint32_t*>(&h);
}
__device__ __forceinline__ uint32_t pack_bf2(float a, float b) {
    __nv_bfloat162 h = __floats2bfloat162_rn(a, b);
    return *reinterpret_cast<uint32_t*>(&h);
}

// ---------------- init ----------------
__global__ void k_init(float* __restrict__ out) {
    int i = blockIdx.x * blockDim.x + threadIdx.x;
    if (i < OUT_ELEMS) out[i] = 0.0f;
    if (blockIdx.x == 0 && threadIdx.x < NE) g_count[threadIdx.x] = 0;
}

// ---------------- fp32 -> hi/lo bf16 split (streaming) ----------------
__global__ void k_conv(const float4* __restrict__ src, uint2* __restrict__ hi,
                       uint2* __restrict__ lo, int n4) {
    for (int i = blockIdx.x * blockDim.x + threadIdx.x; i < n4;
         i += gridDim.x * blockDim.x) {
        float4 v = src[i];
        float r0, r1, r2, r3;
        uint2 H, L;
        H.x = pack_hi(v.x, v.y, r0, r1);
        H.y = pack_hi(v.z, v.w, r2, r3);
        L.x = pack_bf2(r0, r1);
        L.y = pack_bf2(r2, r3);
        hi[i] = H;
        lo[i] = L;
    }
}

// ---------------- fold projector into gate weights ----------------
// Wc = W_ih @ Wp  [384,512],  bc = W_ih @ bp + b_ih
__global__ void __launch_bounds__(128) k_fold(
    const float* __restrict__ Wp, const float* __restrict__ bp,
    const float* __restrict__ W_ih, const float* __restrict__ b_ih)
{
    const int nrow = blockIdx.x;  // 0..383
    __shared__ float wrow[PP];
    const int tid = threadIdx.x;
    wrow[tid] = W_ih[nrow * PP + tid];
    __syncthreads();
    for (int d = tid; d < DM; d += 128) {
        float s = 0.f;
#pragma unroll 8
        for (int p = 0; p < PP; p++) s = fmaf(wrow[p], Wp[p * DM + d], s);
        g_Wc[nrow * DM + d] = s;
    }
    if (tid == 0) {
        float s = b_ih[nrow];
        for (int p = 0; p < PP; p++) s = fmaf(wrow[p], bp[p], s);
        g_bc[nrow] = s;
    }
}

// ---------------- fp32 FFMA GEMM for routing path ----------------
__device__ __forceinline__ void gemm_bt_body(
    const float* __restrict__ A, const float* __restrict__ B,
    const float* __restrict__ bias, float* __restrict__ C,
    int M, int N, int K)
{
    __shared__ float As[8][128];
    __shared__ float Bs[8][128];
    const int tid = threadIdx.x;
    const int m0 = blockIdx.y * 128;
    const int n0 = blockIdx.x * 128;
    const int ty = tid >> 4, tx = tid & 15;
    const int lrow = tid >> 1;
    const int lc4 = (tid & 1) * 4;

    float acc[8][8];
#pragma unroll
    for (int i = 0; i < 8; i++)
#pragma unroll
        for (int j = 0; j < 8; j++) acc[i][j] = 0.f;

    for (int k0 = 0; k0 < K; k0 += 8) {
        float4 av = make_float4(0.f, 0.f, 0.f, 0.f);
        float4 bv = make_float4(0.f, 0.f, 0.f, 0.f);
        if (m0 + lrow < M) av = *(const float4*)(A + (size_t)(m0 + lrow) * K + k0 + lc4);
        if (n0 + lrow < N) bv = *(const float4*)(B + (size_t)(n0 + lrow) * K + k0 + lc4);
        As[lc4 + 0][lrow] = av.x; As[lc4 + 1][lrow] = av.y;
        As[lc4 + 2][lrow] = av.z; As[lc4 + 3][lrow] = av.w;
        Bs[lc4 + 0][lrow] = bv.x; Bs[lc4 + 1][lrow] = bv.y;
        Bs[lc4 + 2][lrow] = bv.z; Bs[lc4 + 3][lrow] = bv.w;
        __syncthreads();
#pragma unroll
        for (int k = 0; k < 8; k++) {
            float ra[8], rb[8];
#pragma unroll
            for (int i = 0; i < 8; i++) ra[i] = As[k][ty * 8 + i];
#pragma unroll
            for (int j = 0; j < 8; j++) rb[j] = Bs[k][tx * 8 + j];
#pragma unroll
            for (int i = 0; i < 8; i++)
#pragma unroll
                for (int j = 0; j < 8; j++) acc[i][j] = fmaf(ra[i], rb[j], acc[i][j]);
        }
        __syncthreads();
    }
#pragma unroll
    for (int i = 0; i < 8; i++) {
        int m = m0 + ty * 8 + i;
        if (m >= M) continue;
#pragma unroll
        for (int j = 0; j < 8; j++) {
            int n = n0 + tx * 8 + j;
            if (n < N) C[(size_t)m * N + n] = acc[i][j] + bias[n];
        }
    }
}

__global__ void __launch_bounds__(256) k_gates_x(const float* __restrict__ x) {
    gemm_bt_body(x, g_Wc, g_bc, g_gx, T_TOK, 3 * PP, DM);
}
__global__ void __launch_bounds__(256) k_gates_h(const float* __restrict__ h_prev,
                                                 const float* __restrict__ W_hh,
                                                 const float* __restrict__ b_hh) {
    gemm_bt_body(h_prev, W_hh, b_hh, g_gh, T_TOK, 3 * PP, PP);
}

// ---------------- GRU + router (top-2) ----------------
__global__ void __launch_bounds__(128) k_gru_route(
    const float* __restrict__ h_prev,
    const float* __restrict__ Wr, const float* __restrict__ br,
    float* __restrict__ h_out)
{
    const int t = blockIdx.x;
    const int j = threadIdx.x;
    __shared__ float hs[PP];
    __shared__ float logit[NE];

    const float* gx = g_gx + (size_t)t * (3 * PP);
    const float* gh = g_gh + (size_t)t * (3 * PP);
    float xr = gx[j], xz = gx[PP + j], xn = gx[2 * PP + j];
    float hr = gh[j], hz = gh[PP + j], hn = gh[2 * PP + j];
    float r = 1.f / (1.f + expf(-(xr + hr)));
    float z = 1.f / (1.f + expf(-(xz + hz)));
    float n = tanhf(xn + r * hn);
    float hp = h_prev[(size_t)t * PP + j];
    float h = (1.f - z) * n + z * hp;
    hs[j] = h;
    h_out[(size_t)t * PP + j] = h;
    __syncthreads();

    const int w = j >> 5, lane = j & 31;
    for (int e = w; e < NE; e += 4) {
        float p = 0.f;
#pragma unroll
        for (int c = 0; c < 4; c++)
            p += Wr[e * PP + lane + 32 * c] * hs[lane + 32 * c];
#pragma unroll
        for (int off = 16; off; off >>= 1) p += __shfl_down_sync(0xffffffffu, p, off);
        if (lane == 0) logit[e] = p + br[e];
    }
    __syncthreads();

    if (j == 0) {
        int e0 = 0, e1 = -1;
        float l0 = logit[0], l1 = -1e30f;
        for (int e = 1; e < NE; e++) {
            float v = logit[e];
            if (v > l0) { l1 = l0; e1 = e0; l0 = v; e0 = e; }
            else if (v > l1) { l1 = v; e1 = e; }
        }
        float p1 = expf(l1 - l0);
        float inv = 1.f / (1.0f + p1);
        float p0 = inv; p1 *= inv;
        int pos0 = atomicAdd(&g_count[e0], 1);
        g_list[e0 * T_TOK + pos0] = t; g_wt[e0 * T_TOK + pos0] = p0;
        int pos1 = atomicAdd(&g_count[e1], 1);
        g_list[e1 * T_TOK + pos1] = t; g_wt[e1 * T_TOK + pos1] = p1;
    }
}

__global__ void k_offsets() {
    if (threadIdx.x == 0) {
        int s = 0;
        for (int e = 0; e < NE; e++) { g_offset[e] = s; s += g_count[e]; }
    }
}

// ============== shared compute body (ldmatrix + 3-product MMA) ==============
__device__ __forceinline__ void chunk_compute(
    uint32_t sb, int mw, int nw, int lane, float acc[2][8][4])
{
#pragma unroll
    for (int ks = 0; ks < 2; ks++) {
        uint32_t ah[2][4], al[2][4];
        uint32_t arow = (uint32_t)((mw + (lane & 15)) * ASTR + ks * 32 + ((lane >> 4) << 4));
        ldmx4(sb + arow, ah[0]);
        ldmx4(sb + arow + 16 * ASTR, ah[1]);
        ldmx4(sb + OFF_ALO + arow, al[0]);
        ldmx4(sb + OFF_ALO + arow + 16 * ASTR, al[1]);
        uint32_t brow = (uint32_t)((ks * 16 + (lane & 15)) * BSTR + (nw + ((lane >> 4) << 3)) * 2);
#pragma unroll
        for (int nb = 0; nb < 4; nb++) {
            uint32_t bh[4], bl[4];
            ldmx4t(sb + OFF_BHI + brow + nb * 32, bh);
            ldmx4t(sb + OFF_BLO + brow + nb * 32, bl);
#pragma unroll
            for (int mt = 0; mt < 2; mt++) {
                mma16816(acc[mt][2 * nb],     ah[mt], bh);
                mma16816(acc[mt][2 * nb],     ah[mt], bl);
                mma16816(acc[mt][2 * nb],     al[mt], bh);
                mma16816(acc[mt][2 * nb + 1], ah[mt], bh + 2);
                mma16816(acc[mt][2 * nb + 1], ah[mt], bl + 2);
                mma16816(acc[mt][2 * nb + 1], al[mt], bh + 2);
            }
        }
    }
}

// ============== expert up-proj (cp.async double-buffer) ==============
__global__ void __launch_bounds__(256) k_expert_up_mma(
    const float* __restrict__ b1)
{
    const int e = blockIdx.z;
    const int cnt = g_count[e];
    const int m0 = blockIdx.y * 128;
    if (m0 >= cnt) return;
    const int n0 = blockIdx.x * 128;
    const float* b1e = b1 + (size_t)e * DFF;
    const size_t rowbase = (size_t)g_offset[e] + m0;

    extern __shared__ __align__(16) char dsm[];
    const uint32_t smb = smem_u32(dsm);
    __shared__ int rowidx[128];

    const int tid = threadIdx.x;
    const int wid = tid >> 5, lane = tid & 31;
    const int mw = (wid & 3) * 32, nw = (wid >> 2) * 64;

    if (tid < 128)
        rowidx[tid] = (m0 + tid < cnt) ? g_list[e * T_TOK + m0 + tid] : -1;
    __syncthreads();

    // staging source pointers (chunk-invariant part)
    const __nv_bfloat16* srcA[2];
    bool okA[2];
    uint32_t dstA[2];
#pragma unroll
    for (int i = 0; i < 2; i++) {
        int it = tid + i * 256;
        int r = it >> 2, q = it & 3;
        int gr = rowidx[r];
        okA[i] = (gr >= 0);
        srcA[i] = g_xhi + (size_t)(okA[i] ? gr : 0) * DM + q * 8;
        dstA[i] = (uint32_t)(r * ASTR + q * 16);
    }
    const __nv_bfloat16* srcB[2];
    uint32_t dstB[2];
#pragma unroll
    for (int i = 0; i < 2; i++) {
        int it = tid + i * 256;
        int k = it >> 4, c = it & 15;
        srcB[i] = g_w1hi + (size_t)e * DM * DFF + (size_t)k * DFF + n0 + c * 8;
        dstB[i] = (uint32_t)(k * BSTR + c * 16);
    }
    const ptrdiff_t dLoA = g_xlo - g_xhi;
    const ptrdiff_t dLoB = g_w1lo - g_w1hi;

    float acc[2][8][4];
#pragma unroll
    for (int a = 0; a < 2; a++)
#pragma unroll
        for (int b = 0; b < 8; b++)
#pragma unroll
            for (int c = 0; c < 4; c++) acc[a][b][c] = 0.f;

    // prologue: stage chunk 0 into buffer 0
#pragma unroll
    for (int i = 0; i < 2; i++) {
        cp16(smb + dstA[i], srcA[i], okA[i]);
        cp16(smb + OFF_ALO + dstA[i], srcA[i] + dLoA, okA[i]);
        cp16(smb + OFF_BHI + dstB[i], srcB[i], true);
        cp16(smb + OFF_BLO + dstB[i], srcB[i] + dLoB, true);
    }
    CP_COMMIT();

    const int NK = DM / BK;  // 16
    for (int c = 0; c < NK; c++) {
        const int s = c & 1;
        if (c + 1 < NK) {
            const uint32_t nb = smb + (s ^ 1) * STAGE;
            const int kc = (c + 1) * BK;
#pragma unroll
            for (int i = 0; i < 2; i++) {
                cp16(nb + dstA[i], srcA[i] + kc, okA[i]);
                cp16(nb + OFF_ALO + dstA[i], srcA[i] + dLoA + kc, okA[i]);
                cp16(nb + OFF_BHI + dstB[i], srcB[i] + (size_t)kc * DFF, true);
                cp16(nb + OFF_BLO + dstB[i], srcB[i] + dLoB + (size_t)kc * DFF, true);
            }
            CP_COMMIT();
            cp_wait<1>();
        } else {
            cp_wait<0>();
        }
        __syncthreads();
        chunk_compute(smb + s * STAGE, mw, nw, lane, acc);
        __syncthreads();
    }

    // ---- epilogue: bias + relu -> split hi/lo -> g_hid ----
#pragma unroll
    for (int mt = 0; mt < 2; mt++) {
        int lr0 = mw + mt * 16 + (lane >> 2);
        int lr1 = lr0 + 8;
        bool ok0 = (m0 + lr0 < cnt), ok1 = (m0 + lr1 < cnt);
        size_t row0 = rowbase + lr0, row1 = rowbase + lr1;
#pragma unroll
        for (int nt = 0; nt < 8; nt++) {
            int c = nw + nt * 8 + (lane & 3) * 2;
            float bz0 = __ldg(&b1e[n0 + c]), bz1 = __ldg(&b1e[n0 + c + 1]);
            if (ok0) {
                float v0 = fmaxf(acc[mt][nt][0] + bz0, 0.f);
                float v1 = fmaxf(acc[mt][nt][1] + bz1, 0.f);
                float r0, r1;
                uint32_t H = pack_hi(v0, v1, r0, r1);
                uint32_t L = pack_bf2(r0, r1);
                *(uint32_t*)(g_hid_hi + row0 * DFF + n0 + c) = H;
                *(uint32_t*)(g_hid_lo + row0 * DFF + n0 + c) = L;
            }
            if (ok1) {
                float v0 = fmaxf(acc[mt][nt][2] + bz0, 0.f);
                float v1 = fmaxf(acc[mt][nt][3] + bz1, 0.f);
                float r0, r1;
                uint32_t H = pack_hi(v0, v1, r0, r1);
                uint32_t L = pack_bf2(r0, r1);
                *(uint32_t*)(g_hid_hi + row1 * DFF + n0 + c) = H;
                *(uint32_t*)(g_hid_lo + row1 * DFF + n0 + c) = L;
            }
        }
    }
}

// ============== expert down-proj (cp.async double-buffer) ==============
__global__ void __launch_bounds__(256) k_expert_down_mma(
    const float* __restrict__ b2, float* __restrict__ out)
{
    const int e = blockIdx.z;
    const int cnt = g_count[e];
    const int m0 = blockIdx.y * 128;
    if (m0 >= cnt) return;
    const int n0 = blockIdx.x * 128;
    const float* b2e = b2 + (size_t)e * DM;
    const size_t rowbase = (size_t)g_offset[e] + m0;

    extern __shared__ __align__(16) char dsm[];
    const uint32_t smb = smem_u32(dsm);
    __shared__ int s_tok[128];
    __shared__ float s_w[128];

    const int tid = threadIdx.x;
    const int wid = tid >> 5, lane = tid & 31;
    const int mw = (wid & 3) * 32, nw = (wid >> 2) * 64;

    if (tid < 128) {
        bool ok = (m0 + tid < cnt);
        s_tok[tid] = ok ? g_list[e * T_TOK + m0 + tid] : 0;
        s_w[tid] = ok ? g_wt[e * T_TOK + m0 + tid] : 0.f;
    }
    __syncthreads();

    const __nv_bfloat16* srcA[2];
    bool okA[2];
    uint32_t dstA[2];
#pragma unroll
    for (int i = 0; i < 2; i++) {
        int it = tid + i * 256;
        int r = it >> 2, q = it & 3;
        okA[i] = (m0 + r < cnt);
        srcA[i] = g_hid_hi + (okA[i] ? (rowbase + r) : 0) * DFF + q * 8;
        dstA[i] = (uint32_t)(r * ASTR + q * 16);
    }
    const __nv_bfloat16* srcB[2];
    uint32_t dstB[2];
#pragma unroll
    for (int i = 0; i < 2; i++) {
        int it = tid + i * 256;
        int k = it >> 4, c = it & 15;
        srcB[i] = g_w2hi + (size_t)e * DFF * DM + (size_t)k * DM + n0 + c * 8;
        dstB[i] = (uint32_t)(k * BSTR + c * 16);
    }
    const ptrdiff_t dLoA = g_hid_lo - g_hid_hi;
    const ptrdiff_t dLoB = g_w2lo - g_w2hi;

    float acc[2][8][4];
#pragma unroll
    for (int a = 0; a < 2; a++)
#pragma unroll
        for (int b = 0; b < 8; b++)
#pragma unroll
            for (int c = 0; c < 4; c++) acc[a][b][c] = 0.f;

#pragma unroll
    for (int i = 0; i < 2; i++) {
        cp16(smb + dstA[i], srcA[i], okA[i]);
        cp16(smb + OFF_ALO + dstA[i], srcA[i] + dLoA, okA[i]);
        cp16(smb + OFF_BHI + dstB[i], srcB[i], true);
        cp16(smb + OFF_BLO + dstB[i], srcB[i] + dLoB, true);
    }
    CP_COMMIT();

    const int NK = DFF / BK;  // 64
    for (int c = 0; c < NK; c++) {
        const int s = c & 1;
        if (c + 1 < NK) {
            const uint32_t nb = smb + (s ^ 1) * STAGE;
            const int kc = (c + 1) * BK;
#pragma unroll
            for (int i = 0; i < 2; i++) {
                cp16(nb + dstA[i], srcA[i] + kc, okA[i]);
                cp16(nb + OFF_ALO + dstA[i], srcA[i] + dLoA + kc, okA[i]);
                cp16(nb + OFF_BHI + dstB[i], srcB[i] + (size_t)kc * DM, true);
                cp16(nb + OFF_BLO + dstB[i], srcB[i] + dLoB + (size_t)kc * DM, true);
            }
            CP_COMMIT();
            cp_wait<1>();
        } else {
            cp_wait<0>();
        }
        __syncthreads();
        chunk_compute(smb + s * STAGE, mw, nw, lane, acc);
        __syncthreads();
    }

    // ---- epilogue: bias + weighted atomic scatter ----
#pragma unroll
    for (int mt = 0; mt < 2; mt++) {
        int lr0 = mw + mt * 16 + (lane >> 2);
        int lr1 = lr0 + 8;
        bool ok0 = (m0 + lr0 < cnt), ok1 = (m0 + lr1 < cnt);
        int tok0 = s_tok[lr0], tok1 = s_tok[lr1];
        float w0 = s_w[lr0], w1 = s_w[lr1];
#pragma unroll
        for (int nt = 0; nt < 8; nt++) {
            int c = nw + nt * 8 + (lane & 3) * 2;
            float bz0 = __ldg(&b2e[n0 + c]), bz1 = __ldg(&b2e[n0 + c + 1]);
            if (ok0) {
                float* op = out + (size_t)tok0 * DM + n0 + c;
                atomicAdd(op,     w0 * (acc[mt][nt][0] + bz0));
                atomicAdd(op + 1, w0 * (acc[mt][nt][1] + bz1));
            }
            if (ok1) {
                float* op = out + (size_t)tok1 * DM + n0 + c;
                atomicAdd(op,     w1 * (acc[mt][nt][2] + bz0));
                atomicAdd(op + 1, w1 * (acc[mt][nt][3] + bz1));
            }
        }
    }
}

// ---------------- host launcher ----------------
extern "C" void kernel_launch(void* const* d_in, const int* in_sizes, int n_in,
                              void* d_out, int out_size) {
    const float* x      = (const float*)d_in[0];
    const float* h_prev = (const float*)d_in[1];
    const float* Wp     = (const float*)d_in[2];
    const float* bp     = (const float*)d_in[3];
    const float* W_ih   = (const float*)d_in[4];
    const float* W_hh   = (const float*)d_in[5];
    const float* b_hh   = (const float*)d_in[7];
    const float* b_ih   = (const float*)d_in[6];
    const float* Wr     = (const float*)d_in[8];
    const float* br     = (const float*)d_in[9];
    const float* W1     = (const float*)d_in[10];
    const float* b1     = (const float*)d_in[11];
    const float* W2     = (const float*)d_in[12];
    const float* b2     = (const float*)d_in[13];

    float* out   = (float*)d_out;
    float* h_out = out + OUT_ELEMS;

    static bool attr_set = false;
    if (!attr_set) {
        cudaFuncSetAttribute(k_expert_up_mma,
                             cudaFuncAttributeMaxDynamicSharedMemorySize, DYN_SMEM);
        cudaFuncSetAttribute(k_expert_down_mma,
                             cudaFuncAttributeMaxDynamicSharedMemorySize, DYN_SMEM);
        attr_set = true;
    }

    // resolve device-global addresses for conversion kernels
    void* p_xhi;  cudaGetSymbolAddress(&p_xhi,  g_xhi);
    void* p_xlo;  cudaGetSymbolAddress(&p_xlo,  g_xlo);
    void* p_w1hi; cudaGetSymbolAddress(&p_w1hi, g_w1hi);
    void* p_w1lo; cudaGetSymbolAddress(&p_w1lo, g_w1lo);
    void* p_w2hi; cudaGetSymbolAddress(&p_w2hi, g_w2hi);
    void* p_w2lo; cudaGetSymbolAddress(&p_w2lo, g_w2lo);

    k_init<<<(OUT_ELEMS + 255) / 256, 256>>>(out);
    k_conv<<<512, 256>>>((const float4*)x, (uint2*)p_xhi, (uint2*)p_xlo,
                         T_TOK * DM / 4);
    k_conv<<<2048, 256>>>((const float4*)W1, (uint2*)p_w1hi, (uint2*)p_w1lo,
                          NE * DM * DFF / 4);
    k_conv<<<2048, 256>>>((const float4*)W2, (uint2*)p_w2hi, (uint2*)p_w2lo,
                          NE * DFF * DM / 4);
    k_fold<<<3 * PP, 128>>>(Wp, bp, W_ih, b_ih);
    k_gates_x<<<dim3(3, T_TOK / 128), 256>>>(x);
    k_gates_h<<<dim3(3, T_TOK / 128), 256>>>(h_prev, W_hh, b_hh);
    k_gru_route<<<T_TOK, 128>>>(h_prev, Wr, br, h_out);
    k_offsets<<<1, 1>>>();
    k_expert_up_mma<<<dim3(DFF / 128, T_TOK / 128, NE), 256, DYN_SMEM>>>(b1);
    k_expert_down_mma<<<dim3(DM / 128, T_TOK / 128, NE), 256, DYN_SMEM>>>(b2, out);
}

// round 5
// speedup vs baseline: 2.2338x; 1.0890x over previous
#include <cuda_runtime.h>
#include <cuda_bf16.h>
#include <cstdint>
#include <math.h>

#define T_TOK 4096
#define DM 512
#define DFF 2048
#define NE 16
#define PP 128
#define OUT_ELEMS (T_TOK * DM)
#define BK 32

// ---- routing 6-product stage layout (BN=128) ----
#define R_APL 10240          // A plane size (128*80)
#define R_BPL 8704           // B plane size (32*272)
#define R_OFFB 30720         // 3*R_APL
#define R_STAGE 56832        // R_OFFB + 3*R_BPL
#define R_DYN (2 * R_STAGE)

// ---- expert up stage layout (BN=256) ----
#define U_ALO 10240
#define U_OFFB 20480
#define U_BPL 16896          // 32*528
#define U_STAGE 54272
#define U_DYN (2 * U_STAGE)

// ---- expert down stage layout (BN=128) ----
#define D_ALO 10240
#define D_OFFB 20480
#define D_BPL 8704
#define D_STAGE 37888
#define D_DYN (2 * D_STAGE)

// ---------------- device scratch ----------------
__device__ float g_gx[T_TOK * 3 * PP];
__device__ float g_gh[T_TOK * 3 * PP];
__device__ float g_Wc[3 * PP * DM];
__device__ float g_bc[3 * PP];
__device__ __nv_bfloat16 g_xb0[T_TOK * DM];
__device__ __nv_bfloat16 g_xb1[T_TOK * DM];
__device__ __nv_bfloat16 g_xb2[T_TOK * DM];
__device__ __nv_bfloat16 g_hb0[T_TOK * PP];
__device__ __nv_bfloat16 g_hb1[T_TOK * PP];
__device__ __nv_bfloat16 g_hb2[T_TOK * PP];
__device__ __nv_bfloat16 g_wcT0[DM * 3 * PP];
__device__ __nv_bfloat16 g_wcT1[DM * 3 * PP];
__device__ __nv_bfloat16 g_wcT2[DM * 3 * PP];
__device__ __nv_bfloat16 g_whT0[PP * 3 * PP];
__device__ __nv_bfloat16 g_whT1[PP * 3 * PP];
__device__ __nv_bfloat16 g_whT2[PP * 3 * PP];
__device__ __nv_bfloat16 g_w1hi[(size_t)NE * DM * DFF];
__device__ __nv_bfloat16 g_w1lo[(size_t)NE * DM * DFF];
__device__ __nv_bfloat16 g_w2hi[(size_t)NE * DFF * DM];
__device__ __nv_bfloat16 g_w2lo[(size_t)NE * DFF * DM];
__device__ __nv_bfloat16 g_hid_hi[(size_t)T_TOK * 2 * DFF];
__device__ __nv_bfloat16 g_hid_lo[(size_t)T_TOK * 2 * DFF];
__device__ int   g_list[NE * T_TOK];
__device__ float g_wt[NE * T_TOK];
__device__ int   g_count[NE];
__device__ int   g_offset[NE];

// ---------------- helpers ----------------
__device__ __forceinline__ uint32_t smem_u32(const void* p) {
    uint32_t a;
    asm("{ .reg .u64 t; cvta.to.shared.u64 t, %1; cvt.u32.u64 %0, t; }"
        : "=r"(a) : "l"(p));
    return a;
}
__device__ __forceinline__ void ldmx4(uint32_t addr, uint32_t* r) {
    asm volatile("ldmatrix.sync.aligned.m8n8.x4.shared.b16 {%0,%1,%2,%3}, [%4];"
                 : "=r"(r[0]), "=r"(r[1]), "=r"(r[2]), "=r"(r[3]) : "r"(addr));
}
__device__ __forceinline__ void ldmx4t(uint32_t addr, uint32_t* r) {
    asm volatile("ldmatrix.sync.aligned.m8n8.x4.trans.shared.b16 {%0,%1,%2,%3}, [%4];"
                 : "=r"(r[0]), "=r"(r[1]), "=r"(r[2]), "=r"(r[3]) : "r"(addr));
}
__device__ __forceinline__ void mma16816(float* d, const uint32_t* a,
                                         const uint32_t* b) {
    asm volatile(
        "mma.sync.aligned.m16n8k16.row.col.f32.bf16.bf16.f32 "
        "{%0,%1,%2,%3}, {%4,%5,%6,%7}, {%8,%9}, {%0,%1,%2,%3};"
        : "+f"(d[0]), "+f"(d[1]), "+f"(d[2]), "+f"(d[3])
        : "r"(a[0]), "r"(a[1]), "r"(a[2]), "r"(a[3]), "r"(b[0]), "r"(b[1]));
}
__device__ __forceinline__ void cp16(uint32_t dst, const void* src, bool ok) {
    int sz = ok ? 16 : 0;
    asm volatile("cp.async.cg.shared.global [%0], [%1], 16, %2;"
                 :: "r"(dst), "l"(src), "r"(sz) : "memory");
}
#define CP_COMMIT() asm volatile("cp.async.commit_group;" ::: "memory")
template <int N>
__device__ __forceinline__ void cp_wait() {
    asm volatile("cp.async.wait_group %0;" :: "n"(N) : "memory");
}
__device__ __forceinline__ uint32_t pack_hi(float a, float b, float& ra, float& rb) {
    __nv_bfloat162 h = __floats2bfloat162_rn(a, b);
    ra = a - __bfloat162float(h.x);
    rb = b - __bfloat162float(h.y);
    return *reinterpret_cast<uint32_t*>(&h);
}
__device__ __forceinline__ uint32_t pack_bf2(float a, float b) {
    __nv_bfloat162 h = __floats2bfloat162_rn(a, b);
    return *reinterpret_cast<uint32_t*>(&h);
}

// ---------------- init ----------------
__global__ void k_init(float* __restrict__ out) {
    int i = blockIdx.x * blockDim.x + threadIdx.x;
    if (i < OUT_ELEMS) out[i] = 0.0f;
    if (blockIdx.x == 0 && threadIdx.x < NE) g_count[threadIdx.x] = 0;
}

// ---------------- fp32 -> 2-plane split ----------------
__global__ void k_conv(const float4* __restrict__ src, uint2* __restrict__ hi,
                       uint2* __restrict__ lo, int n4) {
    for (int i = blockIdx.x * blockDim.x + threadIdx.x; i < n4;
         i += gridDim.x * blockDim.x) {
        float4 v = src[i];
        float r0, r1, r2, r3;
        uint2 H, L;
        H.x = pack_hi(v.x, v.y, r0, r1);
        H.y = pack_hi(v.z, v.w, r2, r3);
        L.x = pack_bf2(r0, r1);
        L.y = pack_bf2(r2, r3);
        hi[i] = H;
        lo[i] = L;
    }
}

// ---------------- fp32 -> 3-plane split ----------------
__global__ void k_conv3(const float4* __restrict__ src, uint2* __restrict__ p0,
                        uint2* __restrict__ p1, uint2* __restrict__ p2, int n4) {
    for (int i = blockIdx.x * blockDim.x + threadIdx.x; i < n4;
         i += gridDim.x * blockDim.x) {
        float4 v = src[i];
        float va[4] = {v.x, v.y, v.z, v.w};
        __nv_bfloat16 b0[4], b1[4], b2[4];
#pragma unroll
        for (int j = 0; j < 4; j++) {
            b0[j] = __float2bfloat16_rn(va[j]);
            float r1 = va[j] - __bfloat162float(b0[j]);
            b1[j] = __float2bfloat16_rn(r1);
            float r2 = r1 - __bfloat162float(b1[j]);
            b2[j] = __float2bfloat16_rn(r2);
        }
        uint2 o0, o1, o2;
        __nv_bfloat162 t;
        t = __nv_bfloat162(b0[0], b0[1]); o0.x = *(uint32_t*)&t;
        t = __nv_bfloat162(b0[2], b0[3]); o0.y = *(uint32_t*)&t;
        t = __nv_bfloat162(b1[0], b1[1]); o1.x = *(uint32_t*)&t;
        t = __nv_bfloat162(b1[2], b1[3]); o1.y = *(uint32_t*)&t;
        t = __nv_bfloat162(b2[0], b2[1]); o2.x = *(uint32_t*)&t;
        t = __nv_bfloat162(b2[2], b2[3]); o2.y = *(uint32_t*)&t;
        p0[i] = o0; p1[i] = o1; p2[i] = o2;
    }
}

// ---------------- transpose + 3-plane split: W[N,K] -> planes [K,N] ----------------
__global__ void k_convT3(const float* __restrict__ W, __nv_bfloat16* __restrict__ p0,
                         __nv_bfloat16* __restrict__ p1, __nv_bfloat16* __restrict__ p2,
                         int N, int K) {
    int total = N * K;
    for (int i = blockIdx.x * blockDim.x + threadIdx.x; i < total;
         i += gridDim.x * blockDim.x) {
        int k = i / N, n = i % N;
        float x = W[(size_t)n * K + k];
        __nv_bfloat16 b0 = __float2bfloat16_rn(x);
        float r1 = x - __bfloat162float(b0);
        __nv_bfloat16 b1 = __float2bfloat16_rn(r1);
        float r2 = r1 - __bfloat162float(b1);
        __nv_bfloat16 b2 = __float2bfloat16_rn(r2);
        p0[i] = b0; p1[i] = b1; p2[i] = b2;
    }
}

// ---------------- fold projector into gate weights ----------------
__global__ void __launch_bounds__(128) k_fold(
    const float* __restrict__ Wp, const float* __restrict__ bp,
    const float* __restrict__ W_ih, const float* __restrict__ b_ih)
{
    const int nrow = blockIdx.x;
    __shared__ float wrow[PP];
    const int tid = threadIdx.x;
    wrow[tid] = W_ih[nrow * PP + tid];
    __syncthreads();
    for (int d = tid; d < DM; d += 128) {
        float s = 0.f;
#pragma unroll 8
        for (int p = 0; p < PP; p++) s = fmaf(wrow[p], Wp[p * DM + d], s);
        g_Wc[nrow * DM + d] = s;
    }
    if (tid == 0) {
        float s = b_ih[nrow];
        for (int p = 0; p < PP; p++) s = fmaf(wrow[p], bp[p], s);
        g_bc[nrow] = s;
    }
}

// ============== compute bodies ==============
// 3-product (expert path), templated on layout
template <int OFFALO, int OFFB, int BPL, int BSTRV>
__device__ __forceinline__ void chunk3(uint32_t sb, int mw, int nw, int lane,
                                       float acc[2][8][4]) {
#pragma unroll
    for (int ks = 0; ks < 2; ks++) {
        uint32_t ah[2][4], al[2][4];
        uint32_t arow = (uint32_t)((mw + (lane & 15)) * 80 + ks * 32 + ((lane >> 4) << 4));
        ldmx4(sb + arow, ah[0]);
        ldmx4(sb + arow + 16 * 80, ah[1]);
        ldmx4(sb + OFFALO + arow, al[0]);
        ldmx4(sb + OFFALO + arow + 16 * 80, al[1]);
        uint32_t brow = (uint32_t)((ks * 16 + (lane & 15)) * BSTRV + (nw + ((lane >> 4) << 3)) * 2);
#pragma unroll
        for (int nb = 0; nb < 4; nb++) {
            uint32_t bh[4], bl[4];
            ldmx4t(sb + OFFB + brow + nb * 32, bh);
            ldmx4t(sb + OFFB + BPL + brow + nb * 32, bl);
#pragma unroll
            for (int mt = 0; mt < 2; mt++) {
                mma16816(acc[mt][2 * nb],     ah[mt], bh);
                mma16816(acc[mt][2 * nb],     ah[mt], bl);
                mma16816(acc[mt][2 * nb],     al[mt], bh);
                mma16816(acc[mt][2 * nb + 1], ah[mt], bh + 2);
                mma16816(acc[mt][2 * nb + 1], ah[mt], bl + 2);
                mma16816(acc[mt][2 * nb + 1], al[mt], bh + 2);
            }
        }
    }
}

// 6-product (routing path, ~fp32 accuracy)
__device__ __forceinline__ void chunk6(uint32_t sb, int mw, int nw, int lane,
                                       float acc[2][8][4]) {
#pragma unroll
    for (int ks = 0; ks < 2; ks++) {
        uint32_t a[3][2][4];
        uint32_t arow = (uint32_t)((mw + (lane & 15)) * 80 + ks * 32 + ((lane >> 4) << 4));
#pragma unroll
        for (int p = 0; p < 3; p++) {
            ldmx4(sb + p * R_APL + arow, a[p][0]);
            ldmx4(sb + p * R_APL + arow + 16 * 80, a[p][1]);
        }
        uint32_t brow = (uint32_t)((ks * 16 + (lane & 15)) * 272 + (nw + ((lane >> 4) << 3)) * 2);
#pragma unroll
        for (int nb = 0; nb < 4; nb++) {
            uint32_t b[3][4];
#pragma unroll
            for (int p = 0; p < 3; p++)
                ldmx4t(sb + R_OFFB + p * R_BPL + brow + nb * 32, b[p]);
#pragma unroll
            for (int mt = 0; mt < 2; mt++) {
#pragma unroll
                for (int h = 0; h < 2; h++) {
                    float* d = acc[mt][2 * nb + h];
                    mma16816(d, a[0][mt], &b[0][2 * h]);
                    mma16816(d, a[0][mt], &b[1][2 * h]);
                    mma16816(d, a[1][mt], &b[0][2 * h]);
                    mma16816(d, a[0][mt], &b[2][2 * h]);
                    mma16816(d, a[2][mt], &b[0][2 * h]);
                    mma16816(d, a[1][mt], &b[1][2 * h]);
                }
            }
        }
    }
}

// ============== routing GEMM: C[M,N] = A@B + bias (B pre-transposed [K,N]) ==============
__global__ void __launch_bounds__(256) k_rgemm6(
    const __nv_bfloat16* __restrict__ A0, const __nv_bfloat16* __restrict__ A1,
    const __nv_bfloat16* __restrict__ A2,
    const __nv_bfloat16* __restrict__ B0, const __nv_bfloat16* __restrict__ B1,
    const __nv_bfloat16* __restrict__ B2,
    const float* __restrict__ bias, float* __restrict__ C, int K, int N)
{
    const int m0 = blockIdx.y * 128;
    const int n0 = blockIdx.x * 128;
    extern __shared__ __align__(16) char dsm[];
    const uint32_t smb = smem_u32(dsm);

    const int tid = threadIdx.x;
    const int wid = tid >> 5, lane = tid & 31;
    const int mw = (wid & 3) * 32, nw = (wid >> 2) * 64;

    const __nv_bfloat16* srcA[2];
    uint32_t dstA[2];
#pragma unroll
    for (int i = 0; i < 2; i++) {
        int it = tid + i * 256;
        int r = it >> 2, q = it & 3;
        srcA[i] = A0 + (size_t)(m0 + r) * K + q * 8;
        dstA[i] = (uint32_t)(r * 80 + q * 16);
    }
    const __nv_bfloat16* srcB[2];
    uint32_t dstB[2];
#pragma unroll
    for (int i = 0; i < 2; i++) {
        int it = tid + i * 256;
        int k = it >> 4, c = it & 15;
        srcB[i] = B0 + (size_t)k * N + n0 + c * 8;
        dstB[i] = (uint32_t)(k * 272 + c * 16);
    }
    const ptrdiff_t a1 = A1 - A0, a2 = A2 - A0;
    const ptrdiff_t b1 = B1 - B0, b2 = B2 - B0;

    float acc[2][8][4];
#pragma unroll
    for (int x = 0; x < 2; x++)
#pragma unroll
        for (int y = 0; y < 8; y++)
#pragma unroll
            for (int z = 0; z < 4; z++) acc[x][y][z] = 0.f;

#pragma unroll
    for (int i = 0; i < 2; i++) {
        cp16(smb + dstA[i], srcA[i], true);
        cp16(smb + R_APL + dstA[i], srcA[i] + a1, true);
        cp16(smb + 2 * R_APL + dstA[i], srcA[i] + a2, true);
        cp16(smb + R_OFFB + dstB[i], srcB[i], true);
        cp16(smb + R_OFFB + R_BPL + dstB[i], srcB[i] + b1, true);
        cp16(smb + R_OFFB + 2 * R_BPL + dstB[i], srcB[i] + b2, true);
    }
    CP_COMMIT();

    const int NK = K / BK;
    for (int c = 0; c < NK; c++) {
        const int s = c & 1;
        if (c + 1 < NK) {
            const uint32_t nb = smb + (s ^ 1) * R_STAGE;
            const int kc = (c + 1) * BK;
#pragma unroll
            for (int i = 0; i < 2; i++) {
                cp16(nb + dstA[i], srcA[i] + kc, true);
                cp16(nb + R_APL + dstA[i], srcA[i] + a1 + kc, true);
                cp16(nb + 2 * R_APL + dstA[i], srcA[i] + a2 + kc, true);
                cp16(nb + R_OFFB + dstB[i], srcB[i] + (size_t)kc * N, true);
                cp16(nb + R_OFFB + R_BPL + dstB[i], srcB[i] + b1 + (size_t)kc * N, true);
                cp16(nb + R_OFFB + 2 * R_BPL + dstB[i], srcB[i] + b2 + (size_t)kc * N, true);
            }
            CP_COMMIT();
            cp_wait<1>();
        } else {
            cp_wait<0>();
        }
        __syncthreads();
        chunk6(smb + s * R_STAGE, mw, nw, lane, acc);
        __syncthreads();
    }

#pragma unroll
    for (int mt = 0; mt < 2; mt++) {
        int lr0 = mw + mt * 16 + (lane >> 2);
        int lr1 = lr0 + 8;
#pragma unroll
        for (int nt = 0; nt < 8; nt++) {
            int c = nw + nt * 8 + (lane & 3) * 2;
            float z0 = __ldg(&bias[n0 + c]), z1 = __ldg(&bias[n0 + c + 1]);
            float2 v0 = make_float2(acc[mt][nt][0] + z0, acc[mt][nt][1] + z1);
            float2 v1 = make_float2(acc[mt][nt][2] + z0, acc[mt][nt][3] + z1);
            *(float2*)&C[(size_t)(m0 + lr0) * N + n0 + c] = v0;
            *(float2*)&C[(size_t)(m0 + lr1) * N + n0 + c] = v1;
        }
    }
}

// ---------------- GRU + router (top-2, fp32 logits) ----------------
__global__ void __launch_bounds__(128) k_gru_route(
    const float* __restrict__ h_prev,
    const float* __restrict__ Wr, const float* __restrict__ br,
    float* __restrict__ h_out)
{
    const int t = blockIdx.x;
    const int j = threadIdx.x;
    __shared__ float hs[PP];
    __shared__ float logit[NE];

    const float* gx = g_gx + (size_t)t * (3 * PP);
    const float* gh = g_gh + (size_t)t * (3 * PP);
    float xr = gx[j], xz = gx[PP + j], xn = gx[2 * PP + j];
    float hr = gh[j], hz = gh[PP + j], hn = gh[2 * PP + j];
    float r = 1.f / (1.f + expf(-(xr + hr)));
    float z = 1.f / (1.f + expf(-(xz + hz)));
    float n = tanhf(xn + r * hn);
    float hp = h_prev[(size_t)t * PP + j];
    float h = (1.f - z) * n + z * hp;
    hs[j] = h;
    h_out[(size_t)t * PP + j] = h;
    __syncthreads();

    const int w = j >> 5, lane = j & 31;
    for (int e = w; e < NE; e += 4) {
        float p = 0.f;
#pragma unroll
        for (int c = 0; c < 4; c++)
            p += Wr[e * PP + lane + 32 * c] * hs[lane + 32 * c];
#pragma unroll
        for (int off = 16; off; off >>= 1) p += __shfl_down_sync(0xffffffffu, p, off);
        if (lane == 0) logit[e] = p + br[e];
    }
    __syncthreads();

    if (j == 0) {
        int e0 = 0, e1 = -1;
        float l0 = logit[0], l1 = -1e30f;
        for (int e = 1; e < NE; e++) {
            float v = logit[e];
            if (v > l0) { l1 = l0; e1 = e0; l0 = v; e0 = e; }
            else if (v > l1) { l1 = v; e1 = e; }
        }
        float p1 = expf(l1 - l0);
        float inv = 1.f / (1.0f + p1);
        float p0 = inv; p1 *= inv;
        int pos0 = atomicAdd(&g_count[e0], 1);
        g_list[e0 * T_TOK + pos0] = t; g_wt[e0 * T_TOK + pos0] = p0;
        int pos1 = atomicAdd(&g_count[e1], 1);
        g_list[e1 * T_TOK + pos1] = t; g_wt[e1 * T_TOK + pos1] = p1;
    }
}

__global__ void k_offsets() {
    if (threadIdx.x == 0) {
        int s = 0;
        for (int e = 0; e < NE; e++) { g_offset[e] = s; s += g_count[e]; }
    }
}

// ============== expert up-proj: BM=128, BN=256, 512 threads ==============
__global__ void __launch_bounds__(512) k_expert_up_mma(const float* __restrict__ b1)
{
    const int e = blockIdx.z;
    const int cnt = g_count[e];
    const int m0 = blockIdx.x * 128;           // m fastest-varying
    if (m0 >= cnt) return;
    const int n0 = blockIdx.y * 256;
    const float* b1e = b1 + (size_t)e * DFF;
    const size_t rowbase = (size_t)g_offset[e] + m0;

    extern __shared__ __align__(16) char dsm[];
    const uint32_t smb = smem_u32(dsm);
    __shared__ int rowidx[128];

    const int tid = threadIdx.x;
    const int wid = tid >> 5, lane = tid & 31;
    const int mw = (wid & 3) * 32, nw = (wid >> 2) * 64;

    if (tid < 128)
        rowidx[tid] = (m0 + tid < cnt) ? g_list[e * T_TOK + m0 + tid] : -1;
    __syncthreads();

    // A staging: one 16B op/thread/plane
    const int ra = tid >> 2, qa = tid & 3;
    const int grA = rowidx[ra];
    const bool okA = (grA >= 0);
    const __nv_bfloat16* srcA = g_xb0 + (size_t)(okA ? grA : 0) * DM + qa * 8;
    const uint32_t dstA = (uint32_t)(ra * 80 + qa * 16);
    const ptrdiff_t dLoA = g_xb1 - g_xb0;

    // B staging: two 16B ops/thread/plane
    const __nv_bfloat16* srcB[2];
    uint32_t dstB[2];
#pragma unroll
    for (int i = 0; i < 2; i++) {
        int it = tid + i * 512;
        int k = it >> 5, c = it & 31;
        srcB[i] = g_w1hi + (size_t)e * DM * DFF + (size_t)k * DFF + n0 + c * 8;
        dstB[i] = (uint32_t)(k * 528 + c * 16);
    }
    const ptrdiff_t dLoB = g_w1lo - g_w1hi;

    float acc[2][8][4];
#pragma unroll
    for (int x = 0; x < 2; x++)
#pragma unroll
        for (int y = 0; y < 8; y++)
#pragma unroll
            for (int z = 0; z < 4; z++) acc[x][y][z] = 0.f;

    cp16(smb + dstA, srcA, okA);
    cp16(smb + U_ALO + dstA, srcA + dLoA, okA);
#pragma unroll
    for (int i = 0; i < 2; i++) {
        cp16(smb + U_OFFB + dstB[i], srcB[i], true);
        cp16(smb + U_OFFB + U_BPL + dstB[i], srcB[i] + dLoB, true);
    }
    CP_COMMIT();

    const int NK = DM / BK;  // 16
    for (int c = 0; c < NK; c++) {
        const int s = c & 1;
        if (c + 1 < NK) {
            const uint32_t nb = smb + (s ^ 1) * U_STAGE;
            const int kc = (c + 1) * BK;
            cp16(nb + dstA, srcA + kc, okA);
            cp16(nb + U_ALO + dstA, srcA + dLoA + kc, okA);
#pragma unroll
            for (int i = 0; i < 2; i++) {
                cp16(nb + U_OFFB + dstB[i], srcB[i] + (size_t)kc * DFF, true);
                cp16(nb + U_OFFB + U_BPL + dstB[i], srcB[i] + dLoB + (size_t)kc * DFF, true);
            }
            CP_COMMIT();
            cp_wait<1>();
        } else {
            cp_wait<0>();
        }
        __syncthreads();
        chunk3<U_ALO, U_OFFB, U_BPL, 528>(smb + s * U_STAGE, mw, nw, lane, acc);
        __syncthreads();
    }

    // epilogue: bias + relu -> hi/lo split -> g_hid
#pragma unroll
    for (int mt = 0; mt < 2; mt++) {
        int lr0 = mw + mt * 16 + (lane >> 2);
        int lr1 = lr0 + 8;
        bool ok0 = (m0 + lr0 < cnt), ok1 = (m0 + lr1 < cnt);
        size_t row0 = rowbase + lr0, row1 = rowbase + lr1;
#pragma unroll
        for (int nt = 0; nt < 8; nt++) {
            int c = nw + nt * 8 + (lane & 3) * 2;
            float z0 = __ldg(&b1e[n0 + c]), z1 = __ldg(&b1e[n0 + c + 1]);
            if (ok0) {
                float v0 = fmaxf(acc[mt][nt][0] + z0, 0.f);
                float v1 = fmaxf(acc[mt][nt][1] + z1, 0.f);
                float r0, r1;
                uint32_t H = pack_hi(v0, v1, r0, r1);
                uint32_t L = pack_bf2(r0, r1);
                *(uint32_t*)(g_hid_hi + row0 * DFF + n0 + c) = H;
                *(uint32_t*)(g_hid_lo + row0 * DFF + n0 + c) = L;
            }
            if (ok1) {
                float v0 = fmaxf(acc[mt][nt][2] + z0, 0.f);
                float v1 = fmaxf(acc[mt][nt][3] + z1, 0.f);
                float r0, r1;
                uint32_t H = pack_hi(v0, v1, r0, r1);
                uint32_t L = pack_bf2(r0, r1);
                *(uint32_t*)(g_hid_hi + row1 * DFF + n0 + c) = H;
                *(uint32_t*)(g_hid_lo + row1 * DFF + n0 + c) = L;
            }
        }
    }
}

// ============== expert down-proj: BM=128, BN=128, 256 threads ==============
__global__ void __launch_bounds__(256) k_expert_down_mma(
    const float* __restrict__ b2, float* __restrict__ out)
{
    const int e = blockIdx.z;
    const int cnt = g_count[e];
    const int m0 = blockIdx.x * 128;           // m fastest-varying
    if (m0 >= cnt) return;
    const int n0 = blockIdx.y * 128;
    const float* b2e = b2 + (size_t)e * DM;
    const size_t rowbase = (size_t)g_offset[e] + m0;

    extern __shared__ __align__(16) char dsm[];
    const uint32_t smb = smem_u32(dsm);
    __shared__ int s_tok[128];
    __shared__ float s_w[128];

    const int tid = threadIdx.x;
    const int wid = tid >> 5, lane = tid & 31;
    const int mw = (wid & 3) * 32, nw = (wid >> 2) * 64;

    if (tid < 128) {
        bool ok = (m0 + tid < cnt);
        s_tok[tid] = ok ? g_list[e * T_TOK + m0 + tid] : 0;
        s_w[tid] = ok ? g_wt[e * T_TOK + m0 + tid] : 0.f;
    }
    __syncthreads();

    const __nv_bfloat16* srcA[2];
    bool okA[2];
    uint32_t dstA[2];
#pragma unroll
    for (int i = 0; i < 2; i++) {
        int it = tid + i * 256;
        int r = it >> 2, q = it & 3;
        okA[i] = (m0 + r < cnt);
        srcA[i] = g_hid_hi + (okA[i] ? (rowbase + r) : 0) * DFF + q * 8;
        dstA[i] = (uint32_t)(r * 80 + q * 16);
    }
    const __nv_bfloat16* srcB[2];
    uint32_t dstB[2];
#pragma unroll
    for (int i = 0; i < 2; i++) {
        int it = tid + i * 256;
        int k = it >> 4, c = it & 15;
        srcB[i] = g_w2hi + (size_t)e * DFF * DM + (size_t)k * DM + n0 + c * 8;
        dstB[i] = (uint32_t)(k * 272 + c * 16);
    }
    const ptrdiff_t dLoA = g_hid_lo - g_hid_hi;
    const ptrdiff_t dLoB = g_w2lo - g_w2hi;

    float acc[2][8][4];
#pragma unroll
    for (int x = 0; x < 2; x++)
#pragma unroll
        for (int y = 0; y < 8; y++)
#pragma unroll
            for (int z = 0; z < 4; z++) acc[x][y][z] = 0.f;

#pragma unroll
    for (int i = 0; i < 2; i++) {
        cp16(smb + dstA[i], srcA[i], okA[i]);
        cp16(smb + D_ALO + dstA[i], srcA[i] + dLoA, okA[i]);
        cp16(smb + D_OFFB + dstB[i], srcB[i], true);
        cp16(smb + D_OFFB + D_BPL + dstB[i], srcB[i] + dLoB, true);
    }
    CP_COMMIT();

    const int NK = DFF / BK;  // 64
    for (int c = 0; c < NK; c++) {
        const int s = c & 1;
        if (c + 1 < NK) {
            const uint32_t nb = smb + (s ^ 1) * D_STAGE;
            const int kc = (c + 1) * BK;
#pragma unroll
            for (int i = 0; i < 2; i++) {
                cp16(nb + dstA[i], srcA[i] + kc, okA[i]);
                cp16(nb + D_ALO + dstA[i], srcA[i] + dLoA + kc, okA[i]);
                cp16(nb + D_OFFB + dstB[i], srcB[i] + (size_t)kc * DM, true);
                cp16(nb + D_OFFB + D_BPL + dstB[i], srcB[i] + dLoB + (size_t)kc * DM, true);
            }
            CP_COMMIT();
            cp_wait<1>();
        } else {
            cp_wait<0>();
        }
        __syncthreads();
        chunk3<D_ALO, D_OFFB, D_BPL, 272>(smb + s * D_STAGE, mw, nw, lane, acc);
        __syncthreads();
    }

#pragma unroll
    for (int mt = 0; mt < 2; mt++) {
        int lr0 = mw + mt * 16 + (lane >> 2);
        int lr1 = lr0 + 8;
        bool ok0 = (m0 + lr0 < cnt), ok1 = (m0 + lr1 < cnt);
        int tok0 = s_tok[lr0], tok1 = s_tok[lr1];
        float w0 = s_w[lr0], w1 = s_w[lr1];
#pragma unroll
        for (int nt = 0; nt < 8; nt++) {
            int c = nw + nt * 8 + (lane & 3) * 2;
            float z0 = __ldg(&b2e[n0 + c]), z1 = __ldg(&b2e[n0 + c + 1]);
            if (ok0) {
                float* op = out + (size_t)tok0 * DM + n0 + c;
                atomicAdd(op,     w0 * (acc[mt][nt][0] + z0));
                atomicAdd(op + 1, w0 * (acc[mt][nt][1] + z1));
            }
            if (ok1) {
                float* op = out + (size_t)tok1 * DM + n0 + c;
                atomicAdd(op,     w1 * (acc[mt][nt][2] + z0));
                atomicAdd(op + 1, w1 * (acc[mt][nt][3] + z1));
            }
        }
    }
}

// ---------------- host launcher ----------------
extern "C" void kernel_launch(void* const* d_in, const int* in_sizes, int n_in,
                              void* d_out, int out_size) {
    const float* x      = (const float*)d_in[0];
    const float* h_prev = (const float*)d_in[1];
    const float* Wp     = (const float*)d_in[2];
    const float* bp     = (const float*)d_in[3];
    const float* W_ih   = (const float*)d_in[4];
    const float* W_hh   = (const float*)d_in[5];
    const float* b_ih   = (const float*)d_in[6];
    const float* b_hh   = (const float*)d_in[7];
    const float* Wr     = (const float*)d_in[8];
    const float* br     = (const float*)d_in[9];
    const float* W1     = (const float*)d_in[10];
    const float* b1     = (const float*)d_in[11];
    const float* W2     = (const float*)d_in[12];
    const float* b2     = (const float*)d_in[13];

    float* out   = (float*)d_out;
    float* h_out = out + OUT_ELEMS;

    static bool attr_set = false;
    if (!attr_set) {
        cudaFuncSetAttribute(k_rgemm6,
                             cudaFuncAttributeMaxDynamicSharedMemorySize, R_DYN);
        cudaFuncSetAttribute(k_expert_up_mma,
                             cudaFuncAttributeMaxDynamicSharedMemorySize, U_DYN);
        cudaFuncSetAttribute(k_expert_down_mma,
                             cudaFuncAttributeMaxDynamicSharedMemorySize, D_DYN);
        attr_set = true;
    }

    void *p_xb0, *p_xb1, *p_xb2, *p_hb0, *p_hb1, *p_hb2;
    void *p_wcT0, *p_wcT1, *p_wcT2, *p_whT0, *p_whT1, *p_whT2;
    void *p_w1hi, *p_w1lo, *p_w2hi, *p_w2lo, *p_Wc, *p_bc, *p_gx, *p_gh;
    cudaGetSymbolAddress(&p_xb0, g_xb0);  cudaGetSymbolAddress(&p_xb1, g_xb1);
    cudaGetSymbolAddress(&p_xb2, g_xb2);
    cudaGetSymbolAddress(&p_hb0, g_hb0);  cudaGetSymbolAddress(&p_hb1, g_hb1);
    cudaGetSymbolAddress(&p_hb2, g_hb2);
    cudaGetSymbolAddress(&p_wcT0, g_wcT0); cudaGetSymbolAddress(&p_wcT1, g_wcT1);
    cudaGetSymbolAddress(&p_wcT2, g_wcT2);
    cudaGetSymbolAddress(&p_whT0, g_whT0); cudaGetSymbolAddress(&p_whT1, g_whT1);
    cudaGetSymbolAddress(&p_whT2, g_whT2);
    cudaGetSymbolAddress(&p_w1hi, g_w1hi); cudaGetSymbolAddress(&p_w1lo, g_w1lo);
    cudaGetSymbolAddress(&p_w2hi, g_w2hi); cudaGetSymbolAddress(&p_w2lo, g_w2lo);
    cudaGetSymbolAddress(&p_Wc, g_Wc);     cudaGetSymbolAddress(&p_bc, g_bc);
    cudaGetSymbolAddress(&p_gx, g_gx);     cudaGetSymbolAddress(&p_gh, g_gh);

    k_init<<<(OUT_ELEMS + 255) / 256, 256>>>(out);
    k_conv3<<<512, 256>>>((const float4*)x, (uint2*)p_xb0, (uint2*)p_xb1,
                          (uint2*)p_xb2, T_TOK * DM / 4);
    k_conv3<<<256, 256>>>((const float4*)h_prev, (uint2*)p_hb0, (uint2*)p_hb1,
                          (uint2*)p_hb2, T_TOK * PP / 4);
    k_conv<<<2048, 256>>>((const float4*)W1, (uint2*)p_w1hi, (uint2*)p_w1lo,
                          NE * DM * DFF / 4);
    k_conv<<<2048, 256>>>((const float4*)W2, (uint2*)p_w2hi, (uint2*)p_w2lo,
                          NE * DFF * DM / 4);
    k_fold<<<3 * PP, 128>>>(Wp, bp, W_ih, b_ih);
    k_convT3<<<768, 256>>>((const float*)p_Wc, (__nv_bfloat16*)p_wcT0,
                           (__nv_bfloat16*)p_wcT1, (__nv_bfloat16*)p_wcT2,
                           3 * PP, DM);
    k_convT3<<<192, 256>>>(W_hh, (__nv_bfloat16*)p_whT0,
                           (__nv_bfloat16*)p_whT1, (__nv_bfloat16*)p_whT2,
                           3 * PP, PP);
    k_rgemm6<<<dim3(3, 32), 256, R_DYN>>>(
        (const __nv_bfloat16*)p_xb0, (const __nv_bfloat16*)p_xb1,
        (const __nv_bfloat16*)p_xb2,
        (const __nv_bfloat16*)p_wcT0, (const __nv_bfloat16*)p_wcT1,
        (const __nv_bfloat16*)p_wcT2,
        (const float*)p_bc, (float*)p_gx, DM, 3 * PP);
    k_rgemm6<<<dim3(3, 32), 256, R_DYN>>>(
        (const __nv_bfloat16*)p_hb0, (const __nv_bfloat16*)p_hb1,
        (const __nv_bfloat16*)p_hb2,
        (const __nv_bfloat16*)p_whT0, (const __nv_bfloat16*)p_whT1,
        (const __nv_bfloat16*)p_whT2,
        b_hh, (float*)p_gh, PP, 3 * PP);
    k_gru_route<<<T_TOK, 128>>>(h_prev, Wr, br, h_out);
    k_offsets<<<1, 1>>>();
    k_expert_up_mma<<<dim3(T_TOK / 128, DFF / 256, NE), 512, U_DYN>>>(b1);
    k_expert_down_mma<<<dim3(T_TOK / 128, DM / 128, NE), 256, D_DYN>>>(b2, out);
}

// round 6
// speedup vs baseline: 2.4579x; 1.1003x over previous
#include <cuda_runtime.h>
#include <cuda_fp16.h>
#include <cstdint>
#include <math.h>

#define T_TOK 4096
#define DM 512
#define DFF 2048
#define NE 16
#define PP 128
#define N3P 384
#define OUT_ELEMS (T_TOK * DM)
#define BK 32

// ---- rgemm stage: A 2 planes (128x80B), B 2 planes (32x272B) ----
#define R_ALO 10240
#define R_OFFB 20480
#define R_BPL 8704
#define R_STAGE 37888
#define R_DYN (2 * R_STAGE)
// ---- up stage: BN=256: A 2 planes, B 1 plane (32x528B) ----
#define U_ALO 10240
#define U_OFFB 20480
#define U_STAGE 37376
#define U_DYN (2 * U_STAGE)
// ---- down stage: BN=128: A 2 planes, B 1 plane (32x272B) ----
#define D_ALO 10240
#define D_OFFB 20480
#define D_STAGE 29184
#define D_DYN (2 * D_STAGE)

// ---------------- device scratch ----------------
__device__ float g_gx[T_TOK * N3P];
__device__ float g_gh[T_TOK * N3P];
__device__ float g_bc[N3P];
__device__ __half g_xh0[T_TOK * DM];
__device__ __half g_xh1[T_TOK * DM];
__device__ __half g_hh0[T_TOK * PP];
__device__ __half g_hh1[T_TOK * PP];
__device__ __half g_wcT0[DM * N3P];
__device__ __half g_wcT1[DM * N3P];
__device__ __half g_whT0[PP * N3P];
__device__ __half g_whT1[PP * N3P];
__device__ __half g_w1h[(size_t)NE * DM * DFF];
__device__ __half g_w2h[(size_t)NE * DFF * DM];
__device__ __half g_hid0[(size_t)T_TOK * 2 * DFF];
__device__ __half g_hid1[(size_t)T_TOK * 2 * DFF];
__device__ int   g_list[NE * T_TOK];
__device__ float g_wt[NE * T_TOK];
__device__ int   g_count[NE];

// ---------------- helpers ----------------
__device__ __forceinline__ uint32_t smem_u32(const void* p) {
    uint32_t a;
    asm("{ .reg .u64 t; cvta.to.shared.u64 t, %1; cvt.u32.u64 %0, t; }"
        : "=r"(a) : "l"(p));
    return a;
}
__device__ __forceinline__ void ldmx4(uint32_t addr, uint32_t* r) {
    asm volatile("ldmatrix.sync.aligned.m8n8.x4.shared.b16 {%0,%1,%2,%3}, [%4];"
                 : "=r"(r[0]), "=r"(r[1]), "=r"(r[2]), "=r"(r[3]) : "r"(addr));
}
__device__ __forceinline__ void ldmx4t(uint32_t addr, uint32_t* r) {
    asm volatile("ldmatrix.sync.aligned.m8n8.x4.trans.shared.b16 {%0,%1,%2,%3}, [%4];"
                 : "=r"(r[0]), "=r"(r[1]), "=r"(r[2]), "=r"(r[3]) : "r"(addr));
}
__device__ __forceinline__ void mmah(float* d, const uint32_t* a, const uint32_t* b) {
    asm volatile(
        "mma.sync.aligned.m16n8k16.row.col.f32.f16.f16.f32 "
        "{%0,%1,%2,%3}, {%4,%5,%6,%7}, {%8,%9}, {%0,%1,%2,%3};"
        : "+f"(d[0]), "+f"(d[1]), "+f"(d[2]), "+f"(d[3])
        : "r"(a[0]), "r"(a[1]), "r"(a[2]), "r"(a[3]), "r"(b[0]), "r"(b[1]));
}
__device__ __forceinline__ void cp16(uint32_t dst, const void* src, bool ok) {
    int sz = ok ? 16 : 0;
    asm volatile("cp.async.cg.shared.global [%0], [%1], 16, %2;"
                 :: "r"(dst), "l"(src), "r"(sz) : "memory");
}
#define CP_COMMIT() asm volatile("cp.async.commit_group;" ::: "memory")
template <int N>
__device__ __forceinline__ void cp_wait() {
    asm volatile("cp.async.wait_group %0;" :: "n"(N) : "memory");
}
__device__ __forceinline__ uint32_t packh2(float a, float b) {
    __half2 h = __floats2half2_rn(a, b);
    return *reinterpret_cast<uint32_t*>(&h);
}
__device__ __forceinline__ uint32_t packh2_hi(float a, float b, float& ra, float& rb) {
    __half2 h = __floats2half2_rn(a, b);
    ra = a - __low2float(h);
    rb = b - __high2float(h);
    return *reinterpret_cast<uint32_t*>(&h);
}

// ---------------- prep: zero/counts, all splits, projector fold ----------------
__global__ void __launch_bounds__(256) k_prep(
    const float* __restrict__ x, const float* __restrict__ h_prev,
    const float* __restrict__ W_ih, const float* __restrict__ b_ih,
    const float* __restrict__ Wp, const float* __restrict__ bp,
    const float* __restrict__ W_hh,
    const float* __restrict__ W1, const float* __restrict__ W2,
    float* __restrict__ out)
{
    const int tid = blockIdx.x * blockDim.x + threadIdx.x;
    const int nth = gridDim.x * blockDim.x;
    if (tid < NE) g_count[tid] = 0;

    float4* o4 = (float4*)out;
    for (int i = tid; i < OUT_ELEMS / 4; i += nth)
        o4[i] = make_float4(0.f, 0.f, 0.f, 0.f);

    // x -> 2 fp16 planes
    {
        const float4* s = (const float4*)x;
        uint2* p0 = (uint2*)g_xh0; uint2* p1 = (uint2*)g_xh1;
        for (int i = tid; i < T_TOK * DM / 4; i += nth) {
            float4 v = s[i]; float r0, r1, r2, r3; uint2 H, L;
            H.x = packh2_hi(v.x, v.y, r0, r1); H.y = packh2_hi(v.z, v.w, r2, r3);
            L.x = packh2(r0, r1); L.y = packh2(r2, r3);
            p0[i] = H; p1[i] = L;
        }
    }
    // h_prev -> 2 fp16 planes
    {
        const float4* s = (const float4*)h_prev;
        uint2* p0 = (uint2*)g_hh0; uint2* p1 = (uint2*)g_hh1;
        for (int i = tid; i < T_TOK * PP / 4; i += nth) {
            float4 v = s[i]; float r0, r1, r2, r3; uint2 H, L;
            H.x = packh2_hi(v.x, v.y, r0, r1); H.y = packh2_hi(v.z, v.w, r2, r3);
            L.x = packh2(r0, r1); L.y = packh2(r2, r3);
            p0[i] = H; p1[i] = L;
        }
    }
    // W1, W2 -> single fp16 plane
    {
        const float4* s = (const float4*)W1;
        uint2* p = (uint2*)g_w1h;
        for (int i = tid; i < NE * DM * DFF / 4; i += nth) {
            float4 v = s[i]; uint2 H;
            H.x = packh2(v.x, v.y); H.y = packh2(v.z, v.w);
            p[i] = H;
        }
    }
    {
        const float4* s = (const float4*)W2;
        uint2* p = (uint2*)g_w2h;
        for (int i = tid; i < NE * DFF * DM / 4; i += nth) {
            float4 v = s[i]; uint2 H;
            H.x = packh2(v.x, v.y); H.y = packh2(v.z, v.w);
            p[i] = H;
        }
    }
    // W_hh transpose -> 2 fp16 planes [PP, N3P]
    for (int i = tid; i < PP * N3P; i += nth) {
        int n = i % N3P, k = i / N3P;
        float v = W_hh[n * PP + k];
        __half h = __float2half_rn(v);
        g_whT0[i] = h;
        g_whT1[i] = __float2half_rn(v - __half2float(h));
    }
    // Wc = W_ih @ Wp, transposed -> 2 fp16 planes [DM, N3P]
    for (int i = tid; i < DM * N3P; i += nth) {
        int n = i % N3P, k = i / N3P;
        float s = 0.f;
        const float* wr = W_ih + n * PP;
#pragma unroll 8
        for (int p = 0; p < PP; p++) s = fmaf(wr[p], Wp[p * DM + k], s);
        __half h = __float2half_rn(s);
        g_wcT0[i] = h;
        g_wcT1[i] = __float2half_rn(s - __half2float(h));
    }
    // bc = W_ih @ bp + b_ih
    for (int i = tid; i < N3P; i += nth) {
        float s = b_ih[i];
        const float* wr = W_ih + i * PP;
        for (int p = 0; p < PP; p++) s = fmaf(wr[p], bp[p], s);
        g_bc[i] = s;
    }
}

// ============== compute bodies ==============
// 3-product fp16 (gates): A 2-plane, B 2-plane
__device__ __forceinline__ void chunk3h(uint32_t sb, int mw, int nw, int lane,
                                        float acc[2][8][4]) {
#pragma unroll
    for (int ks = 0; ks < 2; ks++) {
        uint32_t ah[2][4], al[2][4];
        uint32_t arow = (uint32_t)((mw + (lane & 15)) * 80 + ks * 32 + ((lane >> 4) << 4));
        ldmx4(sb + arow, ah[0]);
        ldmx4(sb + arow + 16 * 80, ah[1]);
        ldmx4(sb + R_ALO + arow, al[0]);
        ldmx4(sb + R_ALO + arow + 16 * 80, al[1]);
        uint32_t brow = (uint32_t)((ks * 16 + (lane & 15)) * 272 + (nw + ((lane >> 4) << 3)) * 2);
#pragma unroll
        for (int nb = 0; nb < 4; nb++) {
            uint32_t bh[4], bl[4];
            ldmx4t(sb + R_OFFB + brow + nb * 32, bh);
            ldmx4t(sb + R_OFFB + R_BPL + brow + nb * 32, bl);
#pragma unroll
            for (int mt = 0; mt < 2; mt++) {
                mmah(acc[mt][2 * nb],     ah[mt], bh);
                mmah(acc[mt][2 * nb],     ah[mt], bl);
                mmah(acc[mt][2 * nb],     al[mt], bh);
                mmah(acc[mt][2 * nb + 1], ah[mt], bh + 2);
                mmah(acc[mt][2 * nb + 1], ah[mt], bl + 2);
                mmah(acc[mt][2 * nb + 1], al[mt], bh + 2);
            }
        }
    }
}

// 2-product fp16 (experts): A 2-plane, B 1-plane
template <int OFFALO, int OFFB, int BSTRV>
__device__ __forceinline__ void chunk2h(uint32_t sb, int mw, int nw, int lane,
                                        float acc[2][8][4]) {
#pragma unroll
    for (int ks = 0; ks < 2; ks++) {
        uint32_t ah[2][4], al[2][4];
        uint32_t arow = (uint32_t)((mw + (lane & 15)) * 80 + ks * 32 + ((lane >> 4) << 4));
        ldmx4(sb + arow, ah[0]);
        ldmx4(sb + arow + 16 * 80, ah[1]);
        ldmx4(sb + OFFALO + arow, al[0]);
        ldmx4(sb + OFFALO + arow + 16 * 80, al[1]);
        uint32_t brow = (uint32_t)((ks * 16 + (lane & 15)) * BSTRV + (nw + ((lane >> 4) << 3)) * 2);
#pragma unroll
        for (int nb = 0; nb < 4; nb++) {
            uint32_t bh[4];
            ldmx4t(sb + OFFB + brow + nb * 32, bh);
#pragma unroll
            for (int mt = 0; mt < 2; mt++) {
                mmah(acc[mt][2 * nb],     ah[mt], bh);
                mmah(acc[mt][2 * nb],     al[mt], bh);
                mmah(acc[mt][2 * nb + 1], ah[mt], bh + 2);
                mmah(acc[mt][2 * nb + 1], al[mt], bh + 2);
            }
        }
    }
}

// ============== fused gate GEMMs (z=0: x-gates K=512, z=1: h-gates K=128) ==============
__global__ void __launch_bounds__(256) k_rgemm(const float* __restrict__ b_hh)
{
    const int z = blockIdx.z;
    const int K = z ? PP : DM;
    const __half* A0 = z ? g_hh0 : g_xh0;
    const __half* A1 = z ? g_hh1 : g_xh1;
    const __half* B0 = z ? g_whT0 : g_wcT0;
    const __half* B1 = z ? g_whT1 : g_wcT1;
    const float* bias = z ? b_hh : g_bc;
    float* C = z ? g_gh : g_gx;

    const int m0 = blockIdx.y * 128;
    const int n0 = blockIdx.x * 128;
    extern __shared__ __align__(16) char dsm[];
    const uint32_t smb = smem_u32(dsm);

    const int tid = threadIdx.x;
    const int wid = tid >> 5, lane = tid & 31;
    const int mw = (wid & 3) * 32, nw = (wid >> 2) * 64;

    const __half* srcA[2];
    uint32_t dstA[2];
#pragma unroll
    for (int i = 0; i < 2; i++) {
        int it = tid + i * 256;
        int r = it >> 2, q = it & 3;
        srcA[i] = A0 + (size_t)(m0 + r) * K + q * 8;
        dstA[i] = (uint32_t)(r * 80 + q * 16);
    }
    const __half* srcB[2];
    uint32_t dstB[2];
#pragma unroll
    for (int i = 0; i < 2; i++) {
        int it = tid + i * 256;
        int k = it >> 4, c = it & 15;
        srcB[i] = B0 + (size_t)k * N3P + n0 + c * 8;
        dstB[i] = (uint32_t)(k * 272 + c * 16);
    }
    const ptrdiff_t dA1 = A1 - A0, dB1 = B1 - B0;

    float acc[2][8][4];
#pragma unroll
    for (int a = 0; a < 2; a++)
#pragma unroll
        for (int b = 0; b < 8; b++)
#pragma unroll
            for (int c = 0; c < 4; c++) acc[a][b][c] = 0.f;

#pragma unroll
    for (int i = 0; i < 2; i++) {
        cp16(smb + dstA[i], srcA[i], true);
        cp16(smb + R_ALO + dstA[i], srcA[i] + dA1, true);
        cp16(smb + R_OFFB + dstB[i], srcB[i], true);
        cp16(smb + R_OFFB + R_BPL + dstB[i], srcB[i] + dB1, true);
    }
    CP_COMMIT();

    const int NK = K / BK;
    for (int c = 0; c < NK; c++) {
        const int s = c & 1;
        if (c + 1 < NK) {
            const uint32_t nb = smb + (s ^ 1) * R_STAGE;
            const int kc = (c + 1) * BK;
#pragma unroll
            for (int i = 0; i < 2; i++) {
                cp16(nb + dstA[i], srcA[i] + kc, true);
                cp16(nb + R_ALO + dstA[i], srcA[i] + dA1 + kc, true);
                cp16(nb + R_OFFB + dstB[i], srcB[i] + (size_t)kc * N3P, true);
                cp16(nb + R_OFFB + R_BPL + dstB[i], srcB[i] + dB1 + (size_t)kc * N3P, true);
            }
            CP_COMMIT();
            cp_wait<1>();
        } else {
            cp_wait<0>();
        }
        __syncthreads();
        chunk3h(smb + s * R_STAGE, mw, nw, lane, acc);
        __syncthreads();
    }

#pragma unroll
    for (int mt = 0; mt < 2; mt++) {
        int lr0 = mw + mt * 16 + (lane >> 2);
        int lr1 = lr0 + 8;
#pragma unroll
        for (int nt = 0; nt < 8; nt++) {
            int c = nw + nt * 8 + (lane & 3) * 2;
            float z0 = __ldg(&bias[n0 + c]), z1 = __ldg(&bias[n0 + c + 1]);
            float2 v0 = make_float2(acc[mt][nt][0] + z0, acc[mt][nt][1] + z1);
            float2 v1 = make_float2(acc[mt][nt][2] + z0, acc[mt][nt][3] + z1);
            *(float2*)&C[(size_t)(m0 + lr0) * N3P + n0 + c] = v0;
            *(float2*)&C[(size_t)(m0 + lr1) * N3P + n0 + c] = v1;
        }
    }
}

// ---------------- GRU + router (top-2) ----------------
__global__ void __launch_bounds__(128) k_gru_route(
    const float* __restrict__ h_prev,
    const float* __restrict__ Wr, const float* __restrict__ br,
    float* __restrict__ h_out)
{
    const int t = blockIdx.x;
    const int j = threadIdx.x;
    __shared__ float hs[PP];
    __shared__ float logit[NE];

    const float* gx = g_gx + (size_t)t * N3P;
    const float* gh = g_gh + (size_t)t * N3P;
    float xr = gx[j], xz = gx[PP + j], xn = gx[2 * PP + j];
    float hr = gh[j], hz = gh[PP + j], hn = gh[2 * PP + j];
    float r = 1.f / (1.f + expf(-(xr + hr)));
    float z = 1.f / (1.f + expf(-(xz + hz)));
    float n = tanhf(xn + r * hn);
    float hp = h_prev[(size_t)t * PP + j];
    float h = (1.f - z) * n + z * hp;
    hs[j] = h;
    h_out[(size_t)t * PP + j] = h;
    __syncthreads();

    const int w = j >> 5, lane = j & 31;
    for (int e = w; e < NE; e += 4) {
        float p = 0.f;
#pragma unroll
        for (int c = 0; c < 4; c++)
            p += Wr[e * PP + lane + 32 * c] * hs[lane + 32 * c];
#pragma unroll
        for (int off = 16; off; off >>= 1) p += __shfl_down_sync(0xffffffffu, p, off);
        if (lane == 0) logit[e] = p + br[e];
    }
    __syncthreads();

    if (j == 0) {
        int e0 = 0, e1 = -1;
        float l0 = logit[0], l1 = -1e30f;
        for (int e = 1; e < NE; e++) {
            float v = logit[e];
            if (v > l0) { l1 = l0; e1 = e0; l0 = v; e0 = e; }
            else if (v > l1) { l1 = v; e1 = e; }
        }
        float p1 = expf(l1 - l0);
        float inv = 1.f / (1.0f + p1);
        float p0 = inv; p1 *= inv;
        int pos0 = atomicAdd(&g_count[e0], 1);
        g_list[e0 * T_TOK + pos0] = t; g_wt[e0 * T_TOK + pos0] = p0;
        int pos1 = atomicAdd(&g_count[e1], 1);
        g_list[e1 * T_TOK + pos1] = t; g_wt[e1 * T_TOK + pos1] = p1;
    }
}

__device__ __forceinline__ void expert_base(int e, int& cnt, int& base) {
    base = 0; cnt = 0;
#pragma unroll
    for (int i = 0; i < NE; i++) {
        int c = __ldg(&g_count[i]);
        if (i < e) base += c;
        if (i == e) cnt = c;
    }
}

// ============== expert up-proj: BM=128, BN=256, 512 threads ==============
__global__ void __launch_bounds__(512) k_expert_up(const float* __restrict__ b1)
{
    const int e = blockIdx.z;
    int cnt, base;
    expert_base(e, cnt, base);
    const int m0 = blockIdx.x * 128;
    if (m0 >= cnt) return;
    const int n0 = blockIdx.y * 256;
    const float* b1e = b1 + (size_t)e * DFF;
    const size_t rowbase = (size_t)base + m0;

    extern __shared__ __align__(16) char dsm[];
    const uint32_t smb = smem_u32(dsm);
    __shared__ int rowidx[128];

    const int tid = threadIdx.x;
    const int wid = tid >> 5, lane = tid & 31;
    const int mw = (wid & 3) * 32, nw = (wid >> 2) * 64;

    if (tid < 128)
        rowidx[tid] = (m0 + tid < cnt) ? g_list[e * T_TOK + m0 + tid] : -1;
    __syncthreads();

    const int ra = tid >> 2, qa = tid & 3;
    const int grA = rowidx[ra];
    const bool okA = (grA >= 0);
    const __half* srcA = g_xh0 + (size_t)(okA ? grA : 0) * DM + qa * 8;
    const uint32_t dstA = (uint32_t)(ra * 80 + qa * 16);
    const ptrdiff_t dA1 = g_xh1 - g_xh0;

    const __half* srcB[2];
    uint32_t dstB[2];
#pragma unroll
    for (int i = 0; i < 2; i++) {
        int it = tid + i * 512;
        int k = it >> 5, c = it & 31;
        srcB[i] = g_w1h + (size_t)e * DM * DFF + (size_t)k * DFF + n0 + c * 8;
        dstB[i] = (uint32_t)(k * 528 + c * 16);
    }

    float acc[2][8][4];
#pragma unroll
    for (int x = 0; x < 2; x++)
#pragma unroll
        for (int y = 0; y < 8; y++)
#pragma unroll
            for (int zz = 0; zz < 4; zz++) acc[x][y][zz] = 0.f;

    cp16(smb + dstA, srcA, okA);
    cp16(smb + U_ALO + dstA, srcA + dA1, okA);
#pragma unroll
    for (int i = 0; i < 2; i++)
        cp16(smb + U_OFFB + dstB[i], srcB[i], true);
    CP_COMMIT();

    const int NK = DM / BK;  // 16
    for (int c = 0; c < NK; c++) {
        const int s = c & 1;
        if (c + 1 < NK) {
            const uint32_t nb = smb + (s ^ 1) * U_STAGE;
            const int kc = (c + 1) * BK;
            cp16(nb + dstA, srcA + kc, okA);
            cp16(nb + U_ALO + dstA, srcA + dA1 + kc, okA);
#pragma unroll
            for (int i = 0; i < 2; i++)
                cp16(nb + U_OFFB + dstB[i], srcB[i] + (size_t)kc * DFF, true);
            CP_COMMIT();
            cp_wait<1>();
        } else {
            cp_wait<0>();
        }
        __syncthreads();
        chunk2h<U_ALO, U_OFFB, 528>(smb + s * U_STAGE, mw, nw, lane, acc);
        __syncthreads();
    }

    // epilogue: bias + relu -> 2-plane fp16 hidden
#pragma unroll
    for (int mt = 0; mt < 2; mt++) {
        int lr0 = mw + mt * 16 + (lane >> 2);
        int lr1 = lr0 + 8;
        bool ok0 = (m0 + lr0 < cnt), ok1 = (m0 + lr1 < cnt);
        size_t row0 = rowbase + lr0, row1 = rowbase + lr1;
#pragma unroll
        for (int nt = 0; nt < 8; nt++) {
            int c = nw + nt * 8 + (lane & 3) * 2;
            float z0 = __ldg(&b1e[n0 + c]), z1 = __ldg(&b1e[n0 + c + 1]);
            if (ok0) {
                float v0 = fmaxf(acc[mt][nt][0] + z0, 0.f);
                float v1 = fmaxf(acc[mt][nt][1] + z1, 0.f);
                float r0, r1;
                uint32_t H = packh2_hi(v0, v1, r0, r1);
                uint32_t L = packh2(r0, r1);
                *(uint32_t*)(g_hid0 + row0 * DFF + n0 + c) = H;
                *(uint32_t*)(g_hid1 + row0 * DFF + n0 + c) = L;
            }
            if (ok1) {
                float v0 = fmaxf(acc[mt][nt][2] + z0, 0.f);
                float v1 = fmaxf(acc[mt][nt][3] + z1, 0.f);
                float r0, r1;
                uint32_t H = packh2_hi(v0, v1, r0, r1);
                uint32_t L = packh2(r0, r1);
                *(uint32_t*)(g_hid0 + row1 * DFF + n0 + c) = H;
                *(uint32_t*)(g_hid1 + row1 * DFF + n0 + c) = L;
            }
        }
    }
}

// ============== expert down-proj: BM=128, BN=128, 256 threads ==============
__global__ void __launch_bounds__(256) k_expert_down(
    const float* __restrict__ b2, float* __restrict__ out)
{
    const int e = blockIdx.z;
    int cnt, base;
    expert_base(e, cnt, base);
    const int m0 = blockIdx.x * 128;
    if (m0 >= cnt) return;
    const int n0 = blockIdx.y * 128;
    const float* b2e = b2 + (size_t)e * DM;
    const size_t rowbase = (size_t)base + m0;

    extern __shared__ __align__(16) char dsm[];
    const uint32_t smb = smem_u32(dsm);
    __shared__ int s_tok[128];
    __shared__ float s_w[128];

    const int tid = threadIdx.x;
    const int wid = tid >> 5, lane = tid & 31;
    const int mw = (wid & 3) * 32, nw = (wid >> 2) * 64;

    if (tid < 128) {
        bool ok = (m0 + tid < cnt);
        s_tok[tid] = ok ? g_list[e * T_TOK + m0 + tid] : 0;
        s_w[tid] = ok ? g_wt[e * T_TOK + m0 + tid] : 0.f;
    }
    __syncthreads();

    const __half* srcA[2];
    bool okA[2];
    uint32_t dstA[2];
#pragma unroll
    for (int i = 0; i < 2; i++) {
        int it = tid + i * 256;
        int r = it >> 2, q = it & 3;
        okA[i] = (m0 + r < cnt);
        srcA[i] = g_hid0 + (okA[i] ? (rowbase + r) : 0) * DFF + q * 8;
        dstA[i] = (uint32_t)(r * 80 + q * 16);
    }
    const __half* srcB[2];
    uint32_t dstB[2];
#pragma unroll
    for (int i = 0; i < 2; i++) {
        int it = tid + i * 256;
        int k = it >> 4, c = it & 15;
        srcB[i] = g_w2h + (size_t)e * DFF * DM + (size_t)k * DM + n0 + c * 8;
        dstB[i] = (uint32_t)(k * 272 + c * 16);
    }
    const ptrdiff_t dA1 = g_hid1 - g_hid0;

    float acc[2][8][4];
#pragma unroll
    for (int x = 0; x < 2; x++)
#pragma unroll
        for (int y = 0; y < 8; y++)
#pragma unroll
            for (int zz = 0; zz < 4; zz++) acc[x][y][zz] = 0.f;

#pragma unroll
    for (int i = 0; i < 2; i++) {
        cp16(smb + dstA[i], srcA[i], okA[i]);
        cp16(smb + D_ALO + dstA[i], srcA[i] + dA1, okA[i]);
        cp16(smb + D_OFFB + dstB[i], srcB[i], true);
    }
    CP_COMMIT();

    const int NK = DFF / BK;  // 64
    for (int c = 0; c < NK; c++) {
        const int s = c & 1;
        if (c + 1 < NK) {
            const uint32_t nb = smb + (s ^ 1) * D_STAGE;
            const int kc = (c + 1) * BK;
#pragma unroll
            for (int i = 0; i < 2; i++) {
                cp16(nb + dstA[i], srcA[i] + kc, okA[i]);
                cp16(nb + D_ALO + dstA[i], srcA[i] + dA1 + kc, okA[i]);
                cp16(nb + D_OFFB + dstB[i], srcB[i] + (size_t)kc * DM, true);
            }
            CP_COMMIT();
            cp_wait<1>();
        } else {
            cp_wait<0>();
        }
        __syncthreads();
        chunk2h<D_ALO, D_OFFB, 272>(smb + s * D_STAGE, mw, nw, lane, acc);
        __syncthreads();
    }

#pragma unroll
    for (int mt = 0; mt < 2; mt++) {
        int lr0 = mw + mt * 16 + (lane >> 2);
        int lr1 = lr0 + 8;
        bool ok0 = (m0 + lr0 < cnt), ok1 = (m0 + lr1 < cnt);
        int tok0 = s_tok[lr0], tok1 = s_tok[lr1];
        float w0 = s_w[lr0], w1 = s_w[lr1];
#pragma unroll
        for (int nt = 0; nt < 8; nt++) {
            int c = nw + nt * 8 + (lane & 3) * 2;
            float z0 = __ldg(&b2e[n0 + c]), z1 = __ldg(&b2e[n0 + c + 1]);
            if (ok0) {
                float* op = out + (size_t)tok0 * DM + n0 + c;
                atomicAdd(op,     w0 * (acc[mt][nt][0] + z0));
                atomicAdd(op + 1, w0 * (acc[mt][nt][1] + z1));
            }
            if (ok1) {
                float* op = out + (size_t)tok1 * DM + n0 + c;
                atomicAdd(op,     w1 * (acc[mt][nt][2] + z0));
                atomicAdd(op + 1, w1 * (acc[mt][nt][3] + z1));
            }
        }
    }
}

// ---------------- host launcher ----------------
extern "C" void kernel_launch(void* const* d_in, const int* in_sizes, int n_in,
                              void* d_out, int out_size) {
    const float* x      = (const float*)d_in[0];
    const float* h_prev = (const float*)d_in[1];
    const float* Wp     = (const float*)d_in[2];
    const float* bp     = (const float*)d_in[3];
    const float* W_ih   = (const float*)d_in[4];
    const float* W_hh   = (const float*)d_in[5];
    const float* b_ih   = (const float*)d_in[6];
    const float* b_hh   = (const float*)d_in[7];
    const float* Wr     = (const float*)d_in[8];
    const float* br     = (const float*)d_in[9];
    const float* W1     = (const float*)d_in[10];
    const float* b1     = (const float*)d_in[11];
    const float* W2     = (const float*)d_in[12];
    const float* b2     = (const float*)d_in[13];

    float* out   = (float*)d_out;
    float* h_out = out + OUT_ELEMS;

    cudaFuncSetAttribute(k_rgemm,
                         cudaFuncAttributeMaxDynamicSharedMemorySize, R_DYN);
    cudaFuncSetAttribute(k_expert_up,
                         cudaFuncAttributeMaxDynamicSharedMemorySize, U_DYN);
    cudaFuncSetAttribute(k_expert_down,
                         cudaFuncAttributeMaxDynamicSharedMemorySize, D_DYN);

    k_prep<<<2048, 256>>>(x, h_prev, W_ih, b_ih, Wp, bp, W_hh, W1, W2, out);
    k_rgemm<<<dim3(3, 32, 2), 256, R_DYN>>>(b_hh);
    k_gru_route<<<T_TOK, 128>>>(h_prev, Wr, br, h_out);
    k_expert_up<<<dim3(T_TOK / 128, DFF / 256, NE), 512, U_DYN>>>(b1);
    k_expert_down<<<dim3(T_TOK / 128, DM / 128, NE), 256, D_DYN>>>(b2, out);
}

// round 7
// speedup vs baseline: 2.6986x; 1.0979x over previous
#include <cuda_runtime.h>
#include <cuda_fp16.h>
#include <cstdint>
#include <math.h>

#define T_TOK 4096
#define DM 512
#define DFF 2048
#define NE 16
#define PP 128
#define N3P 384
#define OUT_ELEMS (T_TOK * DM)
#define BK 32

// ---- rgemm stage: A 2 planes (128x80B), B 2 planes (32x272B) ----
#define R_ALO 10240
#define R_OFFB 20480
#define R_BPL 8704
#define R_STAGE 37888
#define R_DYN (2 * R_STAGE)
// ---- expert stage (BM=128, BN=128): A 2 planes, B 1 plane (32x272B) ----
#define E_ALO 10240
#define E_OFFB 20480
#define E_STAGE 29184
#define E_DYN (3 * E_STAGE)

// ---------------- device scratch ----------------
__device__ float g_gx[T_TOK * N3P];
__device__ float g_gh[T_TOK * N3P];
__device__ float g_bc[N3P];
__device__ __half g_xh0[T_TOK * DM];
__device__ __half g_xh1[T_TOK * DM];
__device__ __half g_hh0[T_TOK * PP];
__device__ __half g_hh1[T_TOK * PP];
__device__ __half g_wcT0[DM * N3P];
__device__ __half g_wcT1[DM * N3P];
__device__ __half g_whT0[PP * N3P];
__device__ __half g_whT1[PP * N3P];
__device__ __half g_w1h[(size_t)NE * DM * DFF];
__device__ __half g_w2h[(size_t)NE * DFF * DM];
__device__ __half g_hid0[(size_t)T_TOK * 2 * DFF];
__device__ __half g_hid1[(size_t)T_TOK * 2 * DFF];
__device__ int   g_list[NE * T_TOK];
__device__ float g_wt[NE * T_TOK];
__device__ int   g_count[NE];

// ---------------- helpers ----------------
__device__ __forceinline__ uint32_t smem_u32(const void* p) {
    uint32_t a;
    asm("{ .reg .u64 t; cvta.to.shared.u64 t, %1; cvt.u32.u64 %0, t; }"
        : "=r"(a) : "l"(p));
    return a;
}
__device__ __forceinline__ void ldmx4(uint32_t addr, uint32_t* r) {
    asm volatile("ldmatrix.sync.aligned.m8n8.x4.shared.b16 {%0,%1,%2,%3}, [%4];"
                 : "=r"(r[0]), "=r"(r[1]), "=r"(r[2]), "=r"(r[3]) : "r"(addr));
}
__device__ __forceinline__ void ldmx4t(uint32_t addr, uint32_t* r) {
    asm volatile("ldmatrix.sync.aligned.m8n8.x4.trans.shared.b16 {%0,%1,%2,%3}, [%4];"
                 : "=r"(r[0]), "=r"(r[1]), "=r"(r[2]), "=r"(r[3]) : "r"(addr));
}
__device__ __forceinline__ void mmah(float* d, const uint32_t* a, const uint32_t* b) {
    asm volatile(
        "mma.sync.aligned.m16n8k16.row.col.f32.f16.f16.f32 "
        "{%0,%1,%2,%3}, {%4,%5,%6,%7}, {%8,%9}, {%0,%1,%2,%3};"
        : "+f"(d[0]), "+f"(d[1]), "+f"(d[2]), "+f"(d[3])
        : "r"(a[0]), "r"(a[1]), "r"(a[2]), "r"(a[3]), "r"(b[0]), "r"(b[1]));
}
__device__ __forceinline__ void cp16(uint32_t dst, const void* src, bool ok) {
    int sz = ok ? 16 : 0;
    asm volatile("cp.async.cg.shared.global [%0], [%1], 16, %2;"
                 :: "r"(dst), "l"(src), "r"(sz) : "memory");
}
#define CP_COMMIT() asm volatile("cp.async.commit_group;" ::: "memory")
template <int N>
__device__ __forceinline__ void cp_wait() {
    asm volatile("cp.async.wait_group %0;" :: "n"(N) : "memory");
}
__device__ __forceinline__ uint32_t packh2(float a, float b) {
    __half2 h = __floats2half2_rn(a, b);
    return *reinterpret_cast<uint32_t*>(&h);
}
__device__ __forceinline__ uint32_t packh2_hi(float a, float b, float& ra, float& rb) {
    __half2 h = __floats2half2_rn(a, b);
    ra = a - __low2float(h);
    rb = b - __high2float(h);
    return *reinterpret_cast<uint32_t*>(&h);
}

// ---------------- prep ----------------
__global__ void __launch_bounds__(256) k_prep(
    const float* __restrict__ x, const float* __restrict__ h_prev,
    const float* __restrict__ W_ih, const float* __restrict__ b_ih,
    const float* __restrict__ Wp, const float* __restrict__ bp,
    const float* __restrict__ W_hh,
    const float* __restrict__ W1, const float* __restrict__ W2,
    float* __restrict__ out)
{
    const int tid = blockIdx.x * blockDim.x + threadIdx.x;
    const int nth = gridDim.x * blockDim.x;
    if (tid < NE) g_count[tid] = 0;

    float4* o4 = (float4*)out;
    for (int i = tid; i < OUT_ELEMS / 4; i += nth)
        o4[i] = make_float4(0.f, 0.f, 0.f, 0.f);

    {
        const float4* s = (const float4*)x;
        uint2* p0 = (uint2*)g_xh0; uint2* p1 = (uint2*)g_xh1;
        for (int i = tid; i < T_TOK * DM / 4; i += nth) {
            float4 v = s[i]; float r0, r1, r2, r3; uint2 H, L;
            H.x = packh2_hi(v.x, v.y, r0, r1); H.y = packh2_hi(v.z, v.w, r2, r3);
            L.x = packh2(r0, r1); L.y = packh2(r2, r3);
            p0[i] = H; p1[i] = L;
        }
    }
    {
        const float4* s = (const float4*)h_prev;
        uint2* p0 = (uint2*)g_hh0; uint2* p1 = (uint2*)g_hh1;
        for (int i = tid; i < T_TOK * PP / 4; i += nth) {
            float4 v = s[i]; float r0, r1, r2, r3; uint2 H, L;
            H.x = packh2_hi(v.x, v.y, r0, r1); H.y = packh2_hi(v.z, v.w, r2, r3);
            L.x = packh2(r0, r1); L.y = packh2(r2, r3);
            p0[i] = H; p1[i] = L;
        }
    }
    {
        const float4* s = (const float4*)W1;
        uint2* p = (uint2*)g_w1h;
        for (int i = tid; i < NE * DM * DFF / 4; i += nth) {
            float4 v = s[i]; uint2 H;
            H.x = packh2(v.x, v.y); H.y = packh2(v.z, v.w);
            p[i] = H;
        }
    }
    {
        const float4* s = (const float4*)W2;
        uint2* p = (uint2*)g_w2h;
        for (int i = tid; i < NE * DFF * DM / 4; i += nth) {
            float4 v = s[i]; uint2 H;
            H.x = packh2(v.x, v.y); H.y = packh2(v.z, v.w);
            p[i] = H;
        }
    }
    for (int i = tid; i < PP * N3P; i += nth) {
        int n = i % N3P, k = i / N3P;
        float v = W_hh[n * PP + k];
        __half h = __float2half_rn(v);
        g_whT0[i] = h;
        g_whT1[i] = __float2half_rn(v - __half2float(h));
    }
    for (int i = tid; i < DM * N3P; i += nth) {
        int n = i % N3P, k = i / N3P;
        float s = 0.f;
        const float* wr = W_ih + n * PP;
#pragma unroll 8
        for (int p = 0; p < PP; p++) s = fmaf(wr[p], Wp[p * DM + k], s);
        __half h = __float2half_rn(s);
        g_wcT0[i] = h;
        g_wcT1[i] = __float2half_rn(s - __half2float(h));
    }
    for (int i = tid; i < N3P; i += nth) {
        float s = b_ih[i];
        const float* wr = W_ih + i * PP;
        for (int p = 0; p < PP; p++) s = fmaf(wr[p], bp[p], s);
        g_bc[i] = s;
    }
}

// ============== compute bodies ==============
__device__ __forceinline__ void chunk3h(uint32_t sb, int mw, int nw, int lane,
                                        float acc[2][8][4]) {
#pragma unroll
    for (int ks = 0; ks < 2; ks++) {
        uint32_t ah[2][4], al[2][4];
        uint32_t arow = (uint32_t)((mw + (lane & 15)) * 80 + ks * 32 + ((lane >> 4) << 4));
        ldmx4(sb + arow, ah[0]);
        ldmx4(sb + arow + 16 * 80, ah[1]);
        ldmx4(sb + R_ALO + arow, al[0]);
        ldmx4(sb + R_ALO + arow + 16 * 80, al[1]);
        uint32_t brow = (uint32_t)((ks * 16 + (lane & 15)) * 272 + (nw + ((lane >> 4) << 3)) * 2);
#pragma unroll
        for (int nb = 0; nb < 4; nb++) {
            uint32_t bh[4], bl[4];
            ldmx4t(sb + R_OFFB + brow + nb * 32, bh);
            ldmx4t(sb + R_OFFB + R_BPL + brow + nb * 32, bl);
#pragma unroll
            for (int mt = 0; mt < 2; mt++) {
                mmah(acc[mt][2 * nb],     ah[mt], bh);
                mmah(acc[mt][2 * nb],     ah[mt], bl);
                mmah(acc[mt][2 * nb],     al[mt], bh);
                mmah(acc[mt][2 * nb + 1], ah[mt], bh + 2);
                mmah(acc[mt][2 * nb + 1], ah[mt], bl + 2);
                mmah(acc[mt][2 * nb + 1], al[mt], bh + 2);
            }
        }
    }
}

// 2-product fp16 (experts): A 2-plane, B 1-plane (BN=128)
__device__ __forceinline__ void chunk2h(uint32_t sb, int mw, int nw, int lane,
                                        float acc[2][8][4]) {
#pragma unroll
    for (int ks = 0; ks < 2; ks++) {
        uint32_t ah[2][4], al[2][4];
        uint32_t arow = (uint32_t)((mw + (lane & 15)) * 80 + ks * 32 + ((lane >> 4) << 4));
        ldmx4(sb + arow, ah[0]);
        ldmx4(sb + arow + 16 * 80, ah[1]);
        ldmx4(sb + E_ALO + arow, al[0]);
        ldmx4(sb + E_ALO + arow + 16 * 80, al[1]);
        uint32_t brow = (uint32_t)((ks * 16 + (lane & 15)) * 272 + (nw + ((lane >> 4) << 3)) * 2);
#pragma unroll
        for (int nb = 0; nb < 4; nb++) {
            uint32_t bh[4];
            ldmx4t(sb + E_OFFB + brow + nb * 32, bh);
#pragma unroll
            for (int mt = 0; mt < 2; mt++) {
                mmah(acc[mt][2 * nb],     ah[mt], bh);
                mmah(acc[mt][2 * nb],     al[mt], bh);
                mmah(acc[mt][2 * nb + 1], ah[mt], bh + 2);
                mmah(acc[mt][2 * nb + 1], al[mt], bh + 2);
            }
        }
    }
}

// ============== fused gate GEMMs ==============
__global__ void __launch_bounds__(256) k_rgemm(const float* __restrict__ b_hh)
{
    const int z = blockIdx.z;
    const int K = z ? PP : DM;
    const __half* A0 = z ? g_hh0 : g_xh0;
    const __half* A1 = z ? g_hh1 : g_xh1;
    const __half* B0 = z ? g_whT0 : g_wcT0;
    const __half* B1 = z ? g_whT1 : g_wcT1;
    const float* bias = z ? b_hh : g_bc;
    float* C = z ? g_gh : g_gx;

    const int m0 = blockIdx.y * 128;
    const int n0 = blockIdx.x * 128;
    extern __shared__ __align__(16) char dsm[];
    const uint32_t smb = smem_u32(dsm);

    const int tid = threadIdx.x;
    const int wid = tid >> 5, lane = tid & 31;
    const int mw = (wid & 3) * 32, nw = (wid >> 2) * 64;

    const __half* srcA[2];
    uint32_t dstA[2];
#pragma unroll
    for (int i = 0; i < 2; i++) {
        int it = tid + i * 256;
        int r = it >> 2, q = it & 3;
        srcA[i] = A0 + (size_t)(m0 + r) * K + q * 8;
        dstA[i] = (uint32_t)(r * 80 + q * 16);
    }
    const __half* srcB[2];
    uint32_t dstB[2];
#pragma unroll
    for (int i = 0; i < 2; i++) {
        int it = tid + i * 256;
        int k = it >> 4, c = it & 15;
        srcB[i] = B0 + (size_t)k * N3P + n0 + c * 8;
        dstB[i] = (uint32_t)(k * 272 + c * 16);
    }
    const ptrdiff_t dA1 = A1 - A0, dB1 = B1 - B0;

    float acc[2][8][4];
#pragma unroll
    for (int a = 0; a < 2; a++)
#pragma unroll
        for (int b = 0; b < 8; b++)
#pragma unroll
            for (int c = 0; c < 4; c++) acc[a][b][c] = 0.f;

#pragma unroll
    for (int i = 0; i < 2; i++) {
        cp16(smb + dstA[i], srcA[i], true);
        cp16(smb + R_ALO + dstA[i], srcA[i] + dA1, true);
        cp16(smb + R_OFFB + dstB[i], srcB[i], true);
        cp16(smb + R_OFFB + R_BPL + dstB[i], srcB[i] + dB1, true);
    }
    CP_COMMIT();

    const int NK = K / BK;
    for (int c = 0; c < NK; c++) {
        const int s = c & 1;
        if (c + 1 < NK) {
            const uint32_t nb = smb + (s ^ 1) * R_STAGE;
            const int kc = (c + 1) * BK;
#pragma unroll
            for (int i = 0; i < 2; i++) {
                cp16(nb + dstA[i], srcA[i] + kc, true);
                cp16(nb + R_ALO + dstA[i], srcA[i] + dA1 + kc, true);
                cp16(nb + R_OFFB + dstB[i], srcB[i] + (size_t)kc * N3P, true);
                cp16(nb + R_OFFB + R_BPL + dstB[i], srcB[i] + dB1 + (size_t)kc * N3P, true);
            }
            CP_COMMIT();
            cp_wait<1>();
        } else {
            cp_wait<0>();
        }
        __syncthreads();
        chunk3h(smb + s * R_STAGE, mw, nw, lane, acc);
        __syncthreads();
    }

#pragma unroll
    for (int mt = 0; mt < 2; mt++) {
        int lr0 = mw + mt * 16 + (lane >> 2);
        int lr1 = lr0 + 8;
#pragma unroll
        for (int nt = 0; nt < 8; nt++) {
            int c = nw + nt * 8 + (lane & 3) * 2;
            float z0 = __ldg(&bias[n0 + c]), z1 = __ldg(&bias[n0 + c + 1]);
            float2 v0 = make_float2(acc[mt][nt][0] + z0, acc[mt][nt][1] + z1);
            float2 v1 = make_float2(acc[mt][nt][2] + z0, acc[mt][nt][3] + z1);
            *(float2*)&C[(size_t)(m0 + lr0) * N3P + n0 + c] = v0;
            *(float2*)&C[(size_t)(m0 + lr1) * N3P + n0 + c] = v1;
        }
    }
}

// ---------------- GRU + router (top-2) ----------------
__global__ void __launch_bounds__(128) k_gru_route(
    const float* __restrict__ h_prev,
    const float* __restrict__ Wr, const float* __restrict__ br,
    float* __restrict__ h_out)
{
    const int t = blockIdx.x;
    const int j = threadIdx.x;
    __shared__ float hs[PP];
    __shared__ float logit[NE];

    const float* gx = g_gx + (size_t)t * N3P;
    const float* gh = g_gh + (size_t)t * N3P;
    float xr = gx[j], xz = gx[PP + j], xn = gx[2 * PP + j];
    float hr = gh[j], hz = gh[PP + j], hn = gh[2 * PP + j];
    float r = 1.f / (1.f + expf(-(xr + hr)));
    float z = 1.f / (1.f + expf(-(xz + hz)));
    float n = tanhf(xn + r * hn);
    float hp = h_prev[(size_t)t * PP + j];
    float h = (1.f - z) * n + z * hp;
    hs[j] = h;
    h_out[(size_t)t * PP + j] = h;
    __syncthreads();

    const int w = j >> 5, lane = j & 31;
    for (int e = w; e < NE; e += 4) {
        float p = 0.f;
#pragma unroll
        for (int c = 0; c < 4; c++)
            p += Wr[e * PP + lane + 32 * c] * hs[lane + 32 * c];
#pragma unroll
        for (int off = 16; off; off >>= 1) p += __shfl_down_sync(0xffffffffu, p, off);
        if (lane == 0) logit[e] = p + br[e];
    }
    __syncthreads();

    if (j == 0) {
        int e0 = 0, e1 = -1;
        float l0 = logit[0], l1 = -1e30f;
        for (int e = 1; e < NE; e++) {
            float v = logit[e];
            if (v > l0) { l1 = l0; e1 = e0; l0 = v; e0 = e; }
            else if (v > l1) { l1 = v; e1 = e; }
        }
        float p1 = expf(l1 - l0);
        float inv = 1.f / (1.0f + p1);
        float p0 = inv; p1 *= inv;
        int pos0 = atomicAdd(&g_count[e0], 1);
        g_list[e0 * T_TOK + pos0] = t; g_wt[e0 * T_TOK + pos0] = p0;
        int pos1 = atomicAdd(&g_count[e1], 1);
        g_list[e1 * T_TOK + pos1] = t; g_wt[e1 * T_TOK + pos1] = p1;
    }
}

__device__ __forceinline__ void expert_base(int e, int& cnt, int& base) {
    base = 0; cnt = 0;
#pragma unroll
    for (int i = 0; i < NE; i++) {
        int c = __ldg(&g_count[i]);
        if (i < e) base += c;
        if (i == e) cnt = c;
    }
}

// ============== expert up-proj: BM=128, BN=128, 256 thr, 3-stage ring ==============
__global__ void __launch_bounds__(256) k_expert_up(const float* __restrict__ b1)
{
    const int e = blockIdx.z;
    int cnt, base;
    expert_base(e, cnt, base);
    const int m0 = blockIdx.x * 128;
    if (m0 >= cnt) return;
    const int n0 = blockIdx.y * 128;
    const float* b1e = b1 + (size_t)e * DFF;
    const size_t rowbase = (size_t)base + m0;

    extern __shared__ __align__(16) char dsm[];
    const uint32_t smb = smem_u32(dsm);
    __shared__ int rowidx[128];

    const int tid = threadIdx.x;
    const int wid = tid >> 5, lane = tid & 31;
    const int mw = (wid & 3) * 32, nw = (wid >> 2) * 64;

    if (tid < 128)
        rowidx[tid] = (m0 + tid < cnt) ? g_list[e * T_TOK + m0 + tid] : -1;
    __syncthreads();

    const __half* srcA[2];
    bool okA[2];
    uint32_t dstA[2];
#pragma unroll
    for (int i = 0; i < 2; i++) {
        int it = tid + i * 256;
        int r = it >> 2, q = it & 3;
        int gr = rowidx[r];
        okA[i] = (gr >= 0);
        srcA[i] = g_xh0 + (size_t)(okA[i] ? gr : 0) * DM + q * 8;
        dstA[i] = (uint32_t)(r * 80 + q * 16);
    }
    const __half* srcB[2];
    uint32_t dstB[2];
#pragma unroll
    for (int i = 0; i < 2; i++) {
        int it = tid + i * 256;
        int k = it >> 4, c = it & 15;
        srcB[i] = g_w1h + (size_t)e * DM * DFF + (size_t)k * DFF + n0 + c * 8;
        dstB[i] = (uint32_t)(k * 272 + c * 16);
    }
    const ptrdiff_t dA1 = g_xh1 - g_xh0;

    float acc[2][8][4];
#pragma unroll
    for (int x = 0; x < 2; x++)
#pragma unroll
        for (int y = 0; y < 8; y++)
#pragma unroll
            for (int zz = 0; zz < 4; zz++) acc[x][y][zz] = 0.f;

#pragma unroll
    for (int st = 0; st < 2; st++) {
        const uint32_t nb = smb + st * E_STAGE;
        const int kc = st * BK;
#pragma unroll
        for (int i = 0; i < 2; i++) {
            cp16(nb + dstA[i], srcA[i] + kc, okA[i]);
            cp16(nb + E_ALO + dstA[i], srcA[i] + dA1 + kc, okA[i]);
            cp16(nb + E_OFFB + dstB[i], srcB[i] + (size_t)kc * DFF, true);
        }
        CP_COMMIT();
    }

    const int NK = DM / BK;  // 16
    int s = 0;
    for (int c = 0; c < NK; c++) {
        if (c + 2 < NK) cp_wait<1>(); else cp_wait<0>();
        __syncthreads();
        if (c + 2 < NK) {
            int s2 = s + 2; if (s2 >= 3) s2 -= 3;
            const uint32_t nb = smb + s2 * E_STAGE;
            const int kc = (c + 2) * BK;
#pragma unroll
            for (int i = 0; i < 2; i++) {
                cp16(nb + dstA[i], srcA[i] + kc, okA[i]);
                cp16(nb + E_ALO + dstA[i], srcA[i] + dA1 + kc, okA[i]);
                cp16(nb + E_OFFB + dstB[i], srcB[i] + (size_t)kc * DFF, true);
            }
            CP_COMMIT();
        }
        chunk2h(smb + s * E_STAGE, mw, nw, lane, acc);
        if (++s == 3) s = 0;
    }

    // epilogue: bias + relu -> 2-plane fp16 hidden
#pragma unroll
    for (int mt = 0; mt < 2; mt++) {
        int lr0 = mw + mt * 16 + (lane >> 2);
        int lr1 = lr0 + 8;
        bool ok0 = (m0 + lr0 < cnt), ok1 = (m0 + lr1 < cnt);
        size_t row0 = rowbase + lr0, row1 = rowbase + lr1;
#pragma unroll
        for (int nt = 0; nt < 8; nt++) {
            int c = nw + nt * 8 + (lane & 3) * 2;
            float z0 = __ldg(&b1e[n0 + c]), z1 = __ldg(&b1e[n0 + c + 1]);
            if (ok0) {
                float v0 = fmaxf(acc[mt][nt][0] + z0, 0.f);
                float v1 = fmaxf(acc[mt][nt][1] + z1, 0.f);
                float r0, r1;
                uint32_t H = packh2_hi(v0, v1, r0, r1);
                uint32_t L = packh2(r0, r1);
                *(uint32_t*)(g_hid0 + row0 * DFF + n0 + c) = H;
                *(uint32_t*)(g_hid1 + row0 * DFF + n0 + c) = L;
            }
            if (ok1) {
                float v0 = fmaxf(acc[mt][nt][2] + z0, 0.f);
                float v1 = fmaxf(acc[mt][nt][3] + z1, 0.f);
                float r0, r1;
                uint32_t H = packh2_hi(v0, v1, r0, r1);
                uint32_t L = packh2(r0, r1);
                *(uint32_t*)(g_hid0 + row1 * DFF + n0 + c) = H;
                *(uint32_t*)(g_hid1 + row1 * DFF + n0 + c) = L;
            }
        }
    }
}

// ============== expert down-proj: BM=128, BN=128, 256 thr, 3-stage ring ==============
__global__ void __launch_bounds__(256) k_expert_down(
    const float* __restrict__ b2, float* __restrict__ out)
{
    const int e = blockIdx.z;
    int cnt, base;
    expert_base(e, cnt, base);
    const int m0 = blockIdx.x * 128;
    if (m0 >= cnt) return;
    const int n0 = blockIdx.y * 128;
    const float* b2e = b2 + (size_t)e * DM;
    const size_t rowbase = (size_t)base + m0;

    extern __shared__ __align__(16) char dsm[];
    const uint32_t smb = smem_u32(dsm);
    __shared__ int s_tok[128];
    __shared__ float s_w[128];

    const int tid = threadIdx.x;
    const int wid = tid >> 5, lane = tid & 31;
    const int mw = (wid & 3) * 32, nw = (wid >> 2) * 64;

    if (tid < 128) {
        bool ok = (m0 + tid < cnt);
        s_tok[tid] = ok ? g_list[e * T_TOK + m0 + tid] : 0;
        s_w[tid] = ok ? g_wt[e * T_TOK + m0 + tid] : 0.f;
    }
    __syncthreads();

    const __half* srcA[2];
    bool okA[2];
    uint32_t dstA[2];
#pragma unroll
    for (int i = 0; i < 2; i++) {
        int it = tid + i * 256;
        int r = it >> 2, q = it & 3;
        okA[i] = (m0 + r < cnt);
        srcA[i] = g_hid0 + (okA[i] ? (rowbase + r) : 0) * DFF + q * 8;
        dstA[i] = (uint32_t)(r * 80 + q * 16);
    }
    const __half* srcB[2];
    uint32_t dstB[2];
#pragma unroll
    for (int i = 0; i < 2; i++) {
        int it = tid + i * 256;
        int k = it >> 4, c = it & 15;
        srcB[i] = g_w2h + (size_t)e * DFF * DM + (size_t)k * DM + n0 + c * 8;
        dstB[i] = (uint32_t)(k * 272 + c * 16);
    }
    const ptrdiff_t dA1 = g_hid1 - g_hid0;

    float acc[2][8][4];
#pragma unroll
    for (int x = 0; x < 2; x++)
#pragma unroll
        for (int y = 0; y < 8; y++)
#pragma unroll
            for (int zz = 0; zz < 4; zz++) acc[x][y][zz] = 0.f;

#pragma unroll
    for (int st = 0; st < 2; st++) {
        const uint32_t nb = smb + st * E_STAGE;
        const int kc = st * BK;
#pragma unroll
        for (int i = 0; i < 2; i++) {
            cp16(nb + dstA[i], srcA[i] + kc, okA[i]);
            cp16(nb + E_ALO + dstA[i], srcA[i] + dA1 + kc, okA[i]);
            cp16(nb + E_OFFB + dstB[i], srcB[i] + (size_t)kc * DM, true);
        }
        CP_COMMIT();
    }

    const int NK = DFF / BK;  // 64
    int s = 0;
    for (int c = 0; c < NK; c++) {
        if (c + 2 < NK) cp_wait<1>(); else cp_wait<0>();
        __syncthreads();
        if (c + 2 < NK) {
            int s2 = s + 2; if (s2 >= 3) s2 -= 3;
            const uint32_t nb = smb + s2 * E_STAGE;
            const int kc = (c + 2) * BK;
#pragma unroll
            for (int i = 0; i < 2; i++) {
                cp16(nb + dstA[i], srcA[i] + kc, okA[i]);
                cp16(nb + E_ALO + dstA[i], srcA[i] + dA1 + kc, okA[i]);
                cp16(nb + E_OFFB + dstB[i], srcB[i] + (size_t)kc * DM, true);
            }
            CP_COMMIT();
        }
        chunk2h(smb + s * E_STAGE, mw, nw, lane, acc);
        if (++s == 3) s = 0;
    }

#pragma unroll
    for (int mt = 0; mt < 2; mt++) {
        int lr0 = mw + mt * 16 + (lane >> 2);
        int lr1 = lr0 + 8;
        bool ok0 = (m0 + lr0 < cnt), ok1 = (m0 + lr1 < cnt);
        int tok0 = s_tok[lr0], tok1 = s_tok[lr1];
        float w0 = s_w[lr0], w1 = s_w[lr1];
#pragma unroll
        for (int nt = 0; nt < 8; nt++) {
            int c = nw + nt * 8 + (lane & 3) * 2;
            float z0 = __ldg(&b2e[n0 + c]), z1 = __ldg(&b2e[n0 + c + 1]);
            if (ok0) {
                float* op = out + (size_t)tok0 * DM + n0 + c;
                atomicAdd(op,     w0 * (acc[mt][nt][0] + z0));
                atomicAdd(op + 1, w0 * (acc[mt][nt][1] + z1));
            }
            if (ok1) {
                float* op = out + (size_t)tok1 * DM + n0 + c;
                atomicAdd(op,     w1 * (acc[mt][nt][2] + z0));
                atomicAdd(op + 1, w1 * (acc[mt][nt][3] + z1));
            }
        }
    }
}

// ---------------- host launcher ----------------
extern "C" void kernel_launch(void* const* d_in, const int* in_sizes, int n_in,
                              void* d_out, int out_size) {
    const float* x      = (const float*)d_in[0];
    const float* h_prev = (const float*)d_in[1];
    const float* Wp     = (const float*)d_in[2];
    const float* bp     = (const float*)d_in[3];
    const float* W_ih   = (const float*)d_in[4];
    const float* W_hh   = (const float*)d_in[5];
    const float* b_ih   = (const float*)d_in[6];
    const float* b_hh   = (const float*)d_in[7];
    const float* Wr     = (const float*)d_in[8];
    const float* br     = (const float*)d_in[9];
    const float* W1     = (const float*)d_in[10];
    const float* b1     = (const float*)d_in[11];
    const float* W2     = (const float*)d_in[12];
    const float* b2     = (const float*)d_in[13];

    float* out   = (float*)d_out;
    float* h_out = out + OUT_ELEMS;

    cudaFuncSetAttribute(k_rgemm,
                         cudaFuncAttributeMaxDynamicSharedMemorySize, R_DYN);
    cudaFuncSetAttribute(k_expert_up,
                         cudaFuncAttributeMaxDynamicSharedMemorySize, E_DYN);
    cudaFuncSetAttribute(k_expert_down,
                         cudaFuncAttributeMaxDynamicSharedMemorySize, E_DYN);

    k_prep<<<2048, 256>>>(x, h_prev, W_ih, b_ih, Wp, bp, W_hh, W1, W2, out);
    k_rgemm<<<dim3(3, 32, 2), 256, R_DYN>>>(b_hh);
    k_gru_route<<<T_TOK, 128>>>(h_prev, Wr, br, h_out);
    k_expert_up<<<dim3(T_TOK / 128, DFF / 128, NE), 256, E_DYN>>>(b1);
    k_expert_down<<<dim3(T_TOK / 128, DM / 128, NE), 256, E_DYN>>>(b2, out);
}

// round 8
// speedup vs baseline: 3.2424x; 1.2015x over previous
#include <cuda_runtime.h>
#include <cuda_fp16.h>
#include <cstdint>
#include <math.h>

#define T_TOK 4096
#define DM 512
#define DFF 2048
#define NE 16
#define PP 128
#define N3P 384
#define OUT_ELEMS (T_TOK * DM)
#define BK 32

// ---- rgemm stage: A 2 planes (128x80B), B 2 planes (32x272B) ----
#define R_ALO 10240
#define R_OFFB 20480
#define R_BPL 8704
#define R_STAGE 37888
#define R_DYN (2 * R_STAGE)
// ---- expert stage (BM=128, BN=128): A 1 plane (10240B), B 1 plane (8704B) ----
#define E_OFFB 10240
#define E_STAGE 18944
#define E_DYN (4 * E_STAGE)
// down split-K
#define KSPLIT 4
#define KSEG (DFF / KSPLIT)   // 512

// ---------------- device scratch ----------------
__device__ float g_gx[T_TOK * N3P];
__device__ float g_gh[T_TOK * N3P];
__device__ float g_bc[N3P];
__device__ __half g_xh0[T_TOK * DM];
__device__ __half g_xh1[T_TOK * DM];
__device__ __half g_hh0[T_TOK * PP];
__device__ __half g_hh1[T_TOK * PP];
__device__ __half g_wcT0[DM * N3P];
__device__ __half g_wcT1[DM * N3P];
__device__ __half g_whT0[PP * N3P];
__device__ __half g_whT1[PP * N3P];
__device__ __half g_w1h[(size_t)NE * DM * DFF];
__device__ __half g_w2h[(size_t)NE * DFF * DM];
__device__ __half g_hid0[(size_t)T_TOK * 2 * DFF];
__device__ int   g_list[NE * T_TOK];
__device__ float g_wt[NE * T_TOK];
__device__ int   g_count[NE];

// ---------------- helpers ----------------
__device__ __forceinline__ uint32_t smem_u32(const void* p) {
    uint32_t a;
    asm("{ .reg .u64 t; cvta.to.shared.u64 t, %1; cvt.u32.u64 %0, t; }"
        : "=r"(a) : "l"(p));
    return a;
}
__device__ __forceinline__ void ldmx4(uint32_t addr, uint32_t* r) {
    asm volatile("ldmatrix.sync.aligned.m8n8.x4.shared.b16 {%0,%1,%2,%3}, [%4];"
                 : "=r"(r[0]), "=r"(r[1]), "=r"(r[2]), "=r"(r[3]) : "r"(addr));
}
__device__ __forceinline__ void ldmx4t(uint32_t addr, uint32_t* r) {
    asm volatile("ldmatrix.sync.aligned.m8n8.x4.trans.shared.b16 {%0,%1,%2,%3}, [%4];"
                 : "=r"(r[0]), "=r"(r[1]), "=r"(r[2]), "=r"(r[3]) : "r"(addr));
}
__device__ __forceinline__ void mmah(float* d, const uint32_t* a, const uint32_t* b) {
    asm volatile(
        "mma.sync.aligned.m16n8k16.row.col.f32.f16.f16.f32 "
        "{%0,%1,%2,%3}, {%4,%5,%6,%7}, {%8,%9}, {%0,%1,%2,%3};"
        : "+f"(d[0]), "+f"(d[1]), "+f"(d[2]), "+f"(d[3])
        : "r"(a[0]), "r"(a[1]), "r"(a[2]), "r"(a[3]), "r"(b[0]), "r"(b[1]));
}
__device__ __forceinline__ void cp16(uint32_t dst, const void* src, bool ok) {
    int sz = ok ? 16 : 0;
    asm volatile("cp.async.cg.shared.global [%0], [%1], 16, %2;"
                 :: "r"(dst), "l"(src), "r"(sz) : "memory");
}
#define CP_COMMIT() asm volatile("cp.async.commit_group;" ::: "memory")
template <int N>
__device__ __forceinline__ void cp_wait() {
    asm volatile("cp.async.wait_group %0;" :: "n"(N) : "memory");
}
__device__ __forceinline__ uint32_t packh2(float a, float b) {
    __half2 h = __floats2half2_rn(a, b);
    return *reinterpret_cast<uint32_t*>(&h);
}
__device__ __forceinline__ uint32_t packh2_hi(float a, float b, float& ra, float& rb) {
    __half2 h = __floats2half2_rn(a, b);
    ra = a - __low2float(h);
    rb = b - __high2float(h);
    return *reinterpret_cast<uint32_t*>(&h);
}

// ---------------- prep ----------------
__global__ void __launch_bounds__(256) k_prep(
    const float* __restrict__ x, const float* __restrict__ h_prev,
    const float* __restrict__ W_ih, const float* __restrict__ b_ih,
    const float* __restrict__ Wp, const float* __restrict__ bp,
    const float* __restrict__ W_hh,
    const float* __restrict__ W1, const float* __restrict__ W2,
    float* __restrict__ out)
{
    const int tid = blockIdx.x * blockDim.x + threadIdx.x;
    const int nth = gridDim.x * blockDim.x;
    if (tid < NE) g_count[tid] = 0;

    float4* o4 = (float4*)out;
    for (int i = tid; i < OUT_ELEMS / 4; i += nth)
        o4[i] = make_float4(0.f, 0.f, 0.f, 0.f);

    {
        const float4* s = (const float4*)x;
        uint2* p0 = (uint2*)g_xh0; uint2* p1 = (uint2*)g_xh1;
        for (int i = tid; i < T_TOK * DM / 4; i += nth) {
            float4 v = s[i]; float r0, r1, r2, r3; uint2 H, L;
            H.x = packh2_hi(v.x, v.y, r0, r1); H.y = packh2_hi(v.z, v.w, r2, r3);
            L.x = packh2(r0, r1); L.y = packh2(r2, r3);
            p0[i] = H; p1[i] = L;
        }
    }
    {
        const float4* s = (const float4*)h_prev;
        uint2* p0 = (uint2*)g_hh0; uint2* p1 = (uint2*)g_hh1;
        for (int i = tid; i < T_TOK * PP / 4; i += nth) {
            float4 v = s[i]; float r0, r1, r2, r3; uint2 H, L;
            H.x = packh2_hi(v.x, v.y, r0, r1); H.y = packh2_hi(v.z, v.w, r2, r3);
            L.x = packh2(r0, r1); L.y = packh2(r2, r3);
            p0[i] = H; p1[i] = L;
        }
    }
    {
        const float4* s = (const float4*)W1;
        uint2* p = (uint2*)g_w1h;
        for (int i = tid; i < NE * DM * DFF / 4; i += nth) {
            float4 v = s[i]; uint2 H;
            H.x = packh2(v.x, v.y); H.y = packh2(v.z, v.w);
            p[i] = H;
        }
    }
    {
        const float4* s = (const float4*)W2;
        uint2* p = (uint2*)g_w2h;
        for (int i = tid; i < NE * DFF * DM / 4; i += nth) {
            float4 v = s[i]; uint2 H;
            H.x = packh2(v.x, v.y); H.y = packh2(v.z, v.w);
            p[i] = H;
        }
    }
    for (int i = tid; i < PP * N3P; i += nth) {
        int n = i % N3P, k = i / N3P;
        float v = W_hh[n * PP + k];
        __half h = __float2half_rn(v);
        g_whT0[i] = h;
        g_whT1[i] = __float2half_rn(v - __half2float(h));
    }
    for (int i = tid; i < DM * N3P; i += nth) {
        int n = i % N3P, k = i / N3P;
        float s = 0.f;
        const float* wr = W_ih + n * PP;
#pragma unroll 8
        for (int p = 0; p < PP; p++) s = fmaf(wr[p], Wp[p * DM + k], s);
        __half h = __float2half_rn(s);
        g_wcT0[i] = h;
        g_wcT1[i] = __float2half_rn(s - __half2float(h));
    }
    for (int i = tid; i < N3P; i += nth) {
        float s = b_ih[i];
        const float* wr = W_ih + i * PP;
        for (int p = 0; p < PP; p++) s = fmaf(wr[p], bp[p], s);
        g_bc[i] = s;
    }
}

// ============== compute bodies ==============
__device__ __forceinline__ void chunk3h(uint32_t sb, int mw, int nw, int lane,
                                        float acc[2][8][4]) {
#pragma unroll
    for (int ks = 0; ks < 2; ks++) {
        uint32_t ah[2][4], al[2][4];
        uint32_t arow = (uint32_t)((mw + (lane & 15)) * 80 + ks * 32 + ((lane >> 4) << 4));
        ldmx4(sb + arow, ah[0]);
        ldmx4(sb + arow + 16 * 80, ah[1]);
        ldmx4(sb + R_ALO + arow, al[0]);
        ldmx4(sb + R_ALO + arow + 16 * 80, al[1]);
        uint32_t brow = (uint32_t)((ks * 16 + (lane & 15)) * 272 + (nw + ((lane >> 4) << 3)) * 2);
#pragma unroll
        for (int nb = 0; nb < 4; nb++) {
            uint32_t bh[4], bl[4];
            ldmx4t(sb + R_OFFB + brow + nb * 32, bh);
            ldmx4t(sb + R_OFFB + R_BPL + brow + nb * 32, bl);
#pragma unroll
            for (int mt = 0; mt < 2; mt++) {
                mmah(acc[mt][2 * nb],     ah[mt], bh);
                mmah(acc[mt][2 * nb],     ah[mt], bl);
                mmah(acc[mt][2 * nb],     al[mt], bh);
                mmah(acc[mt][2 * nb + 1], ah[mt], bh + 2);
                mmah(acc[mt][2 * nb + 1], ah[mt], bl + 2);
                mmah(acc[mt][2 * nb + 1], al[mt], bh + 2);
            }
        }
    }
}

// plain fp16 single-product (experts): A 1 plane, B 1 plane
__device__ __forceinline__ void chunk1h(uint32_t sb, int mw, int nw, int lane,
                                        float acc[2][8][4]) {
#pragma unroll
    for (int ks = 0; ks < 2; ks++) {
        uint32_t ah[2][4];
        uint32_t arow = (uint32_t)((mw + (lane & 15)) * 80 + ks * 32 + ((lane >> 4) << 4));
        ldmx4(sb + arow, ah[0]);
        ldmx4(sb + arow + 16 * 80, ah[1]);
        uint32_t brow = (uint32_t)((ks * 16 + (lane & 15)) * 272 + (nw + ((lane >> 4) << 3)) * 2);
#pragma unroll
        for (int nb = 0; nb < 4; nb++) {
            uint32_t bh[4];
            ldmx4t(sb + E_OFFB + brow + nb * 32, bh);
#pragma unroll
            for (int mt = 0; mt < 2; mt++) {
                mmah(acc[mt][2 * nb],     ah[mt], bh);
                mmah(acc[mt][2 * nb + 1], ah[mt], bh + 2);
            }
        }
    }
}

// ============== fused gate GEMMs ==============
__global__ void __launch_bounds__(256) k_rgemm(const float* __restrict__ b_hh)
{
    const int z = blockIdx.z;
    const int K = z ? PP : DM;
    const __half* A0 = z ? g_hh0 : g_xh0;
    const __half* A1 = z ? g_hh1 : g_xh1;
    const __half* B0 = z ? g_whT0 : g_wcT0;
    const __half* B1 = z ? g_whT1 : g_wcT1;
    const float* bias = z ? b_hh : g_bc;
    float* C = z ? g_gh : g_gx;

    const int m0 = blockIdx.y * 128;
    const int n0 = blockIdx.x * 128;
    extern __shared__ __align__(16) char dsm[];
    const uint32_t smb = smem_u32(dsm);

    const int tid = threadIdx.x;
    const int wid = tid >> 5, lane = tid & 31;
    const int mw = (wid & 3) * 32, nw = (wid >> 2) * 64;

    const __half* srcA[2];
    uint32_t dstA[2];
#pragma unroll
    for (int i = 0; i < 2; i++) {
        int it = tid + i * 256;
        int r = it >> 2, q = it & 3;
        srcA[i] = A0 + (size_t)(m0 + r) * K + q * 8;
        dstA[i] = (uint32_t)(r * 80 + q * 16);
    }
    const __half* srcB[2];
    uint32_t dstB[2];
#pragma unroll
    for (int i = 0; i < 2; i++) {
        int it = tid + i * 256;
        int k = it >> 4, c = it & 15;
        srcB[i] = B0 + (size_t)k * N3P + n0 + c * 8;
        dstB[i] = (uint32_t)(k * 272 + c * 16);
    }
    const ptrdiff_t dA1 = A1 - A0, dB1 = B1 - B0;

    float acc[2][8][4];
#pragma unroll
    for (int a = 0; a < 2; a++)
#pragma unroll
        for (int b = 0; b < 8; b++)
#pragma unroll
            for (int c = 0; c < 4; c++) acc[a][b][c] = 0.f;

#pragma unroll
    for (int i = 0; i < 2; i++) {
        cp16(smb + dstA[i], srcA[i], true);
        cp16(smb + R_ALO + dstA[i], srcA[i] + dA1, true);
        cp16(smb + R_OFFB + dstB[i], srcB[i], true);
        cp16(smb + R_OFFB + R_BPL + dstB[i], srcB[i] + dB1, true);
    }
    CP_COMMIT();

    const int NK = K / BK;
    for (int c = 0; c < NK; c++) {
        const int s = c & 1;
        if (c + 1 < NK) {
            const uint32_t nb = smb + (s ^ 1) * R_STAGE;
            const int kc = (c + 1) * BK;
#pragma unroll
            for (int i = 0; i < 2; i++) {
                cp16(nb + dstA[i], srcA[i] + kc, true);
                cp16(nb + R_ALO + dstA[i], srcA[i] + dA1 + kc, true);
                cp16(nb + R_OFFB + dstB[i], srcB[i] + (size_t)kc * N3P, true);
                cp16(nb + R_OFFB + R_BPL + dstB[i], srcB[i] + dB1 + (size_t)kc * N3P, true);
            }
            CP_COMMIT();
            cp_wait<1>();
        } else {
            cp_wait<0>();
        }
        __syncthreads();
        chunk3h(smb + s * R_STAGE, mw, nw, lane, acc);
        __syncthreads();
    }

#pragma unroll
    for (int mt = 0; mt < 2; mt++) {
        int lr0 = mw + mt * 16 + (lane >> 2);
        int lr1 = lr0 + 8;
#pragma unroll
        for (int nt = 0; nt < 8; nt++) {
            int c = nw + nt * 8 + (lane & 3) * 2;
            float z0 = __ldg(&bias[n0 + c]), z1 = __ldg(&bias[n0 + c + 1]);
            float2 v0 = make_float2(acc[mt][nt][0] + z0, acc[mt][nt][1] + z1);
            float2 v1 = make_float2(acc[mt][nt][2] + z0, acc[mt][nt][3] + z1);
            *(float2*)&C[(size_t)(m0 + lr0) * N3P + n0 + c] = v0;
            *(float2*)&C[(size_t)(m0 + lr1) * N3P + n0 + c] = v1;
        }
    }
}

// ---------------- GRU + router (top-2) ----------------
__global__ void __launch_bounds__(128) k_gru_route(
    const float* __restrict__ h_prev,
    const float* __restrict__ Wr, const float* __restrict__ br,
    float* __restrict__ h_out)
{
    const int t = blockIdx.x;
    const int j = threadIdx.x;
    __shared__ float hs[PP];
    __shared__ float logit[NE];

    const float* gx = g_gx + (size_t)t * N3P;
    const float* gh = g_gh + (size_t)t * N3P;
    float xr = gx[j], xz = gx[PP + j], xn = gx[2 * PP + j];
    float hr = gh[j], hz = gh[PP + j], hn = gh[2 * PP + j];
    float r = 1.f / (1.f + expf(-(xr + hr)));
    float z = 1.f / (1.f + expf(-(xz + hz)));
    float n = tanhf(xn + r * hn);
    float hp = h_prev[(size_t)t * PP + j];
    float h = (1.f - z) * n + z * hp;
    hs[j] = h;
    h_out[(size_t)t * PP + j] = h;
    __syncthreads();

    const int w = j >> 5, lane = j & 31;
    for (int e = w; e < NE; e += 4) {
        float p = 0.f;
#pragma unroll
        for (int c = 0; c < 4; c++)
            p += Wr[e * PP + lane + 32 * c] * hs[lane + 32 * c];
#pragma unroll
        for (int off = 16; off; off >>= 1) p += __shfl_down_sync(0xffffffffu, p, off);
        if (lane == 0) logit[e] = p + br[e];
    }
    __syncthreads();

    if (j == 0) {
        int e0 = 0, e1 = -1;
        float l0 = logit[0], l1 = -1e30f;
        for (int e = 1; e < NE; e++) {
            float v = logit[e];
            if (v > l0) { l1 = l0; e1 = e0; l0 = v; e0 = e; }
            else if (v > l1) { l1 = v; e1 = e; }
        }
        float p1 = expf(l1 - l0);
        float inv = 1.f / (1.0f + p1);
        float p0 = inv; p1 *= inv;
        int pos0 = atomicAdd(&g_count[e0], 1);
        g_list[e0 * T_TOK + pos0] = t; g_wt[e0 * T_TOK + pos0] = p0;
        int pos1 = atomicAdd(&g_count[e1], 1);
        g_list[e1 * T_TOK + pos1] = t; g_wt[e1 * T_TOK + pos1] = p1;
    }
}

__device__ __forceinline__ void expert_base(int e, int& cnt, int& base) {
    base = 0; cnt = 0;
#pragma unroll
    for (int i = 0; i < NE; i++) {
        int c = __ldg(&g_count[i]);
        if (i < e) base += c;
        if (i == e) cnt = c;
    }
}

// ============== expert up-proj: BM=128, BN=128, 4-stage ring, fp16 1-product ==============
__global__ void __launch_bounds__(256, 2) k_expert_up(const float* __restrict__ b1)
{
    const int e = blockIdx.z;
    int cnt, base;
    expert_base(e, cnt, base);
    const int m0 = blockIdx.x * 128;
    if (m0 >= cnt) return;
    const int n0 = blockIdx.y * 128;
    const float* b1e = b1 + (size_t)e * DFF;
    const size_t rowbase = (size_t)base + m0;

    extern __shared__ __align__(16) char dsm[];
    const uint32_t smb = smem_u32(dsm);
    __shared__ int rowidx[128];

    const int tid = threadIdx.x;
    const int wid = tid >> 5, lane = tid & 31;
    const int mw = (wid & 3) * 32, nw = (wid >> 2) * 64;

    if (tid < 128)
        rowidx[tid] = (m0 + tid < cnt) ? g_list[e * T_TOK + m0 + tid] : -1;
    __syncthreads();

    const __half* srcA[2];
    bool okA[2];
    uint32_t dstA[2];
#pragma unroll
    for (int i = 0; i < 2; i++) {
        int it = tid + i * 256;
        int r = it >> 2, q = it & 3;
        int gr = rowidx[r];
        okA[i] = (gr >= 0);
        srcA[i] = g_xh0 + (size_t)(okA[i] ? gr : 0) * DM + q * 8;
        dstA[i] = (uint32_t)(r * 80 + q * 16);
    }
    const __half* srcB[2];
    uint32_t dstB[2];
#pragma unroll
    for (int i = 0; i < 2; i++) {
        int it = tid + i * 256;
        int k = it >> 4, c = it & 15;
        srcB[i] = g_w1h + (size_t)e * DM * DFF + (size_t)k * DFF + n0 + c * 8;
        dstB[i] = (uint32_t)(k * 272 + c * 16);
    }

    float acc[2][8][4];
#pragma unroll
    for (int x = 0; x < 2; x++)
#pragma unroll
        for (int y = 0; y < 8; y++)
#pragma unroll
            for (int zz = 0; zz < 4; zz++) acc[x][y][zz] = 0.f;

#pragma unroll
    for (int st = 0; st < 3; st++) {
        const uint32_t nb = smb + st * E_STAGE;
        const int kc = st * BK;
#pragma unroll
        for (int i = 0; i < 2; i++) {
            cp16(nb + dstA[i], srcA[i] + kc, okA[i]);
            cp16(nb + E_OFFB + dstB[i], srcB[i] + (size_t)kc * DFF, true);
        }
        CP_COMMIT();
    }

    const int NK = DM / BK;  // 16
    int s = 0;
    for (int c = 0; c < NK; c++) {
        if (c + 3 < NK) cp_wait<2>(); else cp_wait<0>();
        __syncthreads();
        if (c + 3 < NK) {
            int s2 = s + 3; if (s2 >= 4) s2 -= 4;
            const uint32_t nb = smb + s2 * E_STAGE;
            const int kc = (c + 3) * BK;
#pragma unroll
            for (int i = 0; i < 2; i++) {
                cp16(nb + dstA[i], srcA[i] + kc, okA[i]);
                cp16(nb + E_OFFB + dstB[i], srcB[i] + (size_t)kc * DFF, true);
            }
            CP_COMMIT();
        }
        chunk1h(smb + s * E_STAGE, mw, nw, lane, acc);
        if (++s == 4) s = 0;
    }

    // epilogue: bias + relu -> single-plane fp16 hidden
#pragma unroll
    for (int mt = 0; mt < 2; mt++) {
        int lr0 = mw + mt * 16 + (lane >> 2);
        int lr1 = lr0 + 8;
        bool ok0 = (m0 + lr0 < cnt), ok1 = (m0 + lr1 < cnt);
        size_t row0 = rowbase + lr0, row1 = rowbase + lr1;
#pragma unroll
        for (int nt = 0; nt < 8; nt++) {
            int c = nw + nt * 8 + (lane & 3) * 2;
            float z0 = __ldg(&b1e[n0 + c]), z1 = __ldg(&b1e[n0 + c + 1]);
            if (ok0) {
                float v0 = fmaxf(acc[mt][nt][0] + z0, 0.f);
                float v1 = fmaxf(acc[mt][nt][1] + z1, 0.f);
                *(uint32_t*)(g_hid0 + row0 * DFF + n0 + c) = packh2(v0, v1);
            }
            if (ok1) {
                float v0 = fmaxf(acc[mt][nt][2] + z0, 0.f);
                float v1 = fmaxf(acc[mt][nt][3] + z1, 0.f);
                *(uint32_t*)(g_hid0 + row1 * DFF + n0 + c) = packh2(v0, v1);
            }
        }
    }
}

// ============== expert down-proj: split-K=4, BM=128, BN=128, 4-stage ring ==============
__global__ void __launch_bounds__(256, 2) k_expert_down(
    const float* __restrict__ b2, float* __restrict__ out)
{
    const int e = blockIdx.z;
    int cnt, base;
    expert_base(e, cnt, base);
    const int m0 = blockIdx.x * 128;
    if (m0 >= cnt) return;
    const int n0 = (blockIdx.y & 3) * 128;
    const int kz = blockIdx.y >> 2;
    const int kbase = kz * KSEG;
    const float* b2e = b2 + (size_t)e * DM;
    const size_t rowbase = (size_t)base + m0;

    extern __shared__ __align__(16) char dsm[];
    const uint32_t smb = smem_u32(dsm);
    __shared__ int s_tok[128];
    __shared__ float s_w[128];

    const int tid = threadIdx.x;
    const int wid = tid >> 5, lane = tid & 31;
    const int mw = (wid & 3) * 32, nw = (wid >> 2) * 64;

    if (tid < 128) {
        bool ok = (m0 + tid < cnt);
        s_tok[tid] = ok ? g_list[e * T_TOK + m0 + tid] : 0;
        s_w[tid] = ok ? g_wt[e * T_TOK + m0 + tid] : 0.f;
    }
    __syncthreads();

    const __half* srcA[2];
    bool okA[2];
    uint32_t dstA[2];
#pragma unroll
    for (int i = 0; i < 2; i++) {
        int it = tid + i * 256;
        int r = it >> 2, q = it & 3;
        okA[i] = (m0 + r < cnt);
        srcA[i] = g_hid0 + (okA[i] ? (rowbase + r) : 0) * DFF + kbase + q * 8;
        dstA[i] = (uint32_t)(r * 80 + q * 16);
    }
    const __half* srcB[2];
    uint32_t dstB[2];
#pragma unroll
    for (int i = 0; i < 2; i++) {
        int it = tid + i * 256;
        int k = it >> 4, c = it & 15;
        srcB[i] = g_w2h + (size_t)e * DFF * DM + (size_t)(kbase + k) * DM + n0 + c * 8;
        dstB[i] = (uint32_t)(k * 272 + c * 16);
    }

    float acc[2][8][4];
#pragma unroll
    for (int x = 0; x < 2; x++)
#pragma unroll
        for (int y = 0; y < 8; y++)
#pragma unroll
            for (int zz = 0; zz < 4; zz++) acc[x][y][zz] = 0.f;

#pragma unroll
    for (int st = 0; st < 3; st++) {
        const uint32_t nb = smb + st * E_STAGE;
        const int kc = st * BK;
#pragma unroll
        for (int i = 0; i < 2; i++) {
            cp16(nb + dstA[i], srcA[i] + kc, okA[i]);
            cp16(nb + E_OFFB + dstB[i], srcB[i] + (size_t)kc * DM, true);
        }
        CP_COMMIT();
    }

    const int NK = KSEG / BK;  // 16
    int s = 0;
    for (int c = 0; c < NK; c++) {
        if (c + 3 < NK) cp_wait<2>(); else cp_wait<0>();
        __syncthreads();
        if (c + 3 < NK) {
            int s2 = s + 3; if (s2 >= 4) s2 -= 4;
            const uint32_t nb = smb + s2 * E_STAGE;
            const int kc = (c + 3) * BK;
#pragma unroll
            for (int i = 0; i < 2; i++) {
                cp16(nb + dstA[i], srcA[i] + kc, okA[i]);
                cp16(nb + E_OFFB + dstB[i], srcB[i] + (size_t)kc * DM, true);
            }
            CP_COMMIT();
        }
        chunk1h(smb + s * E_STAGE, mw, nw, lane, acc);
        if (++s == 4) s = 0;
    }

    const float bscale = (kz == 0) ? 1.f : 0.f;
#pragma unroll
    for (int mt = 0; mt < 2; mt++) {
        int lr0 = mw + mt * 16 + (lane >> 2);
        int lr1 = lr0 + 8;
        bool ok0 = (m0 + lr0 < cnt), ok1 = (m0 + lr1 < cnt);
        int tok0 = s_tok[lr0], tok1 = s_tok[lr1];
        float w0 = s_w[lr0], w1 = s_w[lr1];
#pragma unroll
        for (int nt = 0; nt < 8; nt++) {
            int c = nw + nt * 8 + (lane & 3) * 2;
            float z0 = bscale * __ldg(&b2e[n0 + c]);
            float z1 = bscale * __ldg(&b2e[n0 + c + 1]);
            if (ok0) {
                float* op = out + (size_t)tok0 * DM + n0 + c;
                atomicAdd(op,     w0 * (acc[mt][nt][0] + z0));
                atomicAdd(op + 1, w0 * (acc[mt][nt][1] + z1));
            }
            if (ok1) {
                float* op = out + (size_t)tok1 * DM + n0 + c;
                atomicAdd(op,     w1 * (acc[mt][nt][2] + z0));
                atomicAdd(op + 1, w1 * (acc[mt][nt][3] + z1));
            }
        }
    }
}

// ---------------- host launcher ----------------
extern "C" void kernel_launch(void* const* d_in, const int* in_sizes, int n_in,
                              void* d_out, int out_size) {
    const float* x      = (const float*)d_in[0];
    const float* h_prev = (const float*)d_in[1];
    const float* Wp     = (const float*)d_in[2];
    const float* bp     = (const float*)d_in[3];
    const float* W_ih   = (const float*)d_in[4];
    const float* W_hh   = (const float*)d_in[5];
    const float* b_ih   = (const float*)d_in[6];
    const float* b_hh   = (const float*)d_in[7];
    const float* Wr     = (const float*)d_in[8];
    const float* br     = (const float*)d_in[9];
    const float* W1     = (const float*)d_in[10];
    const float* b1     = (const float*)d_in[11];
    const float* W2     = (const float*)d_in[12];
    const float* b2     = (const float*)d_in[13];

    float* out   = (float*)d_out;
    float* h_out = out + OUT_ELEMS;

    cudaFuncSetAttribute(k_rgemm,
                         cudaFuncAttributeMaxDynamicSharedMemorySize, R_DYN);
    cudaFuncSetAttribute(k_expert_up,
                         cudaFuncAttributeMaxDynamicSharedMemorySize, E_DYN);
    cudaFuncSetAttribute(k_expert_down,
                         cudaFuncAttributeMaxDynamicSharedMemorySize, E_DYN);

    k_prep<<<2048, 256>>>(x, h_prev, W_ih, b_ih, Wp, bp, W_hh, W1, W2, out);
    k_rgemm<<<dim3(3, 32, 2), 256, R_DYN>>>(b_hh);
    k_gru_route<<<T_TOK, 128>>>(h_prev, Wr, br, h_out);
    k_expert_up<<<dim3(T_TOK / 128, DFF / 128, NE), 256, E_DYN>>>(b1);
    k_expert_down<<<dim3(T_TOK / 128, (DM / 128) * KSPLIT, NE), 256, E_DYN>>>(b2, out);
}

// round 9
// speedup vs baseline: 3.2813x; 1.0120x over previous
#include <cuda_runtime.h>
#include <cuda_fp16.h>
#include <cstdint>
#include <math.h>

#define T_TOK 4096
#define DM 512
#define DFF 2048
#define NE 16
#define PP 128
#define N3P 384
#define OUT_ELEMS (T_TOK * DM)
#define BK 32

// ---- rgemm stage: A 2 planes (128x80B), B 2 planes (32x272B) ----
#define R_ALO 10240
#define R_OFFB 20480
#define R_BPL 8704
#define R_STAGE 37888
#define R_DYN (2 * R_STAGE)
// ---- expert stage BK=64: A 1 plane (128x144B), B 1 plane (64x272B) ----
#define E_OFFB 18432
#define E_STAGE 35840
#define E_DYN (2 * E_STAGE)
#define EBK 64
// down split-K
#define KSPLIT 4
#define KSEG (DFF / KSPLIT)   // 512

// ---------------- device scratch ----------------
__device__ float g_gx[T_TOK * N3P];
__device__ float g_gh[T_TOK * N3P];
__device__ float g_bc[N3P];
__device__ __half g_xh0[T_TOK * DM];
__device__ __half g_xh1[T_TOK * DM];
__device__ __half g_hh0[T_TOK * PP];
__device__ __half g_hh1[T_TOK * PP];
__device__ __half g_wcT0[DM * N3P];
__device__ __half g_wcT1[DM * N3P];
__device__ __half g_whT0[PP * N3P];
__device__ __half g_whT1[PP * N3P];
__device__ __half g_w1h[(size_t)NE * DM * DFF];
__device__ __half g_w2h[(size_t)NE * DFF * DM];
__device__ __half g_hid0[(size_t)T_TOK * 2 * DFF];
__device__ int   g_list[NE * T_TOK];
__device__ float g_wt[NE * T_TOK];
__device__ int   g_count[NE];

// ---------------- helpers ----------------
__device__ __forceinline__ uint32_t smem_u32(const void* p) {
    uint32_t a;
    asm("{ .reg .u64 t; cvta.to.shared.u64 t, %1; cvt.u32.u64 %0, t; }"
        : "=r"(a) : "l"(p));
    return a;
}
__device__ __forceinline__ void ldmx4(uint32_t addr, uint32_t* r) {
    asm volatile("ldmatrix.sync.aligned.m8n8.x4.shared.b16 {%0,%1,%2,%3}, [%4];"
                 : "=r"(r[0]), "=r"(r[1]), "=r"(r[2]), "=r"(r[3]) : "r"(addr));
}
__device__ __forceinline__ void ldmx4t(uint32_t addr, uint32_t* r) {
    asm volatile("ldmatrix.sync.aligned.m8n8.x4.trans.shared.b16 {%0,%1,%2,%3}, [%4];"
                 : "=r"(r[0]), "=r"(r[1]), "=r"(r[2]), "=r"(r[3]) : "r"(addr));
}
__device__ __forceinline__ void mmah(float* d, const uint32_t* a, const uint32_t* b) {
    asm volatile(
        "mma.sync.aligned.m16n8k16.row.col.f32.f16.f16.f32 "
        "{%0,%1,%2,%3}, {%4,%5,%6,%7}, {%8,%9}, {%0,%1,%2,%3};"
        : "+f"(d[0]), "+f"(d[1]), "+f"(d[2]), "+f"(d[3])
        : "r"(a[0]), "r"(a[1]), "r"(a[2]), "r"(a[3]), "r"(b[0]), "r"(b[1]));
}
__device__ __forceinline__ void cp16(uint32_t dst, const void* src, bool ok) {
    int sz = ok ? 16 : 0;
    asm volatile("cp.async.cg.shared.global [%0], [%1], 16, %2;"
                 :: "r"(dst), "l"(src), "r"(sz) : "memory");
}
#define CP_COMMIT() asm volatile("cp.async.commit_group;" ::: "memory")
template <int N>
__device__ __forceinline__ void cp_wait() {
    asm volatile("cp.async.wait_group %0;" :: "n"(N) : "memory");
}
__device__ __forceinline__ uint32_t packh2(float a, float b) {
    __half2 h = __floats2half2_rn(a, b);
    return *reinterpret_cast<uint32_t*>(&h);
}
__device__ __forceinline__ uint32_t packh2_hi(float a, float b, float& ra, float& rb) {
    __half2 h = __floats2half2_rn(a, b);
    ra = a - __low2float(h);
    rb = b - __high2float(h);
    return *reinterpret_cast<uint32_t*>(&h);
}

// ---------------- prep ----------------
__global__ void __launch_bounds__(256) k_prep(
    const float* __restrict__ x, const float* __restrict__ h_prev,
    const float* __restrict__ W_ih, const float* __restrict__ b_ih,
    const float* __restrict__ Wp, const float* __restrict__ bp,
    const float* __restrict__ W_hh,
    const float* __restrict__ W1, const float* __restrict__ W2,
    float* __restrict__ out)
{
    const int tid = blockIdx.x * blockDim.x + threadIdx.x;
    const int nth = gridDim.x * blockDim.x;
    if (tid < NE) g_count[tid] = 0;

    float4* o4 = (float4*)out;
    for (int i = tid; i < OUT_ELEMS / 4; i += nth)
        o4[i] = make_float4(0.f, 0.f, 0.f, 0.f);

    {
        const float4* s = (const float4*)x;
        uint2* p0 = (uint2*)g_xh0; uint2* p1 = (uint2*)g_xh1;
        for (int i = tid; i < T_TOK * DM / 4; i += nth) {
            float4 v = s[i]; float r0, r1, r2, r3; uint2 H, L;
            H.x = packh2_hi(v.x, v.y, r0, r1); H.y = packh2_hi(v.z, v.w, r2, r3);
            L.x = packh2(r0, r1); L.y = packh2(r2, r3);
            p0[i] = H; p1[i] = L;
        }
    }
    {
        const float4* s = (const float4*)h_prev;
        uint2* p0 = (uint2*)g_hh0; uint2* p1 = (uint2*)g_hh1;
        for (int i = tid; i < T_TOK * PP / 4; i += nth) {
            float4 v = s[i]; float r0, r1, r2, r3; uint2 H, L;
            H.x = packh2_hi(v.x, v.y, r0, r1); H.y = packh2_hi(v.z, v.w, r2, r3);
            L.x = packh2(r0, r1); L.y = packh2(r2, r3);
            p0[i] = H; p1[i] = L;
        }
    }
    {
        const float4* s = (const float4*)W1;
        uint2* p = (uint2*)g_w1h;
        for (int i = tid; i < NE * DM * DFF / 4; i += nth) {
            float4 v = s[i]; uint2 H;
            H.x = packh2(v.x, v.y); H.y = packh2(v.z, v.w);
            p[i] = H;
        }
    }
    {
        const float4* s = (const float4*)W2;
        uint2* p = (uint2*)g_w2h;
        for (int i = tid; i < NE * DFF * DM / 4; i += nth) {
            float4 v = s[i]; uint2 H;
            H.x = packh2(v.x, v.y); H.y = packh2(v.z, v.w);
            p[i] = H;
        }
    }
    for (int i = tid; i < PP * N3P; i += nth) {
        int n = i % N3P, k = i / N3P;
        float v = W_hh[n * PP + k];
        __half h = __float2half_rn(v);
        g_whT0[i] = h;
        g_whT1[i] = __float2half_rn(v - __half2float(h));
    }
    for (int i = tid; i < DM * N3P; i += nth) {
        int n = i % N3P, k = i / N3P;
        float s = 0.f;
        const float* wr = W_ih + n * PP;
#pragma unroll 8
        for (int p = 0; p < PP; p++) s = fmaf(wr[p], Wp[p * DM + k], s);
        __half h = __float2half_rn(s);
        g_wcT0[i] = h;
        g_wcT1[i] = __float2half_rn(s - __half2float(h));
    }
    for (int i = tid; i < N3P; i += nth) {
        float s = b_ih[i];
        const float* wr = W_ih + i * PP;
        for (int p = 0; p < PP; p++) s = fmaf(wr[p], bp[p], s);
        g_bc[i] = s;
    }
}

// ============== compute bodies ==============
__device__ __forceinline__ void chunk3h(uint32_t sb, int mw, int nw, int lane,
                                        float acc[2][8][4]) {
#pragma unroll
    for (int ks = 0; ks < 2; ks++) {
        uint32_t ah[2][4], al[2][4];
        uint32_t arow = (uint32_t)((mw + (lane & 15)) * 80 + ks * 32 + ((lane >> 4) << 4));
        ldmx4(sb + arow, ah[0]);
        ldmx4(sb + arow + 16 * 80, ah[1]);
        ldmx4(sb + R_ALO + arow, al[0]);
        ldmx4(sb + R_ALO + arow + 16 * 80, al[1]);
        uint32_t brow = (uint32_t)((ks * 16 + (lane & 15)) * 272 + (nw + ((lane >> 4) << 3)) * 2);
#pragma unroll
        for (int nb = 0; nb < 4; nb++) {
            uint32_t bh[4], bl[4];
            ldmx4t(sb + R_OFFB + brow + nb * 32, bh);
            ldmx4t(sb + R_OFFB + R_BPL + brow + nb * 32, bl);
#pragma unroll
            for (int mt = 0; mt < 2; mt++) {
                mmah(acc[mt][2 * nb],     ah[mt], bh);
                mmah(acc[mt][2 * nb],     ah[mt], bl);
                mmah(acc[mt][2 * nb],     al[mt], bh);
                mmah(acc[mt][2 * nb + 1], ah[mt], bh + 2);
                mmah(acc[mt][2 * nb + 1], ah[mt], bl + 2);
                mmah(acc[mt][2 * nb + 1], al[mt], bh + 2);
            }
        }
    }
}

// plain fp16, BK=64: A stride 144, B stride 272 (64 rows)
__device__ __forceinline__ void chunk1h64(uint32_t sb, int mw, int nw, int lane,
                                          float acc[2][8][4]) {
#pragma unroll
    for (int ks = 0; ks < 4; ks++) {
        uint32_t ah[2][4];
        uint32_t arow = (uint32_t)((mw + (lane & 15)) * 144 + ks * 32 + ((lane >> 4) << 4));
        ldmx4(sb + arow, ah[0]);
        ldmx4(sb + arow + 16 * 144, ah[1]);
        uint32_t brow = (uint32_t)((ks * 16 + (lane & 15)) * 272 + (nw + ((lane >> 4) << 3)) * 2);
#pragma unroll
        for (int nb = 0; nb < 4; nb++) {
            uint32_t bh[4];
            ldmx4t(sb + E_OFFB + brow + nb * 32, bh);
#pragma unroll
            for (int mt = 0; mt < 2; mt++) {
                mmah(acc[mt][2 * nb],     ah[mt], bh);
                mmah(acc[mt][2 * nb + 1], ah[mt], bh + 2);
            }
        }
    }
}

// ============== fused gate GEMMs ==============
__global__ void __launch_bounds__(256) k_rgemm(const float* __restrict__ b_hh)
{
    const int z = blockIdx.z;
    const int K = z ? PP : DM;
    const __half* A0 = z ? g_hh0 : g_xh0;
    const __half* A1 = z ? g_hh1 : g_xh1;
    const __half* B0 = z ? g_whT0 : g_wcT0;
    const __half* B1 = z ? g_whT1 : g_wcT1;
    const float* bias = z ? b_hh : g_bc;
    float* C = z ? g_gh : g_gx;

    const int m0 = blockIdx.y * 128;
    const int n0 = blockIdx.x * 128;
    extern __shared__ __align__(16) char dsm[];
    const uint32_t smb = smem_u32(dsm);

    const int tid = threadIdx.x;
    const int wid = tid >> 5, lane = tid & 31;
    const int mw = (wid & 3) * 32, nw = (wid >> 2) * 64;

    const __half* srcA[2];
    uint32_t dstA[2];
#pragma unroll
    for (int i = 0; i < 2; i++) {
        int it = tid + i * 256;
        int r = it >> 2, q = it & 3;
        srcA[i] = A0 + (size_t)(m0 + r) * K + q * 8;
        dstA[i] = (uint32_t)(r * 80 + q * 16);
    }
    const __half* srcB[2];
    uint32_t dstB[2];
#pragma unroll
    for (int i = 0; i < 2; i++) {
        int it = tid + i * 256;
        int k = it >> 4, c = it & 15;
        srcB[i] = B0 + (size_t)k * N3P + n0 + c * 8;
        dstB[i] = (uint32_t)(k * 272 + c * 16);
    }
    const ptrdiff_t dA1 = A1 - A0, dB1 = B1 - B0;

    float acc[2][8][4];
#pragma unroll
    for (int a = 0; a < 2; a++)
#pragma unroll
        for (int b = 0; b < 8; b++)
#pragma unroll
            for (int c = 0; c < 4; c++) acc[a][b][c] = 0.f;

#pragma unroll
    for (int i = 0; i < 2; i++) {
        cp16(smb + dstA[i], srcA[i], true);
        cp16(smb + R_ALO + dstA[i], srcA[i] + dA1, true);
        cp16(smb + R_OFFB + dstB[i], srcB[i], true);
        cp16(smb + R_OFFB + R_BPL + dstB[i], srcB[i] + dB1, true);
    }
    CP_COMMIT();

    const int NK = K / BK;
    for (int c = 0; c < NK; c++) {
        const int s = c & 1;
        if (c + 1 < NK) {
            const uint32_t nb = smb + (s ^ 1) * R_STAGE;
            const int kc = (c + 1) * BK;
#pragma unroll
            for (int i = 0; i < 2; i++) {
                cp16(nb + dstA[i], srcA[i] + kc, true);
                cp16(nb + R_ALO + dstA[i], srcA[i] + dA1 + kc, true);
                cp16(nb + R_OFFB + dstB[i], srcB[i] + (size_t)kc * N3P, true);
                cp16(nb + R_OFFB + R_BPL + dstB[i], srcB[i] + dB1 + (size_t)kc * N3P, true);
            }
            CP_COMMIT();
            cp_wait<1>();
        } else {
            cp_wait<0>();
        }
        __syncthreads();
        chunk3h(smb + s * R_STAGE, mw, nw, lane, acc);
        __syncthreads();
    }

#pragma unroll
    for (int mt = 0; mt < 2; mt++) {
        int lr0 = mw + mt * 16 + (lane >> 2);
        int lr1 = lr0 + 8;
#pragma unroll
        for (int nt = 0; nt < 8; nt++) {
            int c = nw + nt * 8 + (lane & 3) * 2;
            float z0 = __ldg(&bias[n0 + c]), z1 = __ldg(&bias[n0 + c + 1]);
            float2 v0 = make_float2(acc[mt][nt][0] + z0, acc[mt][nt][1] + z1);
            float2 v1 = make_float2(acc[mt][nt][2] + z0, acc[mt][nt][3] + z1);
            *(float2*)&C[(size_t)(m0 + lr0) * N3P + n0 + c] = v0;
            *(float2*)&C[(size_t)(m0 + lr1) * N3P + n0 + c] = v1;
        }
    }
}

// ---------------- GRU + router (top-2) ----------------
__global__ void __launch_bounds__(128) k_gru_route(
    const float* __restrict__ h_prev,
    const float* __restrict__ Wr, const float* __restrict__ br,
    float* __restrict__ h_out)
{
    const int t = blockIdx.x;
    const int j = threadIdx.x;
    __shared__ float hs[PP];
    __shared__ float logit[NE];

    const float* gx = g_gx + (size_t)t * N3P;
    const float* gh = g_gh + (size_t)t * N3P;
    float xr = gx[j], xz = gx[PP + j], xn = gx[2 * PP + j];
    float hr = gh[j], hz = gh[PP + j], hn = gh[2 * PP + j];
    float r = 1.f / (1.f + expf(-(xr + hr)));
    float z = 1.f / (1.f + expf(-(xz + hz)));
    float n = tanhf(xn + r * hn);
    float hp = h_prev[(size_t)t * PP + j];
    float h = (1.f - z) * n + z * hp;
    hs[j] = h;
    h_out[(size_t)t * PP + j] = h;
    __syncthreads();

    const int w = j >> 5, lane = j & 31;
    for (int e = w; e < NE; e += 4) {
        float p = 0.f;
#pragma unroll
        for (int c = 0; c < 4; c++)
            p += Wr[e * PP + lane + 32 * c] * hs[lane + 32 * c];
#pragma unroll
        for (int off = 16; off; off >>= 1) p += __shfl_down_sync(0xffffffffu, p, off);
        if (lane == 0) logit[e] = p + br[e];
    }
    __syncthreads();

    if (j == 0) {
        int e0 = 0, e1 = -1;
        float l0 = logit[0], l1 = -1e30f;
        for (int e = 1; e < NE; e++) {
            float v = logit[e];
            if (v > l0) { l1 = l0; e1 = e0; l0 = v; e0 = e; }
            else if (v > l1) { l1 = v; e1 = e; }
        }
        float p1 = expf(l1 - l0);
        float inv = 1.f / (1.0f + p1);
        float p0 = inv; p1 *= inv;
        int pos0 = atomicAdd(&g_count[e0], 1);
        g_list[e0 * T_TOK + pos0] = t; g_wt[e0 * T_TOK + pos0] = p0;
        int pos1 = atomicAdd(&g_count[e1], 1);
        g_list[e1 * T_TOK + pos1] = t; g_wt[e1 * T_TOK + pos1] = p1;
    }
}

__device__ __forceinline__ void expert_base(int e, int& cnt, int& base) {
    base = 0; cnt = 0;
#pragma unroll
    for (int i = 0; i < NE; i++) {
        int c = __ldg(&g_count[i]);
        if (i < e) base += c;
        if (i == e) cnt = c;
    }
}

// ============== expert up-proj: BK=64, 2-stage, 1 sync/chunk ==============
__global__ void __launch_bounds__(256, 2) k_expert_up(const float* __restrict__ b1)
{
    const int e = blockIdx.z;
    int cnt, base;
    expert_base(e, cnt, base);
    const int m0 = blockIdx.x * 128;
    if (m0 >= cnt) return;
    const int n0 = blockIdx.y * 128;
    const float* b1e = b1 + (size_t)e * DFF;
    const size_t rowbase = (size_t)base + m0;

    extern __shared__ __align__(16) char dsm[];
    const uint32_t smb = smem_u32(dsm);
    __shared__ int rowidx[128];

    const int tid = threadIdx.x;
    const int wid = tid >> 5, lane = tid & 31;
    const int mw = (wid & 3) * 32, nw = (wid >> 2) * 64;

    if (tid < 128)
        rowidx[tid] = (m0 + tid < cnt) ? g_list[e * T_TOK + m0 + tid] : -1;
    __syncthreads();

    const __half* srcA[4];
    bool okA[4];
    uint32_t dstA[4];
#pragma unroll
    for (int i = 0; i < 4; i++) {
        int it = tid + i * 256;
        int r = it >> 3, q = it & 7;
        int gr = rowidx[r];
        okA[i] = (gr >= 0);
        srcA[i] = g_xh0 + (size_t)(okA[i] ? gr : 0) * DM + q * 8;
        dstA[i] = (uint32_t)(r * 144 + q * 16);
    }
    const __half* srcB[4];
    uint32_t dstB[4];
#pragma unroll
    for (int i = 0; i < 4; i++) {
        int it = tid + i * 256;
        int k = it >> 4, c = it & 15;
        srcB[i] = g_w1h + (size_t)e * DM * DFF + (size_t)k * DFF + n0 + c * 8;
        dstB[i] = (uint32_t)(k * 272 + c * 16);
    }

    float acc[2][8][4];
#pragma unroll
    for (int x = 0; x < 2; x++)
#pragma unroll
        for (int y = 0; y < 8; y++)
#pragma unroll
            for (int zz = 0; zz < 4; zz++) acc[x][y][zz] = 0.f;

    // prologue: chunk 0 -> stage 0
#pragma unroll
    for (int i = 0; i < 4; i++) {
        cp16(smb + dstA[i], srcA[i], okA[i]);
        cp16(smb + E_OFFB + dstB[i], srcB[i], true);
    }
    CP_COMMIT();

    const int NK = DM / EBK;  // 8
    for (int c = 0; c < NK; c++) {
        const int s = c & 1;
        cp_wait<0>();
        __syncthreads();
        if (c + 1 < NK) {
            const uint32_t nb = smb + (s ^ 1) * E_STAGE;
            const int kc = (c + 1) * EBK;
#pragma unroll
            for (int i = 0; i < 4; i++) {
                cp16(nb + dstA[i], srcA[i] + kc, okA[i]);
                cp16(nb + E_OFFB + dstB[i], srcB[i] + (size_t)kc * DFF, true);
            }
            CP_COMMIT();
        }
        chunk1h64(smb + s * E_STAGE, mw, nw, lane, acc);
    }

    // epilogue: bias + relu -> single-plane fp16 hidden
#pragma unroll
    for (int mt = 0; mt < 2; mt++) {
        int lr0 = mw + mt * 16 + (lane >> 2);
        int lr1 = lr0 + 8;
        bool ok0 = (m0 + lr0 < cnt), ok1 = (m0 + lr1 < cnt);
        size_t row0 = rowbase + lr0, row1 = rowbase + lr1;
#pragma unroll
        for (int nt = 0; nt < 8; nt++) {
            int c = nw + nt * 8 + (lane & 3) * 2;
            float z0 = __ldg(&b1e[n0 + c]), z1 = __ldg(&b1e[n0 + c + 1]);
            if (ok0) {
                float v0 = fmaxf(acc[mt][nt][0] + z0, 0.f);
                float v1 = fmaxf(acc[mt][nt][1] + z1, 0.f);
                *(uint32_t*)(g_hid0 + row0 * DFF + n0 + c) = packh2(v0, v1);
            }
            if (ok1) {
                float v0 = fmaxf(acc[mt][nt][2] + z0, 0.f);
                float v1 = fmaxf(acc[mt][nt][3] + z1, 0.f);
                *(uint32_t*)(g_hid0 + row1 * DFF + n0 + c) = packh2(v0, v1);
            }
        }
    }
}

// ============== expert down-proj: split-K=4, BK=64, 2-stage ==============
__global__ void __launch_bounds__(256, 2) k_expert_down(
    const float* __restrict__ b2, float* __restrict__ out)
{
    const int e = blockIdx.z;
    int cnt, base;
    expert_base(e, cnt, base);
    const int m0 = blockIdx.x * 128;
    if (m0 >= cnt) return;
    const int n0 = (blockIdx.y & 3) * 128;
    const int kz = blockIdx.y >> 2;
    const int kbase = kz * KSEG;
    const float* b2e = b2 + (size_t)e * DM;
    const size_t rowbase = (size_t)base + m0;

    extern __shared__ __align__(16) char dsm[];
    const uint32_t smb = smem_u32(dsm);
    __shared__ int s_tok[128];
    __shared__ float s_w[128];

    const int tid = threadIdx.x;
    const int wid = tid >> 5, lane = tid & 31;
    const int mw = (wid & 3) * 32, nw = (wid >> 2) * 64;

    if (tid < 128) {
        bool ok = (m0 + tid < cnt);
        s_tok[tid] = ok ? g_list[e * T_TOK + m0 + tid] : 0;
        s_w[tid] = ok ? g_wt[e * T_TOK + m0 + tid] : 0.f;
    }
    __syncthreads();

    const __half* srcA[4];
    bool okA[4];
    uint32_t dstA[4];
#pragma unroll
    for (int i = 0; i < 4; i++) {
        int it = tid + i * 256;
        int r = it >> 3, q = it & 7;
        okA[i] = (m0 + r < cnt);
        srcA[i] = g_hid0 + (okA[i] ? (rowbase + r) : 0) * DFF + kbase + q * 8;
        dstA[i] = (uint32_t)(r * 144 + q * 16);
    }
    const __half* srcB[4];
    uint32_t dstB[4];
#pragma unroll
    for (int i = 0; i < 4; i++) {
        int it = tid + i * 256;
        int k = it >> 4, c = it & 15;
        srcB[i] = g_w2h + (size_t)e * DFF * DM + (size_t)(kbase + k) * DM + n0 + c * 8;
        dstB[i] = (uint32_t)(k * 272 + c * 16);
    }

    float acc[2][8][4];
#pragma unroll
    for (int x = 0; x < 2; x++)
#pragma unroll
        for (int y = 0; y < 8; y++)
#pragma unroll
            for (int zz = 0; zz < 4; zz++) acc[x][y][zz] = 0.f;

#pragma unroll
    for (int i = 0; i < 4; i++) {
        cp16(smb + dstA[i], srcA[i], okA[i]);
        cp16(smb + E_OFFB + dstB[i], srcB[i], true);
    }
    CP_COMMIT();

    const int NK = KSEG / EBK;  // 8
    for (int c = 0; c < NK; c++) {
        const int s = c & 1;
        cp_wait<0>();
        __syncthreads();
        if (c + 1 < NK) {
            const uint32_t nb = smb + (s ^ 1) * E_STAGE;
            const int kc = (c + 1) * EBK;
#pragma unroll
            for (int i = 0; i < 4; i++) {
                cp16(nb + dstA[i], srcA[i] + kc, okA[i]);
                cp16(nb + E_OFFB + dstB[i], srcB[i] + (size_t)kc * DM, true);
            }
            CP_COMMIT();
        }
        chunk1h64(smb + s * E_STAGE, mw, nw, lane, acc);
    }

    const float bscale = (kz == 0) ? 1.f : 0.f;
#pragma unroll
    for (int mt = 0; mt < 2; mt++) {
        int lr0 = mw + mt * 16 + (lane >> 2);
        int lr1 = lr0 + 8;
        bool ok0 = (m0 + lr0 < cnt), ok1 = (m0 + lr1 < cnt);
        int tok0 = s_tok[lr0], tok1 = s_tok[lr1];
        float w0 = s_w[lr0], w1 = s_w[lr1];
#pragma unroll
        for (int nt = 0; nt < 8; nt++) {
            int c = nw + nt * 8 + (lane & 3) * 2;
            float z0 = bscale * __ldg(&b2e[n0 + c]);
            float z1 = bscale * __ldg(&b2e[n0 + c + 1]);
            if (ok0) {
                float* op = out + (size_t)tok0 * DM + n0 + c;
                atomicAdd(op,     w0 * (acc[mt][nt][0] + z0));
                atomicAdd(op + 1, w0 * (acc[mt][nt][1] + z1));
            }
            if (ok1) {
                float* op = out + (size_t)tok1 * DM + n0 + c;
                atomicAdd(op,     w1 * (acc[mt][nt][2] + z0));
                atomicAdd(op + 1, w1 * (acc[mt][nt][3] + z1));
            }
        }
    }
}

// ---------------- host launcher ----------------
extern "C" void kernel_launch(void* const* d_in, const int* in_sizes, int n_in,
                              void* d_out, int out_size) {
    const float* x      = (const float*)d_in[0];
    const float* h_prev = (const float*)d_in[1];
    const float* Wp     = (const float*)d_in[2];
    const float* bp     = (const float*)d_in[3];
    const float* W_ih   = (const float*)d_in[4];
    const float* W_hh   = (const float*)d_in[5];
    const float* b_ih   = (const float*)d_in[6];
    const float* b_hh   = (const float*)d_in[7];
    const float* Wr     = (const float*)d_in[8];
    const float* br     = (const float*)d_in[9];
    const float* W1     = (const float*)d_in[10];
    const float* b1     = (const float*)d_in[11];
    const float* W2     = (const float*)d_in[12];
    const float* b2     = (const float*)d_in[13];

    float* out   = (float*)d_out;
    float* h_out = out + OUT_ELEMS;

    cudaFuncSetAttribute(k_rgemm,
                         cudaFuncAttributeMaxDynamicSharedMemorySize, R_DYN);
    cudaFuncSetAttribute(k_expert_up,
                         cudaFuncAttributeMaxDynamicSharedMemorySize, E_DYN);
    cudaFuncSetAttribute(k_expert_down,
                         cudaFuncAttributeMaxDynamicSharedMemorySize, E_DYN);

    k_prep<<<2048, 256>>>(x, h_prev, W_ih, b_ih, Wp, bp, W_hh, W1, W2, out);
    k_rgemm<<<dim3(3, 32, 2), 256, R_DYN>>>(b_hh);
    k_gru_route<<<T_TOK, 128>>>(h_prev, Wr, br, h_out);
    k_expert_up<<<dim3(T_TOK / 128, DFF / 128, NE), 256, E_DYN>>>(b1);
    k_expert_down<<<dim3(T_TOK / 128, (DM / 128) * KSPLIT, NE), 256, E_DYN>>>(b2, out);
}

// round 10
// speedup vs baseline: 3.3736x; 1.0281x over previous
#include <cuda_runtime.h>
#include <cuda_fp16.h>
#include <cstdint>
#include <math.h>

#define T_TOK 4096
#define DM 512
#define DFF 2048
#define NE 16
#define PP 128
#define N3P 384
#define OUT_ELEMS (T_TOK * DM)
#define BK 32

// ---- rgemm stage: A 2 planes (128x80B), B 2 planes (32x272B) ----
#define R_ALO 10240
#define R_OFFB 20480
#define R_BPL 8704
#define R_STAGE 37888
#define R_DYN (2 * R_STAGE)
// ---- expert stage BK=64: A 1 plane (128x144B), B 1 plane (64x272B) ----
#define E_OFFB 18432
#define E_STAGE 35840
#define E_DYN (2 * E_STAGE)
#define EBK 64
// down split-K (non-atomic partials)
#define KSPLIT 2
#define KSEG (DFF / KSPLIT)   // 1024
#define ROWS2 (T_TOK * 2)

// ---------------- device scratch ----------------
__device__ float g_gx[T_TOK * N3P];
__device__ float g_gh[T_TOK * N3P];
__device__ float g_bc[N3P];
__device__ __half g_xh0[T_TOK * DM];
__device__ __half g_xh1[T_TOK * DM];
__device__ __half g_hh0[T_TOK * PP];
__device__ __half g_hh1[T_TOK * PP];
__device__ __half g_wcT0[DM * N3P];
__device__ __half g_wcT1[DM * N3P];
__device__ __half g_whT0[PP * N3P];
__device__ __half g_whT1[PP * N3P];
__device__ __half g_w1h[(size_t)NE * DM * DFF];
__device__ __half g_w2h[(size_t)NE * DFF * DM];
__device__ __half g_hid0[(size_t)ROWS2 * DFF];
__device__ float g_part[(size_t)KSPLIT * ROWS2 * DM];   // 33.5 MB
__device__ int   g_list[NE * T_TOK];
__device__ float g_wt[NE * T_TOK];
__device__ int4  g_slot[T_TOK];    // (e0, pos0, e1, pos1)
__device__ int   g_count[NE];

// ---------------- helpers ----------------
__device__ __forceinline__ uint32_t smem_u32(const void* p) {
    uint32_t a;
    asm("{ .reg .u64 t; cvta.to.shared.u64 t, %1; cvt.u32.u64 %0, t; }"
        : "=r"(a) : "l"(p));
    return a;
}
__device__ __forceinline__ void ldmx4(uint32_t addr, uint32_t* r) {
    asm volatile("ldmatrix.sync.aligned.m8n8.x4.shared.b16 {%0,%1,%2,%3}, [%4];"
                 : "=r"(r[0]), "=r"(r[1]), "=r"(r[2]), "=r"(r[3]) : "r"(addr));
}
__device__ __forceinline__ void ldmx4t(uint32_t addr, uint32_t* r) {
    asm volatile("ldmatrix.sync.aligned.m8n8.x4.trans.shared.b16 {%0,%1,%2,%3}, [%4];"
                 : "=r"(r[0]), "=r"(r[1]), "=r"(r[2]), "=r"(r[3]) : "r"(addr));
}
__device__ __forceinline__ void mmah(float* d, const uint32_t* a, const uint32_t* b) {
    asm volatile(
        "mma.sync.aligned.m16n8k16.row.col.f32.f16.f16.f32 "
        "{%0,%1,%2,%3}, {%4,%5,%6,%7}, {%8,%9}, {%0,%1,%2,%3};"
        : "+f"(d[0]), "+f"(d[1]), "+f"(d[2]), "+f"(d[3])
        : "r"(a[0]), "r"(a[1]), "r"(a[2]), "r"(a[3]), "r"(b[0]), "r"(b[1]));
}
__device__ __forceinline__ void cp16(uint32_t dst, const void* src, bool ok) {
    int sz = ok ? 16 : 0;
    asm volatile("cp.async.cg.shared.global [%0], [%1], 16, %2;"
                 :: "r"(dst), "l"(src), "r"(sz) : "memory");
}
#define CP_COMMIT() asm volatile("cp.async.commit_group;" ::: "memory")
template <int N>
__device__ __forceinline__ void cp_wait() {
    asm volatile("cp.async.wait_group %0;" :: "n"(N) : "memory");
}
__device__ __forceinline__ uint32_t packh2(float a, float b) {
    __half2 h = __floats2half2_rn(a, b);
    return *reinterpret_cast<uint32_t*>(&h);
}
__device__ __forceinline__ uint32_t packh2_hi(float a, float b, float& ra, float& rb) {
    __half2 h = __floats2half2_rn(a, b);
    ra = a - __low2float(h);
    rb = b - __high2float(h);
    return *reinterpret_cast<uint32_t*>(&h);
}

// ---------------- prep ----------------
__global__ void __launch_bounds__(256) k_prep(
    const float* __restrict__ x, const float* __restrict__ h_prev,
    const float* __restrict__ W_ih, const float* __restrict__ b_ih,
    const float* __restrict__ Wp, const float* __restrict__ bp,
    const float* __restrict__ W_hh,
    const float* __restrict__ W1, const float* __restrict__ W2)
{
    const int tid = blockIdx.x * blockDim.x + threadIdx.x;
    const int nth = gridDim.x * blockDim.x;
    if (tid < NE) g_count[tid] = 0;

    {
        const float4* s = (const float4*)x;
        uint2* p0 = (uint2*)g_xh0; uint2* p1 = (uint2*)g_xh1;
        for (int i = tid; i < T_TOK * DM / 4; i += nth) {
            float4 v = s[i]; float r0, r1, r2, r3; uint2 H, L;
            H.x = packh2_hi(v.x, v.y, r0, r1); H.y = packh2_hi(v.z, v.w, r2, r3);
            L.x = packh2(r0, r1); L.y = packh2(r2, r3);
            p0[i] = H; p1[i] = L;
        }
    }
    {
        const float4* s = (const float4*)h_prev;
        uint2* p0 = (uint2*)g_hh0; uint2* p1 = (uint2*)g_hh1;
        for (int i = tid; i < T_TOK * PP / 4; i += nth) {
            float4 v = s[i]; float r0, r1, r2, r3; uint2 H, L;
            H.x = packh2_hi(v.x, v.y, r0, r1); H.y = packh2_hi(v.z, v.w, r2, r3);
            L.x = packh2(r0, r1); L.y = packh2(r2, r3);
            p0[i] = H; p1[i] = L;
        }
    }
    {
        const float4* s = (const float4*)W1;
        uint2* p = (uint2*)g_w1h;
        for (int i = tid; i < NE * DM * DFF / 4; i += nth) {
            float4 v = s[i]; uint2 H;
            H.x = packh2(v.x, v.y); H.y = packh2(v.z, v.w);
            p[i] = H;
        }
    }
    {
        const float4* s = (const float4*)W2;
        uint2* p = (uint2*)g_w2h;
        for (int i = tid; i < NE * DFF * DM / 4; i += nth) {
            float4 v = s[i]; uint2 H;
            H.x = packh2(v.x, v.y); H.y = packh2(v.z, v.w);
            p[i] = H;
        }
    }
    for (int i = tid; i < PP * N3P; i += nth) {
        int n = i % N3P, k = i / N3P;
        float v = W_hh[n * PP + k];
        __half h = __float2half_rn(v);
        g_whT0[i] = h;
        g_whT1[i] = __float2half_rn(v - __half2float(h));
    }
    for (int i = tid; i < DM * N3P; i += nth) {
        int n = i % N3P, k = i / N3P;
        float s = 0.f;
        const float* wr = W_ih + n * PP;
#pragma unroll 8
        for (int p = 0; p < PP; p++) s = fmaf(wr[p], Wp[p * DM + k], s);
        __half h = __float2half_rn(s);
        g_wcT0[i] = h;
        g_wcT1[i] = __float2half_rn(s - __half2float(h));
    }
    for (int i = tid; i < N3P; i += nth) {
        float s = b_ih[i];
        const float* wr = W_ih + i * PP;
        for (int p = 0; p < PP; p++) s = fmaf(wr[p], bp[p], s);
        g_bc[i] = s;
    }
}

// ============== compute bodies ==============
__device__ __forceinline__ void chunk3h(uint32_t sb, int mw, int nw, int lane,
                                        float acc[2][8][4]) {
#pragma unroll
    for (int ks = 0; ks < 2; ks++) {
        uint32_t ah[2][4], al[2][4];
        uint32_t arow = (uint32_t)((mw + (lane & 15)) * 80 + ks * 32 + ((lane >> 4) << 4));
        ldmx4(sb + arow, ah[0]);
        ldmx4(sb + arow + 16 * 80, ah[1]);
        ldmx4(sb + R_ALO + arow, al[0]);
        ldmx4(sb + R_ALO + arow + 16 * 80, al[1]);
        uint32_t brow = (uint32_t)((ks * 16 + (lane & 15)) * 272 + (nw + ((lane >> 4) << 3)) * 2);
#pragma unroll
        for (int nb = 0; nb < 4; nb++) {
            uint32_t bh[4], bl[4];
            ldmx4t(sb + R_OFFB + brow + nb * 32, bh);
            ldmx4t(sb + R_OFFB + R_BPL + brow + nb * 32, bl);
#pragma unroll
            for (int mt = 0; mt < 2; mt++) {
                mmah(acc[mt][2 * nb],     ah[mt], bh);
                mmah(acc[mt][2 * nb],     ah[mt], bl);
                mmah(acc[mt][2 * nb],     al[mt], bh);
                mmah(acc[mt][2 * nb + 1], ah[mt], bh + 2);
                mmah(acc[mt][2 * nb + 1], ah[mt], bl + 2);
                mmah(acc[mt][2 * nb + 1], al[mt], bh + 2);
            }
        }
    }
}

// plain fp16, BK=64: A stride 144, B stride 272
__device__ __forceinline__ void chunk1h64(uint32_t sb, int mw, int nw, int lane,
                                          float acc[2][8][4]) {
#pragma unroll
    for (int ks = 0; ks < 4; ks++) {
        uint32_t ah[2][4];
        uint32_t arow = (uint32_t)((mw + (lane & 15)) * 144 + ks * 32 + ((lane >> 4) << 4));
        ldmx4(sb + arow, ah[0]);
        ldmx4(sb + arow + 16 * 144, ah[1]);
        uint32_t brow = (uint32_t)((ks * 16 + (lane & 15)) * 272 + (nw + ((lane >> 4) << 3)) * 2);
#pragma unroll
        for (int nb = 0; nb < 4; nb++) {
            uint32_t bh[4];
            ldmx4t(sb + E_OFFB + brow + nb * 32, bh);
#pragma unroll
            for (int mt = 0; mt < 2; mt++) {
                mmah(acc[mt][2 * nb],     ah[mt], bh);
                mmah(acc[mt][2 * nb + 1], ah[mt], bh + 2);
            }
        }
    }
}

// ============== fused gate GEMMs ==============
__global__ void __launch_bounds__(256) k_rgemm(const float* __restrict__ b_hh)
{
    const int z = blockIdx.z;
    const int K = z ? PP : DM;
    const __half* A0 = z ? g_hh0 : g_xh0;
    const __half* A1 = z ? g_hh1 : g_xh1;
    const __half* B0 = z ? g_whT0 : g_wcT0;
    const __half* B1 = z ? g_whT1 : g_wcT1;
    const float* bias = z ? b_hh : g_bc;
    float* C = z ? g_gh : g_gx;

    const int m0 = blockIdx.y * 128;
    const int n0 = blockIdx.x * 128;
    extern __shared__ __align__(16) char dsm[];
    const uint32_t smb = smem_u32(dsm);

    const int tid = threadIdx.x;
    const int wid = tid >> 5, lane = tid & 31;
    const int mw = (wid & 3) * 32, nw = (wid >> 2) * 64;

    const __half* srcA[2];
    uint32_t dstA[2];
#pragma unroll
    for (int i = 0; i < 2; i++) {
        int it = tid + i * 256;
        int r = it >> 2, q = it & 3;
        srcA[i] = A0 + (size_t)(m0 + r) * K + q * 8;
        dstA[i] = (uint32_t)(r * 80 + q * 16);
    }
    const __half* srcB[2];
    uint32_t dstB[2];
#pragma unroll
    for (int i = 0; i < 2; i++) {
        int it = tid + i * 256;
        int k = it >> 4, c = it & 15;
        srcB[i] = B0 + (size_t)k * N3P + n0 + c * 8;
        dstB[i] = (uint32_t)(k * 272 + c * 16);
    }
    const ptrdiff_t dA1 = A1 - A0, dB1 = B1 - B0;

    float acc[2][8][4];
#pragma unroll
    for (int a = 0; a < 2; a++)
#pragma unroll
        for (int b = 0; b < 8; b++)
#pragma unroll
            for (int c = 0; c < 4; c++) acc[a][b][c] = 0.f;

#pragma unroll
    for (int i = 0; i < 2; i++) {
        cp16(smb + dstA[i], srcA[i], true);
        cp16(smb + R_ALO + dstA[i], srcA[i] + dA1, true);
        cp16(smb + R_OFFB + dstB[i], srcB[i], true);
        cp16(smb + R_OFFB + R_BPL + dstB[i], srcB[i] + dB1, true);
    }
    CP_COMMIT();

    const int NK = K / BK;
    for (int c = 0; c < NK; c++) {
        const int s = c & 1;
        if (c + 1 < NK) {
            const uint32_t nb = smb + (s ^ 1) * R_STAGE;
            const int kc = (c + 1) * BK;
#pragma unroll
            for (int i = 0; i < 2; i++) {
                cp16(nb + dstA[i], srcA[i] + kc, true);
                cp16(nb + R_ALO + dstA[i], srcA[i] + dA1 + kc, true);
                cp16(nb + R_OFFB + dstB[i], srcB[i] + (size_t)kc * N3P, true);
                cp16(nb + R_OFFB + R_BPL + dstB[i], srcB[i] + dB1 + (size_t)kc * N3P, true);
            }
            CP_COMMIT();
            cp_wait<1>();
        } else {
            cp_wait<0>();
        }
        __syncthreads();
        chunk3h(smb + s * R_STAGE, mw, nw, lane, acc);
        __syncthreads();
    }

#pragma unroll
    for (int mt = 0; mt < 2; mt++) {
        int lr0 = mw + mt * 16 + (lane >> 2);
        int lr1 = lr0 + 8;
#pragma unroll
        for (int nt = 0; nt < 8; nt++) {
            int c = nw + nt * 8 + (lane & 3) * 2;
            float z0 = __ldg(&bias[n0 + c]), z1 = __ldg(&bias[n0 + c + 1]);
            float2 v0 = make_float2(acc[mt][nt][0] + z0, acc[mt][nt][1] + z1);
            float2 v1 = make_float2(acc[mt][nt][2] + z0, acc[mt][nt][3] + z1);
            *(float2*)&C[(size_t)(m0 + lr0) * N3P + n0 + c] = v0;
            *(float2*)&C[(size_t)(m0 + lr1) * N3P + n0 + c] = v1;
        }
    }
}

// ---------------- GRU + router (top-2) ----------------
__global__ void __launch_bounds__(128) k_gru_route(
    const float* __restrict__ h_prev,
    const float* __restrict__ Wr, const float* __restrict__ br,
    float* __restrict__ h_out)
{
    const int t = blockIdx.x;
    const int j = threadIdx.x;
    __shared__ float hs[PP];
    __shared__ float logit[NE];

    const float* gx = g_gx + (size_t)t * N3P;
    const float* gh = g_gh + (size_t)t * N3P;
    float xr = gx[j], xz = gx[PP + j], xn = gx[2 * PP + j];
    float hr = gh[j], hz = gh[PP + j], hn = gh[2 * PP + j];
    float r = 1.f / (1.f + expf(-(xr + hr)));
    float z = 1.f / (1.f + expf(-(xz + hz)));
    float n = tanhf(xn + r * hn);
    float hp = h_prev[(size_t)t * PP + j];
    float h = (1.f - z) * n + z * hp;
    hs[j] = h;
    h_out[(size_t)t * PP + j] = h;
    __syncthreads();

    const int w = j >> 5, lane = j & 31;
    for (int e = w; e < NE; e += 4) {
        float p = 0.f;
#pragma unroll
        for (int c = 0; c < 4; c++)
            p += Wr[e * PP + lane + 32 * c] * hs[lane + 32 * c];
#pragma unroll
        for (int off = 16; off; off >>= 1) p += __shfl_down_sync(0xffffffffu, p, off);
        if (lane == 0) logit[e] = p + br[e];
    }
    __syncthreads();

    if (j == 0) {
        int e0 = 0, e1 = -1;
        float l0 = logit[0], l1 = -1e30f;
        for (int e = 1; e < NE; e++) {
            float v = logit[e];
            if (v > l0) { l1 = l0; e1 = e0; l0 = v; e0 = e; }
            else if (v > l1) { l1 = v; e1 = e; }
        }
        float p1 = expf(l1 - l0);
        float inv = 1.f / (1.0f + p1);
        float p0 = inv; p1 *= inv;
        int pos0 = atomicAdd(&g_count[e0], 1);
        g_list[e0 * T_TOK + pos0] = t; g_wt[e0 * T_TOK + pos0] = p0;
        int pos1 = atomicAdd(&g_count[e1], 1);
        g_list[e1 * T_TOK + pos1] = t; g_wt[e1 * T_TOK + pos1] = p1;
        g_slot[t] = make_int4(e0, pos0, e1, pos1);
    }
}

__device__ __forceinline__ void expert_base(int e, int& cnt, int& base) {
    base = 0; cnt = 0;
#pragma unroll
    for (int i = 0; i < NE; i++) {
        int c = __ldg(&g_count[i]);
        if (i < e) base += c;
        if (i == e) cnt = c;
    }
}

// ============== expert up-proj: BK=64, 2-stage, 1 sync/chunk ==============
__global__ void __launch_bounds__(256, 2) k_expert_up(const float* __restrict__ b1)
{
    const int e = blockIdx.z;
    int cnt, base;
    expert_base(e, cnt, base);
    const int m0 = blockIdx.x * 128;
    if (m0 >= cnt) return;
    const int n0 = blockIdx.y * 128;
    const float* b1e = b1 + (size_t)e * DFF;
    const size_t rowbase = (size_t)base + m0;

    extern __shared__ __align__(16) char dsm[];
    const uint32_t smb = smem_u32(dsm);
    __shared__ int rowidx[128];

    const int tid = threadIdx.x;
    const int wid = tid >> 5, lane = tid & 31;
    const int mw = (wid & 3) * 32, nw = (wid >> 2) * 64;

    if (tid < 128)
        rowidx[tid] = (m0 + tid < cnt) ? g_list[e * T_TOK + m0 + tid] : -1;
    __syncthreads();

    const __half* srcA[4];
    bool okA[4];
    uint32_t dstA[4];
#pragma unroll
    for (int i = 0; i < 4; i++) {
        int it = tid + i * 256;
        int r = it >> 3, q = it & 7;
        int gr = rowidx[r];
        okA[i] = (gr >= 0);
        srcA[i] = g_xh0 + (size_t)(okA[i] ? gr : 0) * DM + q * 8;
        dstA[i] = (uint32_t)(r * 144 + q * 16);
    }
    const __half* srcB[4];
    uint32_t dstB[4];
#pragma unroll
    for (int i = 0; i < 4; i++) {
        int it = tid + i * 256;
        int k = it >> 4, c = it & 15;
        srcB[i] = g_w1h + (size_t)e * DM * DFF + (size_t)k * DFF + n0 + c * 8;
        dstB[i] = (uint32_t)(k * 272 + c * 16);
    }

    float acc[2][8][4];
#pragma unroll
    for (int x = 0; x < 2; x++)
#pragma unroll
        for (int y = 0; y < 8; y++)
#pragma unroll
            for (int zz = 0; zz < 4; zz++) acc[x][y][zz] = 0.f;

#pragma unroll
    for (int i = 0; i < 4; i++) {
        cp16(smb + dstA[i], srcA[i], okA[i]);
        cp16(smb + E_OFFB + dstB[i], srcB[i], true);
    }
    CP_COMMIT();

    const int NK = DM / EBK;  // 8
    for (int c = 0; c < NK; c++) {
        const int s = c & 1;
        cp_wait<0>();
        __syncthreads();
        if (c + 1 < NK) {
            const uint32_t nb = smb + (s ^ 1) * E_STAGE;
            const int kc = (c + 1) * EBK;
#pragma unroll
            for (int i = 0; i < 4; i++) {
                cp16(nb + dstA[i], srcA[i] + kc, okA[i]);
                cp16(nb + E_OFFB + dstB[i], srcB[i] + (size_t)kc * DFF, true);
            }
            CP_COMMIT();
        }
        chunk1h64(smb + s * E_STAGE, mw, nw, lane, acc);
    }

    // epilogue: bias + relu -> single-plane fp16 hidden
#pragma unroll
    for (int mt = 0; mt < 2; mt++) {
        int lr0 = mw + mt * 16 + (lane >> 2);
        int lr1 = lr0 + 8;
        bool ok0 = (m0 + lr0 < cnt), ok1 = (m0 + lr1 < cnt);
        size_t row0 = rowbase + lr0, row1 = rowbase + lr1;
#pragma unroll
        for (int nt = 0; nt < 8; nt++) {
            int c = nw + nt * 8 + (lane & 3) * 2;
            float z0 = __ldg(&b1e[n0 + c]), z1 = __ldg(&b1e[n0 + c + 1]);
            if (ok0) {
                float v0 = fmaxf(acc[mt][nt][0] + z0, 0.f);
                float v1 = fmaxf(acc[mt][nt][1] + z1, 0.f);
                *(uint32_t*)(g_hid0 + row0 * DFF + n0 + c) = packh2(v0, v1);
            }
            if (ok1) {
                float v0 = fmaxf(acc[mt][nt][2] + z0, 0.f);
                float v1 = fmaxf(acc[mt][nt][3] + z1, 0.f);
                *(uint32_t*)(g_hid0 + row1 * DFF + n0 + c) = packh2(v0, v1);
            }
        }
    }
}

// ============== expert down-proj: split-K=2, NON-ATOMIC partials ==============
__global__ void __launch_bounds__(256, 2) k_expert_down()
{
    const int e = blockIdx.z;
    int cnt, base;
    expert_base(e, cnt, base);
    const int m0 = blockIdx.x * 128;
    if (m0 >= cnt) return;
    const int n0 = (blockIdx.y & 3) * 128;
    const int kz = blockIdx.y >> 2;
    const int kbase = kz * KSEG;
    const size_t rowbase = (size_t)base + m0;
    float* part = g_part + (size_t)kz * ROWS2 * DM;

    extern __shared__ __align__(16) char dsm[];
    const uint32_t smb = smem_u32(dsm);

    const int tid = threadIdx.x;
    const int wid = tid >> 5, lane = tid & 31;
    const int mw = (wid & 3) * 32, nw = (wid >> 2) * 64;

    const __half* srcA[4];
    bool okA[4];
    uint32_t dstA[4];
#pragma unroll
    for (int i = 0; i < 4; i++) {
        int it = tid + i * 256;
        int r = it >> 3, q = it & 7;
        okA[i] = (m0 + r < cnt);
        srcA[i] = g_hid0 + (okA[i] ? (rowbase + r) : 0) * DFF + kbase + q * 8;
        dstA[i] = (uint32_t)(r * 144 + q * 16);
    }
    const __half* srcB[4];
    uint32_t dstB[4];
#pragma unroll
    for (int i = 0; i < 4; i++) {
        int it = tid + i * 256;
        int k = it >> 4, c = it & 15;
        srcB[i] = g_w2h + (size_t)e * DFF * DM + (size_t)(kbase + k) * DM + n0 + c * 8;
        dstB[i] = (uint32_t)(k * 272 + c * 16);
    }

    float acc[2][8][4];
#pragma unroll
    for (int x = 0; x < 2; x++)
#pragma unroll
        for (int y = 0; y < 8; y++)
#pragma unroll
            for (int zz = 0; zz < 4; zz++) acc[x][y][zz] = 0.f;

#pragma unroll
    for (int i = 0; i < 4; i++) {
        cp16(smb + dstA[i], srcA[i], okA[i]);
        cp16(smb + E_OFFB + dstB[i], srcB[i], true);
    }
    CP_COMMIT();

    const int NK = KSEG / EBK;  // 16
    for (int c = 0; c < NK; c++) {
        const int s = c & 1;
        cp_wait<0>();
        __syncthreads();
        if (c + 1 < NK) {
            const uint32_t nb = smb + (s ^ 1) * E_STAGE;
            const int kc = (c + 1) * EBK;
#pragma unroll
            for (int i = 0; i < 4; i++) {
                cp16(nb + dstA[i], srcA[i] + kc, okA[i]);
                cp16(nb + E_OFFB + dstB[i], srcB[i] + (size_t)kc * DM, true);
            }
            CP_COMMIT();
        }
        chunk1h64(smb + s * E_STAGE, mw, nw, lane, acc);
    }

    // epilogue: plain coalesced stores of raw partial sums (no bias, no weight)
#pragma unroll
    for (int mt = 0; mt < 2; mt++) {
        int lr0 = mw + mt * 16 + (lane >> 2);
        int lr1 = lr0 + 8;
        bool ok0 = (m0 + lr0 < cnt), ok1 = (m0 + lr1 < cnt);
        size_t row0 = rowbase + lr0, row1 = rowbase + lr1;
#pragma unroll
        for (int nt = 0; nt < 8; nt++) {
            int c = nw + nt * 8 + (lane & 3) * 2;
            if (ok0)
                *(float2*)&part[row0 * DM + n0 + c] =
                    make_float2(acc[mt][nt][0], acc[mt][nt][1]);
            if (ok1)
                *(float2*)&part[row1 * DM + n0 + c] =
                    make_float2(acc[mt][nt][2], acc[mt][nt][3]);
        }
    }
}

// ============== combine: out[t] = w0*(y0+b2[e0]) + w1*(y1+b2[e1]) ==============
__global__ void __launch_bounds__(128) k_combine(
    const float* __restrict__ b2, float* __restrict__ out)
{
    const int t = blockIdx.x;
    const int tid = threadIdx.x;
    __shared__ int sbase[NE];
    __shared__ int4 sslot;
    if (tid < NE) {
        int b = 0;
        for (int i = 0; i < tid; i++) b += __ldg(&g_count[i]);
        sbase[tid] = b;
    }
    if (tid == 0) sslot = g_slot[t];
    __syncthreads();

    const int e0 = sslot.x, pos0 = sslot.y, e1 = sslot.z, pos1 = sslot.w;
    const size_t r0 = (size_t)sbase[e0] + pos0;
    const size_t r1 = (size_t)sbase[e1] + pos1;
    const float w0 = __ldg(&g_wt[e0 * T_TOK + pos0]);
    const float w1 = __ldg(&g_wt[e1 * T_TOK + pos1]);

    const float4* p0a = (const float4*)(g_part + r0 * DM);
    const float4* p0b = (const float4*)(g_part + (size_t)ROWS2 * DM + r0 * DM);
    const float4* p1a = (const float4*)(g_part + r1 * DM);
    const float4* p1b = (const float4*)(g_part + (size_t)ROWS2 * DM + r1 * DM);
    const float4* bz0 = (const float4*)(b2 + (size_t)e0 * DM);
    const float4* bz1 = (const float4*)(b2 + (size_t)e1 * DM);
    float4* o = (float4*)(out + (size_t)t * DM);

    for (int c = tid; c < DM / 4; c += 128) {
        float4 a0 = p0a[c], a1 = p0b[c], z0 = bz0[c];
        float4 d0 = p1a[c], d1 = p1b[c], z1 = bz1[c];
        float4 r;
        r.x = w0 * (a0.x + a1.x + z0.x) + w1 * (d0.x + d1.x + z1.x);
        r.y = w0 * (a0.y + a1.y + z0.y) + w1 * (d0.y + d1.y + z1.y);
        r.z = w0 * (a0.z + a1.z + z0.z) + w1 * (d0.z + d1.z + z1.z);
        r.w = w0 * (a0.w + a1.w + z0.w) + w1 * (d0.w + d1.w + z1.w);
        o[c] = r;
    }
}

// ---------------- host launcher ----------------
extern "C" void kernel_launch(void* const* d_in, const int* in_sizes, int n_in,
                              void* d_out, int out_size) {
    const float* x      = (const float*)d_in[0];
    const float* h_prev = (const float*)d_in[1];
    const float* Wp     = (const float*)d_in[2];
    const float* bp     = (const float*)d_in[3];
    const float* W_ih   = (const float*)d_in[4];
    const float* W_hh   = (const float*)d_in[5];
    const float* b_ih   = (const float*)d_in[6];
    const float* b_hh   = (const float*)d_in[7];
    const float* Wr     = (const float*)d_in[8];
    const float* br     = (const float*)d_in[9];
    const float* W1     = (const float*)d_in[10];
    const float* b1     = (const float*)d_in[11];
    const float* W2     = (const float*)d_in[12];
    const float* b2     = (const float*)d_in[13];

    float* out   = (float*)d_out;
    float* h_out = out + OUT_ELEMS;

    cudaFuncSetAttribute(k_rgemm,
                         cudaFuncAttributeMaxDynamicSharedMemorySize, R_DYN);
    cudaFuncSetAttribute(k_expert_up,
                         cudaFuncAttributeMaxDynamicSharedMemorySize, E_DYN);
    cudaFuncSetAttribute(k_expert_down,
                         cudaFuncAttributeMaxDynamicSharedMemorySize, E_DYN);

    k_prep<<<2048, 256>>>(x, h_prev, W_ih, b_ih, Wp, bp, W_hh, W1, W2);
    k_rgemm<<<dim3(3, 32, 2), 256, R_DYN>>>(b_hh);
    k_gru_route<<<T_TOK, 128>>>(h_prev, Wr, br, h_out);
    k_expert_up<<<dim3(T_TOK / 128, DFF / 128, NE), 256, E_DYN>>>(b1);
    k_expert_down<<<dim3(T_TOK / 128, (DM / 128) * KSPLIT, NE), 256, E_DYN>>>();
    k_combine<<<T_TOK, 128>>>(b2, out);
}